// round 1
// baseline (speedup 1.0000x reference)
#include <cuda_runtime.h>
#include <math.h>

#define B_  2
#define S_  2048
#define D_  1024
#define H_  16
#define HD_ 64
#define EPS 1e-6f

#define ROWS (B_ * S_)          // 4096
#define FPAD 68                 // padded row stride for 64-wide smem tiles

// ---------------- scratch (device globals; no allocation) ----------------
__device__ float g_xn  [ROWS * D_];          // 16 MB
__device__ float g_qkv [ROWS * 3 * D_];      // 48 MB
__device__ float g_q   [B_ * H_ * S_ * HD_]; // 16 MB
__device__ float g_k   [B_ * H_ * S_ * HD_];
__device__ float g_v   [B_ * H_ * S_ * HD_];
__device__ float g_attn[ROWS * D_];          // 16 MB, layout [b,s,h,hd] == [row, d]

// ---------------- block reduce (256 threads) ----------------
__device__ __forceinline__ float block_reduce_256(float v) {
    __shared__ float sh[8];
    #pragma unroll
    for (int o = 16; o; o >>= 1) v += __shfl_down_sync(0xffffffffu, v, o);
    if ((threadIdx.x & 31) == 0) sh[threadIdx.x >> 5] = v;
    __syncthreads();
    if (threadIdx.x == 0) {
        float t = 0.f;
        #pragma unroll
        for (int i = 0; i < 8; i++) t += sh[i];
        sh[0] = t;
    }
    __syncthreads();
    float r = sh[0];
    __syncthreads();
    return r;
}

// ---------------- kernel 1: input layernorm ----------------
__global__ __launch_bounds__(256) void ln_kernel(
    const float* __restrict__ x, const float* __restrict__ scale,
    const float* __restrict__ bias, float* __restrict__ out)
{
    int row = blockIdx.x;
    const float4* xr = (const float4*)(x + (size_t)row * D_);
    float4 v = xr[threadIdx.x];

    float s = v.x + v.y + v.z + v.w;
    float tot = block_reduce_256(s);
    float mu = tot * (1.0f / D_);

    float dx = v.x - mu, dy = v.y - mu, dz = v.z - mu, dw = v.w - mu;
    float sq = dx*dx + dy*dy + dz*dz + dw*dw;
    float vtot = block_reduce_256(sq);
    float rstd = rsqrtf(vtot * (1.0f / D_) + EPS);

    float4 sc = ((const float4*)scale)[threadIdx.x];
    float4 bi = ((const float4*)bias)[threadIdx.x];
    float4 o;
    o.x = dx * rstd * sc.x + bi.x;
    o.y = dy * rstd * sc.y + bi.y;
    o.z = dz * rstd * sc.z + bi.z;
    o.w = dw * rstd * sc.w + bi.w;
    ((float4*)(out + (size_t)row * D_))[threadIdx.x] = o;
}

// ---------------- kernel 2/5: tiled GEMM  C[M,N] = A[M,K] @ B[K,N] + bias ----------------
// 64x64 tile, BK=16, 256 threads (16x16), 4x4 micro-tile per thread.
__global__ __launch_bounds__(256) void gemm64(
    const float* __restrict__ A, const float* __restrict__ Bm,
    const float* __restrict__ bias, float* __restrict__ C,
    int M, int N, int K)
{
    __shared__ float At[16][FPAD];   // At[k][m]
    __shared__ float Bs[16][FPAD];   // Bs[k][n]

    int tid = threadIdx.x;
    int tx = tid & 15, ty = tid >> 4;
    int m0 = blockIdx.y * 64, n0 = blockIdx.x * 64;

    int ar = tid >> 2;           // 0..63
    int ak = (tid & 3) * 4;      // 0,4,8,12
    int bk = tid >> 4;           // 0..15
    int bc = (tid & 15) * 4;     // 0..60

    float acc[4][4];
    #pragma unroll
    for (int i = 0; i < 4; i++)
        #pragma unroll
        for (int j = 0; j < 4; j++) acc[i][j] = 0.f;

    for (int k0 = 0; k0 < K; k0 += 16) {
        float4 a = *(const float4*)&A[(size_t)(m0 + ar) * K + k0 + ak];
        At[ak + 0][ar] = a.x; At[ak + 1][ar] = a.y;
        At[ak + 2][ar] = a.z; At[ak + 3][ar] = a.w;
        float4 b = *(const float4*)&Bm[(size_t)(k0 + bk) * N + n0 + bc];
        *(float4*)&Bs[bk][bc] = b;
        __syncthreads();

        #pragma unroll
        for (int kk = 0; kk < 16; kk++) {
            float4 a4 = *(const float4*)&At[kk][ty * 4];
            float4 b4 = *(const float4*)&Bs[kk][tx * 4];
            float av[4] = {a4.x, a4.y, a4.z, a4.w};
            float bv[4] = {b4.x, b4.y, b4.z, b4.w};
            #pragma unroll
            for (int i = 0; i < 4; i++)
                #pragma unroll
                for (int j = 0; j < 4; j++)
                    acc[i][j] += av[i] * bv[j];
        }
        __syncthreads();
    }

    #pragma unroll
    for (int i = 0; i < 4; i++) {
        int row = m0 + ty * 4 + i;
        #pragma unroll
        for (int j = 0; j < 4; j++) {
            int col = n0 + tx * 4 + j;
            C[(size_t)row * N + col] = acc[i][j] + bias[col];
        }
    }
}

// ---------------- kernel 3: split qkv + per-head LN + RoPE ----------------
__global__ __launch_bounds__(64) void split_rope(
    const float* __restrict__ qkv, const float* __restrict__ q_scale,
    const float* __restrict__ k_scale,
    float* __restrict__ qO, float* __restrict__ kO, float* __restrict__ vO)
{
    __shared__ float qn[HD_], kn[HD_];
    __shared__ float red[8];

    int row = blockIdx.x;            // b*S + s
    int h   = blockIdx.y;
    int i   = threadIdx.x;           // 0..63
    int b   = row / S_;
    int s   = row - b * S_;

    const float* base = qkv + (size_t)row * (3 * D_) + h * HD_;
    float qv = base[i];
    float kv = base[D_ + i];
    float vv = base[2 * D_ + i];

    float qs = qv, qq = qv * qv, ks = kv, kq = kv * kv;
    #pragma unroll
    for (int o = 16; o; o >>= 1) {
        qs += __shfl_down_sync(0xffffffffu, qs, o);
        qq += __shfl_down_sync(0xffffffffu, qq, o);
        ks += __shfl_down_sync(0xffffffffu, ks, o);
        kq += __shfl_down_sync(0xffffffffu, kq, o);
    }
    if ((i & 31) == 0) {
        int w = i >> 5;
        red[w * 4 + 0] = qs; red[w * 4 + 1] = qq;
        red[w * 4 + 2] = ks; red[w * 4 + 3] = kq;
    }
    __syncthreads();
    qs = red[0] + red[4]; qq = red[1] + red[5];
    ks = red[2] + red[6]; kq = red[3] + red[7];

    float muq = qs * (1.0f / HD_);
    float vaq = qq * (1.0f / HD_) - muq * muq;
    float rq  = rsqrtf(vaq + EPS);
    float muk = ks * (1.0f / HD_);
    float vak = kq * (1.0f / HD_) - muk * muk;
    float rk  = rsqrtf(vak + EPS);

    qn[i] = (qv - muq) * rq * q_scale[i];
    kn[i] = (kv - muk) * rk * k_scale[i];
    __syncthreads();

    int j = i & 31;
    // inv_freq = 10000^(-2j/64)
    float inv = expf(-(float)(2 * j) * (1.0f / 64.0f) * 9.210340371976184f);
    float ang = (float)s * inv;
    float sn, cs;
    sincosf(ang, &sn, &cs);

    float qrot = (i < 32) ? -qn[i + 32] : qn[i - 32];
    float krot = (i < 32) ? -kn[i + 32] : kn[i - 32];

    size_t oidx = (((size_t)(b * H_ + h)) * S_ + s) * HD_ + i;
    qO[oidx] = qn[i] * cs + qrot * sn;
    kO[oidx] = kn[i] * cs + krot * sn;
    vO[oidx] = vv;
}

// ---------------- kernel 4: flash attention (fp32) ----------------
// grid: (S/64, B*H), 256 threads. BM=BN=64, online softmax.
__global__ __launch_bounds__(256) void flash_kernel(
    const float* __restrict__ Q, const float* __restrict__ K,
    const float* __restrict__ V, float* __restrict__ O)
{
    extern __shared__ float sm[];
    float* Qt = sm;                  // [64][FPAD]  Qt[d][r]
    float* Kt = Qt + 64 * FPAD;      // [64][FPAD]  Kt[d][c]
    float* Vs = Kt + 64 * FPAD;      // [64][FPAD]  Vs[j][c]
    float* St = Vs + 64 * FPAD;      // [64][FPAD]  St[c][r]  (scores transposed)
    float* rm = St + 64 * FPAD;      // [64] running max
    float* rl = rm + 64;             // [64] running sum
    float* ra = rl + 64;             // [64] alpha

    int tid = threadIdx.x;
    int tx = tid & 15, ty = tid >> 4;
    int bh = blockIdx.y;
    int b  = bh / H_, h = bh - b * H_;
    int q0 = blockIdx.x * 64;

    const float* Qp = Q + (size_t)bh * S_ * HD_;
    const float* Kp = K + (size_t)bh * S_ * HD_;
    const float* Vp = V + (size_t)bh * S_ * HD_;
    const float scale = 0.125f;      // 1/sqrt(64)

    // load Q tile (scaled), transposed
    {
        int r  = tid >> 2;
        int d0 = (tid & 3) * 16;
        #pragma unroll
        for (int ii = 0; ii < 4; ii++) {
            int d = d0 + ii * 4;
            float4 qv = *(const float4*)&Qp[(size_t)(q0 + r) * HD_ + d];
            Qt[(d + 0) * FPAD + r] = qv.x * scale;
            Qt[(d + 1) * FPAD + r] = qv.y * scale;
            Qt[(d + 2) * FPAD + r] = qv.z * scale;
            Qt[(d + 3) * FPAD + r] = qv.w * scale;
        }
    }
    if (tid < 64) { rm[tid] = -INFINITY; rl[tid] = 0.f; }

    float o[4][4];
    #pragma unroll
    for (int i = 0; i < 4; i++)
        #pragma unroll
        for (int j = 0; j < 4; j++) o[i][j] = 0.f;

    for (int kt = 0; kt < S_ / 64; kt++) {
        int j0 = kt * 64;
        // load K (transposed) and V tiles
        {
            int r  = tid >> 2;
            int d0 = (tid & 3) * 16;
            #pragma unroll
            for (int ii = 0; ii < 4; ii++) {
                int d = d0 + ii * 4;
                float4 kv = *(const float4*)&Kp[(size_t)(j0 + r) * HD_ + d];
                Kt[(d + 0) * FPAD + r] = kv.x;
                Kt[(d + 1) * FPAD + r] = kv.y;
                Kt[(d + 2) * FPAD + r] = kv.z;
                Kt[(d + 3) * FPAD + r] = kv.w;
                float4 vv = *(const float4*)&Vp[(size_t)(j0 + r) * HD_ + d];
                *(float4*)&Vs[r * FPAD + d] = vv;
            }
        }
        __syncthreads();

        // scores S = Q @ K^T (scaled)
        float sa[4][4];
        #pragma unroll
        for (int i = 0; i < 4; i++)
            #pragma unroll
            for (int j = 0; j < 4; j++) sa[i][j] = 0.f;

        #pragma unroll 8
        for (int d = 0; d < 64; d++) {
            float4 q4 = *(const float4*)&Qt[d * FPAD + ty * 4];
            float4 k4 = *(const float4*)&Kt[d * FPAD + tx * 4];
            float qv[4] = {q4.x, q4.y, q4.z, q4.w};
            float kv[4] = {k4.x, k4.y, k4.z, k4.w};
            #pragma unroll
            for (int i = 0; i < 4; i++)
                #pragma unroll
                for (int j = 0; j < 4; j++)
                    sa[i][j] += qv[i] * kv[j];
        }
        #pragma unroll
        for (int j = 0; j < 4; j++) {
            float4 w = make_float4(sa[0][j], sa[1][j], sa[2][j], sa[3][j]);
            *(float4*)&St[(tx * 4 + j) * FPAD + ty * 4] = w;
        }
        __syncthreads();

        // online softmax (one thread per row)
        if (tid < 64) {
            int r = tid;
            float mold = rm[r];
            float mx = mold;
            #pragma unroll 8
            for (int jj = 0; jj < 64; jj++) {
                float sv = St[jj * FPAD + r];
                mx = fmaxf(mx, sv);
            }
            float alpha = __expf(mold - mx);
            float sum = 0.f;
            #pragma unroll 8
            for (int jj = 0; jj < 64; jj++) {
                float p = __expf(St[jj * FPAD + r] - mx);
                St[jj * FPAD + r] = p;
                sum += p;
            }
            rl[r] = rl[r] * alpha + sum;
            rm[r] = mx;
            ra[r] = alpha;
        }
        __syncthreads();

        // O = O*alpha + P @ V
        #pragma unroll
        for (int i = 0; i < 4; i++) {
            float a = ra[ty * 4 + i];
            #pragma unroll
            for (int j = 0; j < 4; j++) o[i][j] *= a;
        }
        #pragma unroll 8
        for (int jj = 0; jj < 64; jj++) {
            float4 p4 = *(const float4*)&St[jj * FPAD + ty * 4];
            float4 v4 = *(const float4*)&Vs[jj * FPAD + tx * 4];
            float pv[4] = {p4.x, p4.y, p4.z, p4.w};
            float vv[4] = {v4.x, v4.y, v4.z, v4.w};
            #pragma unroll
            for (int i = 0; i < 4; i++)
                #pragma unroll
                for (int j = 0; j < 4; j++)
                    o[i][j] += pv[i] * vv[j];
        }
        __syncthreads();
    }

    // write O / l to attn buffer, layout [b, s, h, hd]
    #pragma unroll
    for (int i = 0; i < 4; i++) {
        int r = ty * 4 + i;
        float linv = 1.0f / rl[r];
        size_t base = (((size_t)(b * S_ + q0 + r)) * H_ + h) * HD_ + tx * 4;
        float4 w = make_float4(o[i][0] * linv, o[i][1] * linv,
                               o[i][2] * linv, o[i][3] * linv);
        *(float4*)&O[base] = w;
    }
}

// ---------------- launcher ----------------
extern "C" void kernel_launch(void* const* d_in, const int* in_sizes, int n_in,
                              void* d_out, int out_size)
{
    const float* x        = (const float*)d_in[0];
    const float* w_qkv    = (const float*)d_in[1];
    const float* b_qkv    = (const float*)d_in[2];
    const float* w_out    = (const float*)d_in[3];
    const float* b_out    = (const float*)d_in[4];
    const float* ln_scale = (const float*)d_in[5];
    const float* ln_bias  = (const float*)d_in[6];
    const float* q_scale  = (const float*)d_in[7];
    const float* k_scale  = (const float*)d_in[8];
    float* out = (float*)d_out;

    float *xn, *qkv, *q, *k, *v, *attn;
    cudaGetSymbolAddress((void**)&xn,   g_xn);
    cudaGetSymbolAddress((void**)&qkv,  g_qkv);
    cudaGetSymbolAddress((void**)&q,    g_q);
    cudaGetSymbolAddress((void**)&k,    g_k);
    cudaGetSymbolAddress((void**)&v,    g_v);
    cudaGetSymbolAddress((void**)&attn, g_attn);

    // 1. input layernorm
    ln_kernel<<<ROWS, 256>>>(x, ln_scale, ln_bias, xn);

    // 2. QKV GEMM: [4096,1024] @ [1024,3072] + bias
    gemm64<<<dim3((3 * D_) / 64, ROWS / 64), 256>>>(xn, w_qkv, b_qkv, qkv,
                                                    ROWS, 3 * D_, D_);

    // 3. split + per-head LN + RoPE
    split_rope<<<dim3(ROWS, H_), 64>>>(qkv, q_scale, k_scale, q, k, v);

    // 4. flash attention
    const int smem_bytes = (4 * 64 * FPAD + 3 * 64) * (int)sizeof(float);
    cudaFuncSetAttribute(flash_kernel,
                         cudaFuncAttributeMaxDynamicSharedMemorySize, smem_bytes);
    flash_kernel<<<dim3(S_ / 64, B_ * H_), 256, smem_bytes>>>(q, k, v, attn);

    // 5. output GEMM: [4096,1024] @ [1024,1024] + bias
    gemm64<<<dim3(D_ / 64, ROWS / 64), 256>>>(attn, w_out, b_out, out,
                                              ROWS, D_, D_);
}

// round 3
// speedup vs baseline: 2.0336x; 2.0336x over previous
#include <cuda_runtime.h>
#include <cuda_bf16.h>
#include <mma.h>
#include <cstdint>
#include <math.h>

using namespace nvcuda;

#define B_  2
#define S_  2048
#define D_  1024
#define H_  16
#define HD_ 64
#define EPS 1e-6f

#define ROWS (B_ * S_)          // 4096
#define FPAD 68                 // padded row stride for 64-wide smem tiles

// ---------------- scratch (device globals; no allocation) ----------------
__device__ __nv_bfloat16 g_xnh [ROWS * D_];
__device__ __nv_bfloat16 g_xnl [ROWS * D_];
__device__ __nv_bfloat16 g_wqT_h[3 * D_ * D_];   // [3072][1024] K-major
__device__ __nv_bfloat16 g_wqT_l[3 * D_ * D_];
__device__ __nv_bfloat16 g_woT_h[D_ * D_];       // [1024][1024] K-major
__device__ __nv_bfloat16 g_woT_l[D_ * D_];
__device__ float g_qkv [ROWS * 3 * D_];          // 48 MB
__device__ float g_q   [B_ * H_ * S_ * HD_];
__device__ float g_k   [B_ * H_ * S_ * HD_];
__device__ float g_v   [B_ * H_ * S_ * HD_];
__device__ __nv_bfloat16 g_attnh[ROWS * D_];
__device__ __nv_bfloat16 g_attnl[ROWS * D_];

// ---------------- block reduce (256 threads) ----------------
__device__ __forceinline__ float block_reduce_256(float v) {
    __shared__ float sh[8];
    #pragma unroll
    for (int o = 16; o; o >>= 1) v += __shfl_down_sync(0xffffffffu, v, o);
    if ((threadIdx.x & 31) == 0) sh[threadIdx.x >> 5] = v;
    __syncthreads();
    if (threadIdx.x == 0) {
        float t = 0.f;
        #pragma unroll
        for (int i = 0; i < 8; i++) t += sh[i];
        sh[0] = t;
    }
    __syncthreads();
    float r = sh[0];
    __syncthreads();
    return r;
}

// ---------------- kernel 1: input layernorm -> bf16 hi/lo ----------------
__global__ __launch_bounds__(256) void ln_kernel(
    const float* __restrict__ x, const float* __restrict__ scale,
    const float* __restrict__ bias,
    __nv_bfloat16* __restrict__ oh, __nv_bfloat16* __restrict__ ol)
{
    int row = blockIdx.x;
    const float4* xr = (const float4*)(x + (size_t)row * D_);
    float4 v = xr[threadIdx.x];

    float s = v.x + v.y + v.z + v.w;
    float tot = block_reduce_256(s);
    float mu = tot * (1.0f / D_);

    float dx = v.x - mu, dy = v.y - mu, dz = v.z - mu, dw = v.w - mu;
    float sq = dx*dx + dy*dy + dz*dz + dw*dw;
    float vtot = block_reduce_256(sq);
    float rstd = rsqrtf(vtot * (1.0f / D_) + EPS);

    float4 sc = ((const float4*)scale)[threadIdx.x];
    float4 bi = ((const float4*)bias)[threadIdx.x];
    float ov[4];
    ov[0] = dx * rstd * sc.x + bi.x;
    ov[1] = dy * rstd * sc.y + bi.y;
    ov[2] = dz * rstd * sc.z + bi.z;
    ov[3] = dw * rstd * sc.w + bi.w;

    size_t base = (size_t)row * D_ + threadIdx.x * 4;
    #pragma unroll
    for (int j = 0; j < 4; j += 2) {
        __nv_bfloat162 hp, lp;
        __nv_bfloat16 h0 = __float2bfloat16(ov[j]);
        __nv_bfloat16 h1 = __float2bfloat16(ov[j + 1]);
        hp.x = h0; hp.y = h1;
        lp.x = __float2bfloat16(ov[j]     - __bfloat162float(h0));
        lp.y = __float2bfloat16(ov[j + 1] - __bfloat162float(h1));
        *(__nv_bfloat162*)&oh[base + j] = hp;
        *(__nv_bfloat162*)&ol[base + j] = lp;
    }
}

// ---------------- weight transpose + bf16 split: W[K][N] -> T[N][K] ----------------
__global__ __launch_bounds__(256) void convT_kernel(
    const float* __restrict__ W,
    __nv_bfloat16* __restrict__ Th, __nv_bfloat16* __restrict__ Tl,
    int K, int N)
{
    __shared__ float t[32][33];
    int tx = threadIdx.x, ty = threadIdx.y;   // 32 x 8
    int nb = blockIdx.x * 32, kb = blockIdx.y * 32;
    #pragma unroll
    for (int i = 0; i < 4; i++)
        t[ty + 8 * i][tx] = W[(size_t)(kb + ty + 8 * i) * N + nb + tx];
    __syncthreads();
    #pragma unroll
    for (int i = 0; i < 4; i++) {
        int n = nb + ty + 8 * i, k = kb + tx;
        float v = t[tx][ty + 8 * i];
        __nv_bfloat16 h = __float2bfloat16(v);
        Th[(size_t)n * K + k] = h;
        Tl[(size_t)n * K + k] = __float2bfloat16(v - __bfloat162float(h));
    }
}

// ---------------- WMMA bf16x3 GEMM: C[M,N] = A[M,K] @ Bt[N,K]^T + bias ----------------
// Block tile 128x128, 8 warps (2 N x 4 M), warp tile 32x64, K-slab 32.
#define LDA 40   // padded k-stride (elements) for smem tiles

__global__ __launch_bounds__(256) void gemm_wmma(
    const __nv_bfloat16* __restrict__ Ah, const __nv_bfloat16* __restrict__ Al,
    const __nv_bfloat16* __restrict__ Bh, const __nv_bfloat16* __restrict__ Bl,
    const float* __restrict__ bias, float* __restrict__ C, int M, int N, int K)
{
    __shared__ __align__(32) __nv_bfloat16 sAh[128 * LDA];
    __shared__ __align__(32) __nv_bfloat16 sAl[128 * LDA];
    __shared__ __align__(32) __nv_bfloat16 sBh[128 * LDA];
    __shared__ __align__(32) __nv_bfloat16 sBl[128 * LDA];
    __shared__ __align__(32) float sbias[16 * 128];

    int tid = threadIdx.x;
    int w   = tid >> 5;
    int wm  = w >> 1;        // 0..3  (M direction, 32 rows each)
    int wn  = w & 1;         // 0..1  (N direction, 64 cols each)
    int m0 = blockIdx.y * 128, n0 = blockIdx.x * 128;

    // replicated bias tile (16 identical rows)
    for (int idx = tid; idx < 16 * 128; idx += 256)
        sbias[idx] = bias[n0 + (idx & 127)];
    __syncthreads();

    wmma::fragment<wmma::accumulator, 16, 16, 16, float> acc[2][4];
    #pragma unroll
    for (int i = 0; i < 2; i++)
        #pragma unroll
        for (int j = 0; j < 4; j++)
            wmma::load_matrix_sync(acc[i][j], &sbias[wn * 64 + j * 16], 128,
                                   wmma::mem_row_major);

    for (int kc = 0; kc < K; kc += 32) {
        // load 4 tiles: 128 rows x 32 bf16 each. 512 uint4 per tile.
        #pragma unroll
        for (int i = 0; i < 2; i++) {
            int u = tid + i * 256;
            int r = u >> 2, c = (u & 3) * 8;
            size_t goA = (size_t)(m0 + r) * K + kc + c;
            size_t goB = (size_t)(n0 + r) * K + kc + c;
            int so = r * LDA + c;
            *(uint4*)&sAh[so] = *(const uint4*)&Ah[goA];
            *(uint4*)&sAl[so] = *(const uint4*)&Al[goA];
            *(uint4*)&sBh[so] = *(const uint4*)&Bh[goB];
            *(uint4*)&sBl[so] = *(const uint4*)&Bl[goB];
        }
        __syncthreads();

        #pragma unroll
        for (int kk = 0; kk < 32; kk += 16) {
            wmma::fragment<wmma::matrix_b, 16, 16, 16, __nv_bfloat16, wmma::col_major> bh[4], bl[4];
            #pragma unroll
            for (int j = 0; j < 4; j++) {
                wmma::load_matrix_sync(bh[j], &sBh[(wn * 64 + j * 16) * LDA + kk], LDA);
                wmma::load_matrix_sync(bl[j], &sBl[(wn * 64 + j * 16) * LDA + kk], LDA);
            }
            #pragma unroll
            for (int i = 0; i < 2; i++) {
                wmma::fragment<wmma::matrix_a, 16, 16, 16, __nv_bfloat16, wmma::row_major> ah, al;
                wmma::load_matrix_sync(ah, &sAh[(wm * 32 + i * 16) * LDA + kk], LDA);
                wmma::load_matrix_sync(al, &sAl[(wm * 32 + i * 16) * LDA + kk], LDA);
                #pragma unroll
                for (int j = 0; j < 4; j++) {
                    wmma::mma_sync(acc[i][j], ah, bh[j], acc[i][j]);
                    wmma::mma_sync(acc[i][j], ah, bl[j], acc[i][j]);
                    wmma::mma_sync(acc[i][j], al, bh[j], acc[i][j]);
                }
            }
        }
        __syncthreads();
    }

    // direct store (bias already folded into accumulator init)
    #pragma unroll
    for (int i = 0; i < 2; i++) {
        int row = m0 + wm * 32 + i * 16;
        #pragma unroll
        for (int j = 0; j < 4; j++) {
            int col = n0 + wn * 64 + j * 16;
            wmma::store_matrix_sync(&C[(size_t)row * N + col], acc[i][j], N,
                                    wmma::mem_row_major);
        }
    }
}

// ---------------- kernel 3: split qkv + per-head LN + RoPE ----------------
__global__ __launch_bounds__(64) void split_rope(
    const float* __restrict__ qkv, const float* __restrict__ q_scale,
    const float* __restrict__ k_scale,
    float* __restrict__ qO, float* __restrict__ kO, float* __restrict__ vO)
{
    __shared__ float qn[HD_], kn[HD_];
    __shared__ float red[8];

    int row = blockIdx.x;            // b*S + s
    int h   = blockIdx.y;
    int i   = threadIdx.x;           // 0..63
    int b   = row / S_;
    int s   = row - b * S_;

    const float* base = qkv + (size_t)row * (3 * D_) + h * HD_;
    float qv = base[i];
    float kv = base[D_ + i];
    float vv = base[2 * D_ + i];

    float qs = qv, qq = qv * qv, ks = kv, kq = kv * kv;
    #pragma unroll
    for (int o = 16; o; o >>= 1) {
        qs += __shfl_down_sync(0xffffffffu, qs, o);
        qq += __shfl_down_sync(0xffffffffu, qq, o);
        ks += __shfl_down_sync(0xffffffffu, ks, o);
        kq += __shfl_down_sync(0xffffffffu, kq, o);
    }
    if ((i & 31) == 0) {
        int w = i >> 5;
        red[w * 4 + 0] = qs; red[w * 4 + 1] = qq;
        red[w * 4 + 2] = ks; red[w * 4 + 3] = kq;
    }
    __syncthreads();
    qs = red[0] + red[4]; qq = red[1] + red[5];
    ks = red[2] + red[6]; kq = red[3] + red[7];

    float muq = qs * (1.0f / HD_);
    float vaq = qq * (1.0f / HD_) - muq * muq;
    float rq  = rsqrtf(vaq + EPS);
    float muk = ks * (1.0f / HD_);
    float vak = kq * (1.0f / HD_) - muk * muk;
    float rk  = rsqrtf(vak + EPS);

    qn[i] = (qv - muq) * rq * q_scale[i];
    kn[i] = (kv - muk) * rk * k_scale[i];
    __syncthreads();

    int j = i & 31;
    float inv = expf(-(float)(2 * j) * (1.0f / 64.0f) * 9.210340371976184f);
    float ang = (float)s * inv;
    float sn, cs;
    sincosf(ang, &sn, &cs);

    float qrot = (i < 32) ? -qn[i + 32] : qn[i - 32];
    float krot = (i < 32) ? -kn[i + 32] : kn[i - 32];

    size_t oidx = (((size_t)(b * H_ + h)) * S_ + s) * HD_ + i;
    qO[oidx] = qn[i] * cs + qrot * sn;
    kO[oidx] = kn[i] * cs + krot * sn;
    vO[oidx] = vv;
}

// ---------------- kernel 4: flash attention (fp32) ----------------
__global__ __launch_bounds__(256) void flash_kernel(
    const float* __restrict__ Q, const float* __restrict__ K,
    const float* __restrict__ V,
    __nv_bfloat16* __restrict__ Oh, __nv_bfloat16* __restrict__ Ol)
{
    extern __shared__ float sm[];
    float* Qt = sm;                  // [64][FPAD]  Qt[d][r]
    float* Kt = Qt + 64 * FPAD;      // [64][FPAD]
    float* Vs = Kt + 64 * FPAD;      // [64][FPAD]
    float* St = Vs + 64 * FPAD;      // [64][FPAD]
    float* rm = St + 64 * FPAD;
    float* rl = rm + 64;
    float* ra = rl + 64;

    int tid = threadIdx.x;
    int tx = tid & 15, ty = tid >> 4;
    int bh = blockIdx.y;
    int b  = bh / H_, h = bh - b * H_;
    int q0 = blockIdx.x * 64;

    const float* Qp = Q + (size_t)bh * S_ * HD_;
    const float* Kp = K + (size_t)bh * S_ * HD_;
    const float* Vp = V + (size_t)bh * S_ * HD_;
    const float scale = 0.125f;

    {
        int r  = tid >> 2;
        int d0 = (tid & 3) * 16;
        #pragma unroll
        for (int ii = 0; ii < 4; ii++) {
            int d = d0 + ii * 4;
            float4 qv = *(const float4*)&Qp[(size_t)(q0 + r) * HD_ + d];
            Qt[(d + 0) * FPAD + r] = qv.x * scale;
            Qt[(d + 1) * FPAD + r] = qv.y * scale;
            Qt[(d + 2) * FPAD + r] = qv.z * scale;
            Qt[(d + 3) * FPAD + r] = qv.w * scale;
        }
    }
    if (tid < 64) { rm[tid] = -INFINITY; rl[tid] = 0.f; }

    float o[4][4];
    #pragma unroll
    for (int i = 0; i < 4; i++)
        #pragma unroll
        for (int j = 0; j < 4; j++) o[i][j] = 0.f;

    for (int kt = 0; kt < S_ / 64; kt++) {
        int j0 = kt * 64;
        {
            int r  = tid >> 2;
            int d0 = (tid & 3) * 16;
            #pragma unroll
            for (int ii = 0; ii < 4; ii++) {
                int d = d0 + ii * 4;
                float4 kv = *(const float4*)&Kp[(size_t)(j0 + r) * HD_ + d];
                Kt[(d + 0) * FPAD + r] = kv.x;
                Kt[(d + 1) * FPAD + r] = kv.y;
                Kt[(d + 2) * FPAD + r] = kv.z;
                Kt[(d + 3) * FPAD + r] = kv.w;
                float4 vv = *(const float4*)&Vp[(size_t)(j0 + r) * HD_ + d];
                *(float4*)&Vs[r * FPAD + d] = vv;
            }
        }
        __syncthreads();

        float sa[4][4];
        #pragma unroll
        for (int i = 0; i < 4; i++)
            #pragma unroll
            for (int j = 0; j < 4; j++) sa[i][j] = 0.f;

        #pragma unroll 8
        for (int d = 0; d < 64; d++) {
            float4 q4 = *(const float4*)&Qt[d * FPAD + ty * 4];
            float4 k4 = *(const float4*)&Kt[d * FPAD + tx * 4];
            float qv[4] = {q4.x, q4.y, q4.z, q4.w};
            float kv[4] = {k4.x, k4.y, k4.z, k4.w};
            #pragma unroll
            for (int i = 0; i < 4; i++)
                #pragma unroll
                for (int j = 0; j < 4; j++)
                    sa[i][j] += qv[i] * kv[j];
        }
        #pragma unroll
        for (int j = 0; j < 4; j++) {
            float4 w = make_float4(sa[0][j], sa[1][j], sa[2][j], sa[3][j]);
            *(float4*)&St[(tx * 4 + j) * FPAD + ty * 4] = w;
        }
        __syncthreads();

        if (tid < 64) {
            int r = tid;
            float mold = rm[r];
            float mx = mold;
            #pragma unroll 8
            for (int jj = 0; jj < 64; jj++) {
                float sv = St[jj * FPAD + r];
                mx = fmaxf(mx, sv);
            }
            float alpha = __expf(mold - mx);
            float sum = 0.f;
            #pragma unroll 8
            for (int jj = 0; jj < 64; jj++) {
                float p = __expf(St[jj * FPAD + r] - mx);
                St[jj * FPAD + r] = p;
                sum += p;
            }
            rl[r] = rl[r] * alpha + sum;
            rm[r] = mx;
            ra[r] = alpha;
        }
        __syncthreads();

        #pragma unroll
        for (int i = 0; i < 4; i++) {
            float a = ra[ty * 4 + i];
            #pragma unroll
            for (int j = 0; j < 4; j++) o[i][j] *= a;
        }
        #pragma unroll 8
        for (int jj = 0; jj < 64; jj++) {
            float4 p4 = *(const float4*)&St[jj * FPAD + ty * 4];
            float4 v4 = *(const float4*)&Vs[jj * FPAD + tx * 4];
            float pv[4] = {p4.x, p4.y, p4.z, p4.w};
            float vv[4] = {v4.x, v4.y, v4.z, v4.w};
            #pragma unroll
            for (int i = 0; i < 4; i++)
                #pragma unroll
                for (int j = 0; j < 4; j++)
                    o[i][j] += pv[i] * vv[j];
        }
        __syncthreads();
    }

    // epilogue: write attn as bf16 hi/lo, layout [b, s, h, hd]
    #pragma unroll
    for (int i = 0; i < 4; i++) {
        int r = ty * 4 + i;
        float linv = 1.0f / rl[r];
        size_t base = (((size_t)(b * S_ + q0 + r)) * H_ + h) * HD_ + tx * 4;
        float v0 = o[i][0] * linv, v1 = o[i][1] * linv;
        float v2 = o[i][2] * linv, v3 = o[i][3] * linv;
        __nv_bfloat16 h0 = __float2bfloat16(v0), h1 = __float2bfloat16(v1);
        __nv_bfloat16 h2 = __float2bfloat16(v2), h3 = __float2bfloat16(v3);
        __nv_bfloat162 p;
        p.x = h0; p.y = h1; *(__nv_bfloat162*)&Oh[base + 0] = p;
        p.x = h2; p.y = h3; *(__nv_bfloat162*)&Oh[base + 2] = p;
        p.x = __float2bfloat16(v0 - __bfloat162float(h0));
        p.y = __float2bfloat16(v1 - __bfloat162float(h1));
        *(__nv_bfloat162*)&Ol[base + 0] = p;
        p.x = __float2bfloat16(v2 - __bfloat162float(h2));
        p.y = __float2bfloat16(v3 - __bfloat162float(h3));
        *(__nv_bfloat162*)&Ol[base + 2] = p;
    }
}

// ---------------- launcher ----------------
extern "C" void kernel_launch(void* const* d_in, const int* in_sizes, int n_in,
                              void* d_out, int out_size)
{
    const float* x        = (const float*)d_in[0];
    const float* w_qkv    = (const float*)d_in[1];
    const float* b_qkv    = (const float*)d_in[2];
    const float* w_out    = (const float*)d_in[3];
    const float* b_out    = (const float*)d_in[4];
    const float* ln_scale = (const float*)d_in[5];
    const float* ln_bias  = (const float*)d_in[6];
    const float* q_scale  = (const float*)d_in[7];
    const float* k_scale  = (const float*)d_in[8];
    float* out = (float*)d_out;

    __nv_bfloat16 *xnh, *xnl, *wqh, *wql, *woh, *wol, *ath, *atl;
    float *qkv, *q, *k, *v;
    cudaGetSymbolAddress((void**)&xnh, g_xnh);
    cudaGetSymbolAddress((void**)&xnl, g_xnl);
    cudaGetSymbolAddress((void**)&wqh, g_wqT_h);
    cudaGetSymbolAddress((void**)&wql, g_wqT_l);
    cudaGetSymbolAddress((void**)&woh, g_woT_h);
    cudaGetSymbolAddress((void**)&wol, g_woT_l);
    cudaGetSymbolAddress((void**)&qkv, g_qkv);
    cudaGetSymbolAddress((void**)&q,   g_q);
    cudaGetSymbolAddress((void**)&k,   g_k);
    cudaGetSymbolAddress((void**)&v,   g_v);
    cudaGetSymbolAddress((void**)&ath, g_attnh);
    cudaGetSymbolAddress((void**)&atl, g_attnl);

    // 1. input layernorm -> bf16 hi/lo
    ln_kernel<<<ROWS, 256>>>(x, ln_scale, ln_bias, xnh, xnl);

    // 2. weight transpose+split
    convT_kernel<<<dim3((3 * D_) / 32, D_ / 32), dim3(32, 8)>>>(w_qkv, wqh, wql, D_, 3 * D_);
    convT_kernel<<<dim3(D_ / 32, D_ / 32), dim3(32, 8)>>>(w_out, woh, wol, D_, D_);

    // 3. QKV GEMM (WMMA bf16x3): [4096,1024] x [1024,3072]
    gemm_wmma<<<dim3((3 * D_) / 128, ROWS / 128), 256>>>(
        xnh, xnl, wqh, wql, b_qkv, qkv, ROWS, 3 * D_, D_);

    // 4. split + per-head LN + RoPE
    split_rope<<<dim3(ROWS, H_), 64>>>(qkv, q_scale, k_scale, q, k, v);

    // 5. flash attention (fp32) -> bf16 hi/lo attn
    const int smem_bytes = (4 * 64 * FPAD + 3 * 64) * (int)sizeof(float);
    cudaFuncSetAttribute(flash_kernel,
                         cudaFuncAttributeMaxDynamicSharedMemorySize, smem_bytes);
    flash_kernel<<<dim3(S_ / 64, B_ * H_), 256, smem_bytes>>>(q, k, v, ath, atl);

    // 6. output GEMM (WMMA bf16x3): [4096,1024] x [1024,1024]
    gemm_wmma<<<dim3(D_ / 128, ROWS / 128), 256>>>(
        ath, atl, woh, wol, b_out, out, ROWS, D_, D_);
}

// round 4
// speedup vs baseline: 3.7375x; 1.8379x over previous
#include <cuda_runtime.h>
#include <cuda_bf16.h>
#include <mma.h>
#include <cstdint>
#include <math.h>

using namespace nvcuda;

#define B_  2
#define S_  2048
#define D_  1024
#define H_  16
#define HD_ 64
#define EPS 1e-6f

#define ROWS (B_ * S_)          // 4096

// ---------------- scratch (device globals; no allocation) ----------------
__device__ __nv_bfloat16 g_xnh [ROWS * D_];
__device__ __nv_bfloat16 g_xnl [ROWS * D_];
__device__ __nv_bfloat16 g_wqT_h[3 * D_ * D_];   // [3072][1024] K-major
__device__ __nv_bfloat16 g_wqT_l[3 * D_ * D_];
__device__ __nv_bfloat16 g_woT_h[D_ * D_];       // [1024][1024] K-major
__device__ __nv_bfloat16 g_woT_l[D_ * D_];
__device__ float g_qkv [ROWS * 3 * D_];          // 48 MB
__device__ __nv_bfloat16 g_qh[B_ * H_ * S_ * HD_];
__device__ __nv_bfloat16 g_ql[B_ * H_ * S_ * HD_];
__device__ __nv_bfloat16 g_kh[B_ * H_ * S_ * HD_];
__device__ __nv_bfloat16 g_kl[B_ * H_ * S_ * HD_];
__device__ __nv_bfloat16 g_vh[B_ * H_ * S_ * HD_];
__device__ __nv_bfloat16 g_vl[B_ * H_ * S_ * HD_];
__device__ __nv_bfloat16 g_attnh[ROWS * D_];
__device__ __nv_bfloat16 g_attnl[ROWS * D_];

// ---------------- block reduce (256 threads) ----------------
__device__ __forceinline__ float block_reduce_256(float v) {
    __shared__ float sh[8];
    #pragma unroll
    for (int o = 16; o; o >>= 1) v += __shfl_down_sync(0xffffffffu, v, o);
    if ((threadIdx.x & 31) == 0) sh[threadIdx.x >> 5] = v;
    __syncthreads();
    if (threadIdx.x == 0) {
        float t = 0.f;
        #pragma unroll
        for (int i = 0; i < 8; i++) t += sh[i];
        sh[0] = t;
    }
    __syncthreads();
    float r = sh[0];
    __syncthreads();
    return r;
}

// ---------------- kernel 1: input layernorm -> bf16 hi/lo ----------------
__global__ __launch_bounds__(256) void ln_kernel(
    const float* __restrict__ x, const float* __restrict__ scale,
    const float* __restrict__ bias,
    __nv_bfloat16* __restrict__ oh, __nv_bfloat16* __restrict__ ol)
{
    int row = blockIdx.x;
    const float4* xr = (const float4*)(x + (size_t)row * D_);
    float4 v = xr[threadIdx.x];

    float s = v.x + v.y + v.z + v.w;
    float tot = block_reduce_256(s);
    float mu = tot * (1.0f / D_);

    float dx = v.x - mu, dy = v.y - mu, dz = v.z - mu, dw = v.w - mu;
    float sq = dx*dx + dy*dy + dz*dz + dw*dw;
    float vtot = block_reduce_256(sq);
    float rstd = rsqrtf(vtot * (1.0f / D_) + EPS);

    float4 sc = ((const float4*)scale)[threadIdx.x];
    float4 bi = ((const float4*)bias)[threadIdx.x];
    float ov[4];
    ov[0] = dx * rstd * sc.x + bi.x;
    ov[1] = dy * rstd * sc.y + bi.y;
    ov[2] = dz * rstd * sc.z + bi.z;
    ov[3] = dw * rstd * sc.w + bi.w;

    size_t base = (size_t)row * D_ + threadIdx.x * 4;
    #pragma unroll
    for (int j = 0; j < 4; j += 2) {
        __nv_bfloat162 hp, lp;
        __nv_bfloat16 h0 = __float2bfloat16(ov[j]);
        __nv_bfloat16 h1 = __float2bfloat16(ov[j + 1]);
        hp.x = h0; hp.y = h1;
        lp.x = __float2bfloat16(ov[j]     - __bfloat162float(h0));
        lp.y = __float2bfloat16(ov[j + 1] - __bfloat162float(h1));
        *(__nv_bfloat162*)&oh[base + j] = hp;
        *(__nv_bfloat162*)&ol[base + j] = lp;
    }
}

// ---------------- weight transpose + bf16 split: W[K][N] -> T[N][K] ----------------
__global__ __launch_bounds__(256) void convT_kernel(
    const float* __restrict__ W,
    __nv_bfloat16* __restrict__ Th, __nv_bfloat16* __restrict__ Tl,
    int K, int N)
{
    __shared__ float t[32][33];
    int tx = threadIdx.x, ty = threadIdx.y;   // 32 x 8
    int nb = blockIdx.x * 32, kb = blockIdx.y * 32;
    #pragma unroll
    for (int i = 0; i < 4; i++)
        t[ty + 8 * i][tx] = W[(size_t)(kb + ty + 8 * i) * N + nb + tx];
    __syncthreads();
    #pragma unroll
    for (int i = 0; i < 4; i++) {
        int n = nb + ty + 8 * i, k = kb + tx;
        float v = t[tx][ty + 8 * i];
        __nv_bfloat16 h = __float2bfloat16(v);
        Th[(size_t)n * K + k] = h;
        Tl[(size_t)n * K + k] = __float2bfloat16(v - __bfloat162float(h));
    }
}

// ---------------- WMMA bf16x3 GEMM (unchanged from R3) ----------------
#define LDA 40

__global__ __launch_bounds__(256) void gemm_wmma(
    const __nv_bfloat16* __restrict__ Ah, const __nv_bfloat16* __restrict__ Al,
    const __nv_bfloat16* __restrict__ Bh, const __nv_bfloat16* __restrict__ Bl,
    const float* __restrict__ bias, float* __restrict__ C, int M, int N, int K)
{
    __shared__ __align__(32) __nv_bfloat16 sAh[128 * LDA];
    __shared__ __align__(32) __nv_bfloat16 sAl[128 * LDA];
    __shared__ __align__(32) __nv_bfloat16 sBh[128 * LDA];
    __shared__ __align__(32) __nv_bfloat16 sBl[128 * LDA];
    __shared__ __align__(32) float sbias[16 * 128];

    int tid = threadIdx.x;
    int w   = tid >> 5;
    int wm  = w >> 1;
    int wn  = w & 1;
    int m0 = blockIdx.y * 128, n0 = blockIdx.x * 128;

    for (int idx = tid; idx < 16 * 128; idx += 256)
        sbias[idx] = bias[n0 + (idx & 127)];
    __syncthreads();

    wmma::fragment<wmma::accumulator, 16, 16, 16, float> acc[2][4];
    #pragma unroll
    for (int i = 0; i < 2; i++)
        #pragma unroll
        for (int j = 0; j < 4; j++)
            wmma::load_matrix_sync(acc[i][j], &sbias[wn * 64 + j * 16], 128,
                                   wmma::mem_row_major);

    for (int kc = 0; kc < K; kc += 32) {
        #pragma unroll
        for (int i = 0; i < 2; i++) {
            int u = tid + i * 256;
            int r = u >> 2, c = (u & 3) * 8;
            size_t goA = (size_t)(m0 + r) * K + kc + c;
            size_t goB = (size_t)(n0 + r) * K + kc + c;
            int so = r * LDA + c;
            *(uint4*)&sAh[so] = *(const uint4*)&Ah[goA];
            *(uint4*)&sAl[so] = *(const uint4*)&Al[goA];
            *(uint4*)&sBh[so] = *(const uint4*)&Bh[goB];
            *(uint4*)&sBl[so] = *(const uint4*)&Bl[goB];
        }
        __syncthreads();

        #pragma unroll
        for (int kk = 0; kk < 32; kk += 16) {
            wmma::fragment<wmma::matrix_b, 16, 16, 16, __nv_bfloat16, wmma::col_major> bh[4], bl[4];
            #pragma unroll
            for (int j = 0; j < 4; j++) {
                wmma::load_matrix_sync(bh[j], &sBh[(wn * 64 + j * 16) * LDA + kk], LDA);
                wmma::load_matrix_sync(bl[j], &sBl[(wn * 64 + j * 16) * LDA + kk], LDA);
            }
            #pragma unroll
            for (int i = 0; i < 2; i++) {
                wmma::fragment<wmma::matrix_a, 16, 16, 16, __nv_bfloat16, wmma::row_major> ah, al;
                wmma::load_matrix_sync(ah, &sAh[(wm * 32 + i * 16) * LDA + kk], LDA);
                wmma::load_matrix_sync(al, &sAl[(wm * 32 + i * 16) * LDA + kk], LDA);
                #pragma unroll
                for (int j = 0; j < 4; j++) {
                    wmma::mma_sync(acc[i][j], ah, bh[j], acc[i][j]);
                    wmma::mma_sync(acc[i][j], ah, bl[j], acc[i][j]);
                    wmma::mma_sync(acc[i][j], al, bh[j], acc[i][j]);
                }
            }
        }
        __syncthreads();
    }

    #pragma unroll
    for (int i = 0; i < 2; i++) {
        int row = m0 + wm * 32 + i * 16;
        #pragma unroll
        for (int j = 0; j < 4; j++) {
            int col = n0 + wn * 64 + j * 16;
            wmma::store_matrix_sync(&C[(size_t)row * N + col], acc[i][j], N,
                                    wmma::mem_row_major);
        }
    }
}

// ---------------- kernel 3: split qkv + per-head LN + RoPE -> bf16 hi/lo ----------------
__global__ __launch_bounds__(64) void split_rope(
    const float* __restrict__ qkv, const float* __restrict__ q_scale,
    const float* __restrict__ k_scale,
    __nv_bfloat16* __restrict__ qh, __nv_bfloat16* __restrict__ ql,
    __nv_bfloat16* __restrict__ kh, __nv_bfloat16* __restrict__ kl,
    __nv_bfloat16* __restrict__ vh, __nv_bfloat16* __restrict__ vl)
{
    __shared__ float qn[HD_], kn[HD_];
    __shared__ float red[8];

    int row = blockIdx.x;
    int h   = blockIdx.y;
    int i   = threadIdx.x;
    int b   = row / S_;
    int s   = row - b * S_;

    const float* base = qkv + (size_t)row * (3 * D_) + h * HD_;
    float qv = base[i];
    float kv = base[D_ + i];
    float vv = base[2 * D_ + i];

    float qs = qv, qsq = qv * qv, ks = kv, ksq = kv * kv;
    #pragma unroll
    for (int o = 16; o; o >>= 1) {
        qs  += __shfl_down_sync(0xffffffffu, qs, o);
        qsq += __shfl_down_sync(0xffffffffu, qsq, o);
        ks  += __shfl_down_sync(0xffffffffu, ks, o);
        ksq += __shfl_down_sync(0xffffffffu, ksq, o);
    }
    if ((i & 31) == 0) {
        int w = i >> 5;
        red[w * 4 + 0] = qs; red[w * 4 + 1] = qsq;
        red[w * 4 + 2] = ks; red[w * 4 + 3] = ksq;
    }
    __syncthreads();
    qs = red[0] + red[4]; qsq = red[1] + red[5];
    ks = red[2] + red[6]; ksq = red[3] + red[7];

    float muq = qs * (1.0f / HD_);
    float vaq = qsq * (1.0f / HD_) - muq * muq;
    float rq  = rsqrtf(vaq + EPS);
    float muk = ks * (1.0f / HD_);
    float vak = ksq * (1.0f / HD_) - muk * muk;
    float rk  = rsqrtf(vak + EPS);

    qn[i] = (qv - muq) * rq * q_scale[i];
    kn[i] = (kv - muk) * rk * k_scale[i];
    __syncthreads();

    int j = i & 31;
    float inv = expf(-(float)(2 * j) * (1.0f / 64.0f) * 9.210340371976184f);
    float ang = (float)s * inv;
    float sn, cs;
    sincosf(ang, &sn, &cs);

    float qrot = (i < 32) ? -qn[i + 32] : qn[i - 32];
    float krot = (i < 32) ? -kn[i + 32] : kn[i - 32];

    float qf = (qn[i] * cs + qrot * sn) * 0.125f;   // fold 1/sqrt(64)
    float kf = kn[i] * cs + krot * sn;

    size_t oidx = (((size_t)(b * H_ + h)) * S_ + s) * HD_ + i;
    __nv_bfloat16 t;
    t = __float2bfloat16(qf); qh[oidx] = t; ql[oidx] = __float2bfloat16(qf - __bfloat162float(t));
    t = __float2bfloat16(kf); kh[oidx] = t; kl[oidx] = __float2bfloat16(kf - __bfloat162float(t));
    t = __float2bfloat16(vv); vh[oidx] = t; vl[oidx] = __float2bfloat16(vv - __bfloat162float(t));
}

// ---------------- flash attention on tensor cores (mma.sync bf16x3) ----------------
#define LQ 72   // row stride: bank(frag load) = (4g+q) -> conflict-free

__device__ __forceinline__ void mma16816(float* c, const uint32_t* a, const uint32_t* b) {
    asm volatile(
        "mma.sync.aligned.m16n8k16.row.col.f32.bf16.bf16.f32 "
        "{%0,%1,%2,%3}, {%4,%5,%6,%7}, {%8,%9}, {%0,%1,%2,%3};"
        : "+f"(c[0]), "+f"(c[1]), "+f"(c[2]), "+f"(c[3])
        : "r"(a[0]), "r"(a[1]), "r"(a[2]), "r"(a[3]),
          "r"(b[0]), "r"(b[1]));
}
__device__ __forceinline__ uint32_t bf2u(__nv_bfloat162 v) { return *(uint32_t*)&v; }

__global__ __launch_bounds__(256, 2) void flash_mma(
    const __nv_bfloat16* __restrict__ Qh_, const __nv_bfloat16* __restrict__ Ql_,
    const __nv_bfloat16* __restrict__ Kh_, const __nv_bfloat16* __restrict__ Kl_,
    const __nv_bfloat16* __restrict__ Vh_, const __nv_bfloat16* __restrict__ Vl_,
    __nv_bfloat16* __restrict__ Oh_, __nv_bfloat16* __restrict__ Ol_)
{
    extern __shared__ __nv_bfloat16 fsm[];
    __nv_bfloat16* sQh = fsm;                 // [128][LQ]
    __nv_bfloat16* sQl = sQh + 128 * LQ;
    __nv_bfloat16* sKh = sQl + 128 * LQ;      // [64][LQ]
    __nv_bfloat16* sKl = sKh + 64 * LQ;
    __nv_bfloat16* sVh = sKl + 64 * LQ;       // [64(j)][LQ] row-major (j, d)
    __nv_bfloat16* sVl = sVh + 64 * LQ;

    int tid = threadIdx.x, lane = tid & 31, wid = tid >> 5;
    int g = lane >> 2, qi = lane & 3;
    int bh = blockIdx.y;
    int b = bh >> 4, h = bh & 15;
    int q0 = blockIdx.x * 128;
    size_t hbase = (size_t)bh * S_ * HD_;
    const __nv_bfloat16* Qhp = Qh_ + hbase;
    const __nv_bfloat16* Qlp = Ql_ + hbase;
    const __nv_bfloat16* Khp = Kh_ + hbase;
    const __nv_bfloat16* Klp = Kl_ + hbase;
    const __nv_bfloat16* Vhp = Vh_ + hbase;
    const __nv_bfloat16* Vlp = Vl_ + hbase;

    // load Q tiles (persistent)
    #pragma unroll
    for (int i = 0; i < 4; i++) {
        int u = tid + i * 256;
        int r = u >> 3, c = (u & 7) * 8;
        *(uint4*)&sQh[r * LQ + c] = *(const uint4*)&Qhp[(size_t)(q0 + r) * HD_ + c];
        *(uint4*)&sQl[r * LQ + c] = *(const uint4*)&Qlp[(size_t)(q0 + r) * HD_ + c];
    }

    float o[8][4];
    #pragma unroll
    for (int t = 0; t < 8; t++)
        #pragma unroll
        for (int e = 0; e < 4; e++) o[t][e] = 0.f;
    float m_g = -1e30f, m_g8 = -1e30f, l_g = 0.f, l_g8 = 0.f;
    int wr = wid * 16;

    for (int kt = 0; kt < S_ / 64; kt++) {
        int j0 = kt * 64;
        __syncthreads();
        {
            int r = tid >> 2, c = (tid & 3) * 16;
            size_t go = (size_t)(j0 + r) * HD_ + c;
            int so = r * LQ + c;
            *(uint4*)&sKh[so]     = *(const uint4*)&Khp[go];
            *(uint4*)&sKh[so + 8] = *(const uint4*)&Khp[go + 8];
            *(uint4*)&sKl[so]     = *(const uint4*)&Klp[go];
            *(uint4*)&sKl[so + 8] = *(const uint4*)&Klp[go + 8];
            *(uint4*)&sVh[so]     = *(const uint4*)&Vhp[go];
            *(uint4*)&sVh[so + 8] = *(const uint4*)&Vhp[go + 8];
            *(uint4*)&sVl[so]     = *(const uint4*)&Vlp[go];
            *(uint4*)&sVl[so + 8] = *(const uint4*)&Vlp[go + 8];
        }
        __syncthreads();

        // ---- S = Q K^T (bf16x3) ----
        float s[8][4];
        #pragma unroll
        for (int t = 0; t < 8; t++)
            #pragma unroll
            for (int e = 0; e < 4; e++) s[t][e] = 0.f;

        #pragma unroll
        for (int u = 0; u < 4; u++) {
            int d0 = u * 16 + 2 * qi;
            uint32_t ah[4], al[4];
            ah[0] = *(const uint32_t*)&sQh[(wr + g)     * LQ + d0];
            ah[1] = *(const uint32_t*)&sQh[(wr + g + 8) * LQ + d0];
            ah[2] = *(const uint32_t*)&sQh[(wr + g)     * LQ + d0 + 8];
            ah[3] = *(const uint32_t*)&sQh[(wr + g + 8) * LQ + d0 + 8];
            al[0] = *(const uint32_t*)&sQl[(wr + g)     * LQ + d0];
            al[1] = *(const uint32_t*)&sQl[(wr + g + 8) * LQ + d0];
            al[2] = *(const uint32_t*)&sQl[(wr + g)     * LQ + d0 + 8];
            al[3] = *(const uint32_t*)&sQl[(wr + g + 8) * LQ + d0 + 8];
            #pragma unroll
            for (int t = 0; t < 8; t++) {
                int kr = (8 * t + g) * LQ + d0;
                uint32_t bh2[2], bl2[2];
                bh2[0] = *(const uint32_t*)&sKh[kr];
                bh2[1] = *(const uint32_t*)&sKh[kr + 8];
                bl2[0] = *(const uint32_t*)&sKl[kr];
                bl2[1] = *(const uint32_t*)&sKl[kr + 8];
                mma16816(s[t], ah, bh2);
                mma16816(s[t], ah, bl2);
                mma16816(s[t], al, bh2);
            }
        }

        // ---- online softmax (registers + 2 shuffles) ----
        float mt_g = -1e30f, mt_g8 = -1e30f;
        #pragma unroll
        for (int t = 0; t < 8; t++) {
            mt_g  = fmaxf(mt_g,  fmaxf(s[t][0], s[t][1]));
            mt_g8 = fmaxf(mt_g8, fmaxf(s[t][2], s[t][3]));
        }
        mt_g  = fmaxf(mt_g,  __shfl_xor_sync(0xffffffffu, mt_g, 1));
        mt_g  = fmaxf(mt_g,  __shfl_xor_sync(0xffffffffu, mt_g, 2));
        mt_g8 = fmaxf(mt_g8, __shfl_xor_sync(0xffffffffu, mt_g8, 1));
        mt_g8 = fmaxf(mt_g8, __shfl_xor_sync(0xffffffffu, mt_g8, 2));
        float mn_g = fmaxf(m_g, mt_g), mn_g8 = fmaxf(m_g8, mt_g8);
        float al_g = __expf(m_g - mn_g), al_g8 = __expf(m_g8 - mn_g8);
        m_g = mn_g; m_g8 = mn_g8;

        uint32_t ph01[8], ph23[8], pl01[8], pl23[8];
        float sum_g = 0.f, sum_g8 = 0.f;
        #pragma unroll
        for (int t = 0; t < 8; t++) {
            float p0 = __expf(s[t][0] - mn_g);
            float p1 = __expf(s[t][1] - mn_g);
            float p2 = __expf(s[t][2] - mn_g8);
            float p3 = __expf(s[t][3] - mn_g8);
            sum_g += p0 + p1; sum_g8 += p2 + p3;
            __nv_bfloat162 hh = __floats2bfloat162_rn(p0, p1);
            ph01[t] = bf2u(hh);
            pl01[t] = bf2u(__floats2bfloat162_rn(p0 - __bfloat162float(hh.x),
                                                 p1 - __bfloat162float(hh.y)));
            hh = __floats2bfloat162_rn(p2, p3);
            ph23[t] = bf2u(hh);
            pl23[t] = bf2u(__floats2bfloat162_rn(p2 - __bfloat162float(hh.x),
                                                 p3 - __bfloat162float(hh.y)));
        }
        sum_g  += __shfl_xor_sync(0xffffffffu, sum_g, 1);
        sum_g  += __shfl_xor_sync(0xffffffffu, sum_g, 2);
        sum_g8 += __shfl_xor_sync(0xffffffffu, sum_g8, 1);
        sum_g8 += __shfl_xor_sync(0xffffffffu, sum_g8, 2);
        l_g  = l_g  * al_g  + sum_g;
        l_g8 = l_g8 * al_g8 + sum_g8;

        #pragma unroll
        for (int t = 0; t < 8; t++) {
            o[t][0] *= al_g;  o[t][1] *= al_g;
            o[t][2] *= al_g8; o[t][3] *= al_g8;
        }

        // ---- O += P V (P register-resident; bf16x3) ----
        #pragma unroll
        for (int u = 0; u < 4; u++) {
            uint32_t pah[4] = {ph01[2*u], ph23[2*u], ph01[2*u+1], ph23[2*u+1]};
            uint32_t pal[4] = {pl01[2*u], pl23[2*u], pl01[2*u+1], pl23[2*u+1]};
            int jr = u * 16 + 2 * qi;
            #pragma unroll
            for (int td = 0; td < 8; td++) {
                int dd = 8 * td + g;
                __nv_bfloat162 w;
                uint32_t bvh[2], bvl[2];
                w.x = sVh[(jr)     * LQ + dd]; w.y = sVh[(jr + 1) * LQ + dd]; bvh[0] = bf2u(w);
                w.x = sVh[(jr + 8) * LQ + dd]; w.y = sVh[(jr + 9) * LQ + dd]; bvh[1] = bf2u(w);
                w.x = sVl[(jr)     * LQ + dd]; w.y = sVl[(jr + 1) * LQ + dd]; bvl[0] = bf2u(w);
                w.x = sVl[(jr + 8) * LQ + dd]; w.y = sVl[(jr + 9) * LQ + dd]; bvl[1] = bf2u(w);
                mma16816(o[td], pah, bvh);
                mma16816(o[td], pah, bvl);
                mma16816(o[td], pal, bvh);
            }
        }
    }

    // ---- epilogue: normalize, split hi/lo, store [b,s,h,hd] ----
    float iv_g = 1.f / l_g, iv_g8 = 1.f / l_g8;
    size_t ob  = ((size_t)(b * S_ + q0 + wr + g)     * H_ + h) * HD_;
    size_t ob8 = ((size_t)(b * S_ + q0 + wr + g + 8) * H_ + h) * HD_;
    #pragma unroll
    for (int td = 0; td < 8; td++) {
        int d = 8 * td + 2 * qi;
        float v0 = o[td][0] * iv_g,  v1 = o[td][1] * iv_g;
        float v2 = o[td][2] * iv_g8, v3 = o[td][3] * iv_g8;
        __nv_bfloat162 hh = __floats2bfloat162_rn(v0, v1);
        *(uint32_t*)&Oh_[ob + d] = bf2u(hh);
        *(uint32_t*)&Ol_[ob + d] = bf2u(__floats2bfloat162_rn(
            v0 - __bfloat162float(hh.x), v1 - __bfloat162float(hh.y)));
        hh = __floats2bfloat162_rn(v2, v3);
        *(uint32_t*)&Oh_[ob8 + d] = bf2u(hh);
        *(uint32_t*)&Ol_[ob8 + d] = bf2u(__floats2bfloat162_rn(
            v2 - __bfloat162float(hh.x), v3 - __bfloat162float(hh.y)));
    }
}

// ---------------- launcher ----------------
extern "C" void kernel_launch(void* const* d_in, const int* in_sizes, int n_in,
                              void* d_out, int out_size)
{
    const float* x        = (const float*)d_in[0];
    const float* w_qkv    = (const float*)d_in[1];
    const float* b_qkv    = (const float*)d_in[2];
    const float* w_out    = (const float*)d_in[3];
    const float* b_out    = (const float*)d_in[4];
    const float* ln_scale = (const float*)d_in[5];
    const float* ln_bias  = (const float*)d_in[6];
    const float* q_scale  = (const float*)d_in[7];
    const float* k_scale  = (const float*)d_in[8];
    float* out = (float*)d_out;

    __nv_bfloat16 *xnh, *xnl, *wqh, *wql, *woh, *wol, *ath, *atl;
    __nv_bfloat16 *qh, *ql, *kh, *kl, *vh, *vl;
    float *qkv;
    cudaGetSymbolAddress((void**)&xnh, g_xnh);
    cudaGetSymbolAddress((void**)&xnl, g_xnl);
    cudaGetSymbolAddress((void**)&wqh, g_wqT_h);
    cudaGetSymbolAddress((void**)&wql, g_wqT_l);
    cudaGetSymbolAddress((void**)&woh, g_woT_h);
    cudaGetSymbolAddress((void**)&wol, g_woT_l);
    cudaGetSymbolAddress((void**)&qkv, g_qkv);
    cudaGetSymbolAddress((void**)&qh,  g_qh);
    cudaGetSymbolAddress((void**)&ql,  g_ql);
    cudaGetSymbolAddress((void**)&kh,  g_kh);
    cudaGetSymbolAddress((void**)&kl,  g_kl);
    cudaGetSymbolAddress((void**)&vh,  g_vh);
    cudaGetSymbolAddress((void**)&vl,  g_vl);
    cudaGetSymbolAddress((void**)&ath, g_attnh);
    cudaGetSymbolAddress((void**)&atl, g_attnl);

    // 1. input layernorm -> bf16 hi/lo
    ln_kernel<<<ROWS, 256>>>(x, ln_scale, ln_bias, xnh, xnl);

    // 2. weight transpose+split
    convT_kernel<<<dim3((3 * D_) / 32, D_ / 32), dim3(32, 8)>>>(w_qkv, wqh, wql, D_, 3 * D_);
    convT_kernel<<<dim3(D_ / 32, D_ / 32), dim3(32, 8)>>>(w_out, woh, wol, D_, D_);

    // 3. QKV GEMM (WMMA bf16x3)
    gemm_wmma<<<dim3((3 * D_) / 128, ROWS / 128), 256>>>(
        xnh, xnl, wqh, wql, b_qkv, qkv, ROWS, 3 * D_, D_);

    // 4. split + per-head LN + RoPE -> bf16 hi/lo
    split_rope<<<dim3(ROWS, H_), 64>>>(qkv, q_scale, k_scale,
                                       qh, ql, kh, kl, vh, vl);

    // 5. flash attention on tensor cores
    const int fl_smem = (2 * 128 * LQ + 4 * 64 * LQ) * (int)sizeof(__nv_bfloat16);
    cudaFuncSetAttribute(flash_mma,
                         cudaFuncAttributeMaxDynamicSharedMemorySize, fl_smem);
    flash_mma<<<dim3(S_ / 128, B_ * H_), 256, fl_smem>>>(
        qh, ql, kh, kl, vh, vl, ath, atl);

    // 6. output GEMM (WMMA bf16x3)
    gemm_wmma<<<dim3(D_ / 128, ROWS / 128), 256>>>(
        ath, atl, woh, wol, b_out, out, ROWS, D_, D_);
}

// round 5
// speedup vs baseline: 4.4743x; 1.1971x over previous
#include <cuda_runtime.h>
#include <cuda_bf16.h>
#include <cstdint>
#include <math.h>

#define B_  2
#define S_  2048
#define D_  1024
#define H_  16
#define HD_ 64
#define EPS 1e-6f

#define ROWS (B_ * S_)          // 4096

// ---------------- scratch (device globals; no allocation) ----------------
__device__ __nv_bfloat16 g_xnh [ROWS * D_];
__device__ __nv_bfloat16 g_xnl [ROWS * D_];
__device__ __nv_bfloat16 g_wqT_h[3 * D_ * D_];   // [3072][1024] K-major
__device__ __nv_bfloat16 g_wqT_l[3 * D_ * D_];
__device__ __nv_bfloat16 g_woT_h[D_ * D_];       // [1024][1024] K-major
__device__ __nv_bfloat16 g_woT_l[D_ * D_];
__device__ float g_qkv [ROWS * 3 * D_];          // 48 MB
__device__ __nv_bfloat16 g_qh[B_ * H_ * S_ * HD_];
__device__ __nv_bfloat16 g_ql[B_ * H_ * S_ * HD_];
__device__ __nv_bfloat16 g_kh[B_ * H_ * S_ * HD_];
__device__ __nv_bfloat16 g_kl[B_ * H_ * S_ * HD_];
__device__ __nv_bfloat16 g_vh[B_ * H_ * S_ * HD_];
__device__ __nv_bfloat16 g_vl[B_ * H_ * S_ * HD_];
__device__ __nv_bfloat16 g_attnh[ROWS * D_];
__device__ __nv_bfloat16 g_attnl[ROWS * D_];

// ================= helpers =================
__device__ __forceinline__ uint32_t smem_to_u32(const void* p) {
    uint32_t a;
    asm("{ .reg .u64 t; cvta.to.shared.u64 t, %1; cvt.u32.u64 %0, t; }"
        : "=r"(a) : "l"(p));
    return a;
}
__device__ __forceinline__ void cp16(void* sp, const void* gp) {
    uint32_t s = smem_to_u32(sp);
    asm volatile("cp.async.cg.shared.global [%0], [%1], 16;" :: "r"(s), "l"(gp));
}
#define CP_COMMIT() asm volatile("cp.async.commit_group;" ::: "memory")
#define CP_WAIT1()  asm volatile("cp.async.wait_group 1;"  ::: "memory")
#define CP_WAIT0()  asm volatile("cp.async.wait_group 0;"  ::: "memory")

__device__ __forceinline__ void mma16816(float* c, const uint32_t* a, const uint32_t* b) {
    asm volatile(
        "mma.sync.aligned.m16n8k16.row.col.f32.bf16.bf16.f32 "
        "{%0,%1,%2,%3}, {%4,%5,%6,%7}, {%8,%9}, {%0,%1,%2,%3};"
        : "+f"(c[0]), "+f"(c[1]), "+f"(c[2]), "+f"(c[3])
        : "r"(a[0]), "r"(a[1]), "r"(a[2]), "r"(a[3]),
          "r"(b[0]), "r"(b[1]));
}
__device__ __forceinline__ uint32_t bf2u(__nv_bfloat162 v) { return *(uint32_t*)&v; }

// ---------------- block reduce (256 threads) ----------------
__device__ __forceinline__ float block_reduce_256(float v) {
    __shared__ float sh[8];
    #pragma unroll
    for (int o = 16; o; o >>= 1) v += __shfl_down_sync(0xffffffffu, v, o);
    if ((threadIdx.x & 31) == 0) sh[threadIdx.x >> 5] = v;
    __syncthreads();
    if (threadIdx.x == 0) {
        float t = 0.f;
        #pragma unroll
        for (int i = 0; i < 8; i++) t += sh[i];
        sh[0] = t;
    }
    __syncthreads();
    float r = sh[0];
    __syncthreads();
    return r;
}

// ---------------- kernel 1: input layernorm -> bf16 hi/lo ----------------
__global__ __launch_bounds__(256) void ln_kernel(
    const float* __restrict__ x, const float* __restrict__ scale,
    const float* __restrict__ bias,
    __nv_bfloat16* __restrict__ oh, __nv_bfloat16* __restrict__ ol)
{
    int row = blockIdx.x;
    const float4* xr = (const float4*)(x + (size_t)row * D_);
    float4 v = xr[threadIdx.x];

    float s = v.x + v.y + v.z + v.w;
    float tot = block_reduce_256(s);
    float mu = tot * (1.0f / D_);

    float dx = v.x - mu, dy = v.y - mu, dz = v.z - mu, dw = v.w - mu;
    float sq = dx*dx + dy*dy + dz*dz + dw*dw;
    float vtot = block_reduce_256(sq);
    float rstd = rsqrtf(vtot * (1.0f / D_) + EPS);

    float4 sc = ((const float4*)scale)[threadIdx.x];
    float4 bi = ((const float4*)bias)[threadIdx.x];
    float ov[4];
    ov[0] = dx * rstd * sc.x + bi.x;
    ov[1] = dy * rstd * sc.y + bi.y;
    ov[2] = dz * rstd * sc.z + bi.z;
    ov[3] = dw * rstd * sc.w + bi.w;

    size_t base = (size_t)row * D_ + threadIdx.x * 4;
    #pragma unroll
    for (int j = 0; j < 4; j += 2) {
        __nv_bfloat162 hp, lp;
        __nv_bfloat16 h0 = __float2bfloat16(ov[j]);
        __nv_bfloat16 h1 = __float2bfloat16(ov[j + 1]);
        hp.x = h0; hp.y = h1;
        lp.x = __float2bfloat16(ov[j]     - __bfloat162float(h0));
        lp.y = __float2bfloat16(ov[j + 1] - __bfloat162float(h1));
        *(__nv_bfloat162*)&oh[base + j] = hp;
        *(__nv_bfloat162*)&ol[base + j] = lp;
    }
}

// ---------------- weight transpose + bf16 split: W[K][N] -> T[N][K] ----------------
__global__ __launch_bounds__(256) void convT_kernel(
    const float* __restrict__ W,
    __nv_bfloat16* __restrict__ Th, __nv_bfloat16* __restrict__ Tl,
    int K, int N)
{
    __shared__ float t[32][33];
    int tx = threadIdx.x, ty = threadIdx.y;   // 32 x 8
    int nb = blockIdx.x * 32, kb = blockIdx.y * 32;
    #pragma unroll
    for (int i = 0; i < 4; i++)
        t[ty + 8 * i][tx] = W[(size_t)(kb + ty + 8 * i) * N + nb + tx];
    __syncthreads();
    #pragma unroll
    for (int i = 0; i < 4; i++) {
        int n = nb + ty + 8 * i, k = kb + tx;
        float v = t[tx][ty + 8 * i];
        __nv_bfloat16 h = __float2bfloat16(v);
        Th[(size_t)n * K + k] = h;
        Tl[(size_t)n * K + k] = __float2bfloat16(v - __bfloat162float(h));
    }
}

// ---------------- pipelined mma.sync bf16x3 GEMM ----------------
// C[M,N] = A[M,K] @ Bt[N,K]^T + bias. Block 128x128, 8 warps (4M x 2N),
// warp tile 32x64, K-slab 32, cp.async 2-stage double buffer, 2 CTAs/SM.
#define GLDA 40   // elements; 80B row stride -> conflict-free frag loads
#define GEMM_TILE (128 * GLDA)
#define GEMM_SMEM (2 * 4 * GEMM_TILE * (int)sizeof(__nv_bfloat16))   // 81920

__device__ __forceinline__ void gemm_issue_stage(
    __nv_bfloat16* sm,
    const __nv_bfloat16* __restrict__ Ah, const __nv_bfloat16* __restrict__ Al,
    const __nv_bfloat16* __restrict__ Bh, const __nv_bfloat16* __restrict__ Bl,
    int m0, int n0, int K, int kc, int tid)
{
    const __nv_bfloat16* srcs[4] = {Ah, Al, Bh, Bl};
    const int row0s[4] = {m0, m0, n0, n0};
    #pragma unroll
    for (int t = 0; t < 4; t++) {
        #pragma unroll
        for (int i = 0; i < 2; i++) {
            int u = tid + i * 256;
            int r = u >> 2, c = (u & 3) * 8;
            cp16(sm + t * GEMM_TILE + r * GLDA + c,
                 srcs[t] + (size_t)(row0s[t] + r) * K + kc + c);
        }
    }
}

__global__ __launch_bounds__(256, 2) void gemm_mma(
    const __nv_bfloat16* __restrict__ Ah, const __nv_bfloat16* __restrict__ Al,
    const __nv_bfloat16* __restrict__ Bh, const __nv_bfloat16* __restrict__ Bl,
    const float* __restrict__ bias, float* __restrict__ C, int M, int N, int K)
{
    extern __shared__ __nv_bfloat16 gsm[];
    int tid = threadIdx.x, lane = tid & 31, w = tid >> 5;
    int g = lane >> 2, qi = lane & 3;
    int wm = w >> 1, wn = w & 1;             // 4 x 2 warp grid
    int m0 = blockIdx.y * 128, n0 = blockIdx.x * 128;

    float acc[2][8][4];
    #pragma unroll
    for (int i = 0; i < 2; i++)
        #pragma unroll
        for (int j = 0; j < 8; j++)
            #pragma unroll
            for (int e = 0; e < 4; e++) acc[i][j][e] = 0.f;

    gemm_issue_stage(gsm, Ah, Al, Bh, Bl, m0, n0, K, 0, tid);
    CP_COMMIT();
    gemm_issue_stage(gsm + 4 * GEMM_TILE, Ah, Al, Bh, Bl, m0, n0, K, 32, tid);
    CP_COMMIT();
    CP_WAIT1();
    __syncthreads();

    for (int kc = 0; kc < K; kc += 32) {
        __nv_bfloat16* st = gsm + ((kc >> 5) & 1) * 4 * GEMM_TILE;
        const __nv_bfloat16* sAh = st;
        const __nv_bfloat16* sAl = st + GEMM_TILE;
        const __nv_bfloat16* sBh = st + 2 * GEMM_TILE;
        const __nv_bfloat16* sBl = st + 3 * GEMM_TILE;

        #pragma unroll
        for (int kk = 0; kk < 32; kk += 16) {
            uint32_t ah[2][4], al[2][4];
            #pragma unroll
            for (int i = 0; i < 2; i++) {
                int ar = (wm * 32 + i * 16 + g) * GLDA + kk + 2 * qi;
                ah[i][0] = *(const uint32_t*)&sAh[ar];
                ah[i][1] = *(const uint32_t*)&sAh[ar + 8 * GLDA];
                ah[i][2] = *(const uint32_t*)&sAh[ar + 8];
                ah[i][3] = *(const uint32_t*)&sAh[ar + 8 * GLDA + 8];
                al[i][0] = *(const uint32_t*)&sAl[ar];
                al[i][1] = *(const uint32_t*)&sAl[ar + 8 * GLDA];
                al[i][2] = *(const uint32_t*)&sAl[ar + 8];
                al[i][3] = *(const uint32_t*)&sAl[ar + 8 * GLDA + 8];
            }
            #pragma unroll
            for (int j = 0; j < 8; j++) {
                int br = (wn * 64 + j * 8 + g) * GLDA + kk + 2 * qi;
                uint32_t bh2[2], bl2[2];
                bh2[0] = *(const uint32_t*)&sBh[br];
                bh2[1] = *(const uint32_t*)&sBh[br + 8];
                bl2[0] = *(const uint32_t*)&sBl[br];
                bl2[1] = *(const uint32_t*)&sBl[br + 8];
                #pragma unroll
                for (int i = 0; i < 2; i++) {
                    mma16816(acc[i][j], ah[i], bh2);
                    mma16816(acc[i][j], ah[i], bl2);
                    mma16816(acc[i][j], al[i], bh2);
                }
            }
        }
        __syncthreads();   // all warps done reading this buffer
        if (kc + 64 < K) {
            gemm_issue_stage(gsm + ((kc >> 5) & 1) * 4 * GEMM_TILE,
                             Ah, Al, Bh, Bl, m0, n0, K, kc + 64, tid);
            CP_COMMIT();
            CP_WAIT1();
        } else {
            CP_WAIT0();
        }
        __syncthreads();
    }

    // epilogue: direct stores + bias
    #pragma unroll
    for (int i = 0; i < 2; i++) {
        int r0 = m0 + wm * 32 + i * 16 + g;
        #pragma unroll
        for (int j = 0; j < 8; j++) {
            int col = n0 + wn * 64 + j * 8 + 2 * qi;
            float b0 = __ldg(&bias[col]), b1 = __ldg(&bias[col + 1]);
            float2 v0 = make_float2(acc[i][j][0] + b0, acc[i][j][1] + b1);
            float2 v1 = make_float2(acc[i][j][2] + b0, acc[i][j][3] + b1);
            *(float2*)&C[(size_t)r0 * N + col]       = v0;
            *(float2*)&C[(size_t)(r0 + 8) * N + col] = v1;
        }
    }
}

// ---------------- kernel 3: split qkv + per-head LN + RoPE -> bf16 hi/lo ----------------
__global__ __launch_bounds__(64) void split_rope(
    const float* __restrict__ qkv, const float* __restrict__ q_scale,
    const float* __restrict__ k_scale,
    __nv_bfloat16* __restrict__ qh, __nv_bfloat16* __restrict__ ql,
    __nv_bfloat16* __restrict__ kh, __nv_bfloat16* __restrict__ kl,
    __nv_bfloat16* __restrict__ vh, __nv_bfloat16* __restrict__ vl)
{
    __shared__ float qn[HD_], kn[HD_];
    __shared__ float red[8];

    int row = blockIdx.x;
    int h   = blockIdx.y;
    int i   = threadIdx.x;
    int b   = row / S_;
    int s   = row - b * S_;

    const float* base = qkv + (size_t)row * (3 * D_) + h * HD_;
    float qv = base[i];
    float kv = base[D_ + i];
    float vv = base[2 * D_ + i];

    float qs = qv, qsq = qv * qv, ks = kv, ksq = kv * kv;
    #pragma unroll
    for (int o = 16; o; o >>= 1) {
        qs  += __shfl_down_sync(0xffffffffu, qs, o);
        qsq += __shfl_down_sync(0xffffffffu, qsq, o);
        ks  += __shfl_down_sync(0xffffffffu, ks, o);
        ksq += __shfl_down_sync(0xffffffffu, ksq, o);
    }
    if ((i & 31) == 0) {
        int w = i >> 5;
        red[w * 4 + 0] = qs; red[w * 4 + 1] = qsq;
        red[w * 4 + 2] = ks; red[w * 4 + 3] = ksq;
    }
    __syncthreads();
    qs = red[0] + red[4]; qsq = red[1] + red[5];
    ks = red[2] + red[6]; ksq = red[3] + red[7];

    float muq = qs * (1.0f / HD_);
    float vaq = qsq * (1.0f / HD_) - muq * muq;
    float rq  = rsqrtf(vaq + EPS);
    float muk = ks * (1.0f / HD_);
    float vak = ksq * (1.0f / HD_) - muk * muk;
    float rk  = rsqrtf(vak + EPS);

    qn[i] = (qv - muq) * rq * q_scale[i];
    kn[i] = (kv - muk) * rk * k_scale[i];
    __syncthreads();

    int j = i & 31;
    float inv = expf(-(float)(2 * j) * (1.0f / 64.0f) * 9.210340371976184f);
    float ang = (float)s * inv;
    float sn, cs;
    sincosf(ang, &sn, &cs);

    float qrot = (i < 32) ? -qn[i + 32] : qn[i - 32];
    float krot = (i < 32) ? -kn[i + 32] : kn[i - 32];

    float qf = (qn[i] * cs + qrot * sn) * 0.125f;   // fold 1/sqrt(64)
    float kf = kn[i] * cs + krot * sn;

    size_t oidx = (((size_t)(b * H_ + h)) * S_ + s) * HD_ + i;
    __nv_bfloat16 t;
    t = __float2bfloat16(qf); qh[oidx] = t; ql[oidx] = __float2bfloat16(qf - __bfloat162float(t));
    t = __float2bfloat16(kf); kh[oidx] = t; kl[oidx] = __float2bfloat16(kf - __bfloat162float(t));
    t = __float2bfloat16(vv); vh[oidx] = t; vl[oidx] = __float2bfloat16(vv - __bfloat162float(t));
}

// ---------------- flash attention on tensor cores (mma.sync bf16x3) ----------------
#define LQ 72

__global__ __launch_bounds__(256, 2) void flash_mma(
    const __nv_bfloat16* __restrict__ Qh_, const __nv_bfloat16* __restrict__ Ql_,
    const __nv_bfloat16* __restrict__ Kh_, const __nv_bfloat16* __restrict__ Kl_,
    const __nv_bfloat16* __restrict__ Vh_, const __nv_bfloat16* __restrict__ Vl_,
    __nv_bfloat16* __restrict__ Oh_, __nv_bfloat16* __restrict__ Ol_)
{
    extern __shared__ __nv_bfloat16 fsm[];
    __nv_bfloat16* sQh = fsm;                 // [128][LQ]
    __nv_bfloat16* sQl = sQh + 128 * LQ;
    __nv_bfloat16* sKh = sQl + 128 * LQ;      // [64][LQ]
    __nv_bfloat16* sKl = sKh + 64 * LQ;
    __nv_bfloat16* sVh = sKl + 64 * LQ;
    __nv_bfloat16* sVl = sVh + 64 * LQ;

    int tid = threadIdx.x, lane = tid & 31, wid = tid >> 5;
    int g = lane >> 2, qi = lane & 3;
    int bh = blockIdx.y;
    int b = bh >> 4, h = bh & 15;
    int q0 = blockIdx.x * 128;
    size_t hbase = (size_t)bh * S_ * HD_;
    const __nv_bfloat16* Qhp = Qh_ + hbase;
    const __nv_bfloat16* Qlp = Ql_ + hbase;
    const __nv_bfloat16* Khp = Kh_ + hbase;
    const __nv_bfloat16* Klp = Kl_ + hbase;
    const __nv_bfloat16* Vhp = Vh_ + hbase;
    const __nv_bfloat16* Vlp = Vl_ + hbase;

    #pragma unroll
    for (int i = 0; i < 4; i++) {
        int u = tid + i * 256;
        int r = u >> 3, c = (u & 7) * 8;
        *(uint4*)&sQh[r * LQ + c] = *(const uint4*)&Qhp[(size_t)(q0 + r) * HD_ + c];
        *(uint4*)&sQl[r * LQ + c] = *(const uint4*)&Qlp[(size_t)(q0 + r) * HD_ + c];
    }

    float o[8][4];
    #pragma unroll
    for (int t = 0; t < 8; t++)
        #pragma unroll
        for (int e = 0; e < 4; e++) o[t][e] = 0.f;
    float m_g = -1e30f, m_g8 = -1e30f, l_g = 0.f, l_g8 = 0.f;
    int wr = wid * 16;

    for (int kt = 0; kt < S_ / 64; kt++) {
        int j0 = kt * 64;
        __syncthreads();
        {
            int r = tid >> 2, c = (tid & 3) * 16;
            size_t go = (size_t)(j0 + r) * HD_ + c;
            int so = r * LQ + c;
            *(uint4*)&sKh[so]     = *(const uint4*)&Khp[go];
            *(uint4*)&sKh[so + 8] = *(const uint4*)&Khp[go + 8];
            *(uint4*)&sKl[so]     = *(const uint4*)&Klp[go];
            *(uint4*)&sKl[so + 8] = *(const uint4*)&Klp[go + 8];
            *(uint4*)&sVh[so]     = *(const uint4*)&Vhp[go];
            *(uint4*)&sVh[so + 8] = *(const uint4*)&Vhp[go + 8];
            *(uint4*)&sVl[so]     = *(const uint4*)&Vlp[go];
            *(uint4*)&sVl[so + 8] = *(const uint4*)&Vlp[go + 8];
        }
        __syncthreads();

        float s[8][4];
        #pragma unroll
        for (int t = 0; t < 8; t++)
            #pragma unroll
            for (int e = 0; e < 4; e++) s[t][e] = 0.f;

        #pragma unroll
        for (int u = 0; u < 4; u++) {
            int d0 = u * 16 + 2 * qi;
            uint32_t ah[4], al[4];
            ah[0] = *(const uint32_t*)&sQh[(wr + g)     * LQ + d0];
            ah[1] = *(const uint32_t*)&sQh[(wr + g + 8) * LQ + d0];
            ah[2] = *(const uint32_t*)&sQh[(wr + g)     * LQ + d0 + 8];
            ah[3] = *(const uint32_t*)&sQh[(wr + g + 8) * LQ + d0 + 8];
            al[0] = *(const uint32_t*)&sQl[(wr + g)     * LQ + d0];
            al[1] = *(const uint32_t*)&sQl[(wr + g + 8) * LQ + d0];
            al[2] = *(const uint32_t*)&sQl[(wr + g)     * LQ + d0 + 8];
            al[3] = *(const uint32_t*)&sQl[(wr + g + 8) * LQ + d0 + 8];
            #pragma unroll
            for (int t = 0; t < 8; t++) {
                int kr = (8 * t + g) * LQ + d0;
                uint32_t bh2[2], bl2[2];
                bh2[0] = *(const uint32_t*)&sKh[kr];
                bh2[1] = *(const uint32_t*)&sKh[kr + 8];
                bl2[0] = *(const uint32_t*)&sKl[kr];
                bl2[1] = *(const uint32_t*)&sKl[kr + 8];
                mma16816(s[t], ah, bh2);
                mma16816(s[t], ah, bl2);
                mma16816(s[t], al, bh2);
            }
        }

        float mt_g = -1e30f, mt_g8 = -1e30f;
        #pragma unroll
        for (int t = 0; t < 8; t++) {
            mt_g  = fmaxf(mt_g,  fmaxf(s[t][0], s[t][1]));
            mt_g8 = fmaxf(mt_g8, fmaxf(s[t][2], s[t][3]));
        }
        mt_g  = fmaxf(mt_g,  __shfl_xor_sync(0xffffffffu, mt_g, 1));
        mt_g  = fmaxf(mt_g,  __shfl_xor_sync(0xffffffffu, mt_g, 2));
        mt_g8 = fmaxf(mt_g8, __shfl_xor_sync(0xffffffffu, mt_g8, 1));
        mt_g8 = fmaxf(mt_g8, __shfl_xor_sync(0xffffffffu, mt_g8, 2));
        float mn_g = fmaxf(m_g, mt_g), mn_g8 = fmaxf(m_g8, mt_g8);
        float al_g = __expf(m_g - mn_g), al_g8 = __expf(m_g8 - mn_g8);
        m_g = mn_g; m_g8 = mn_g8;

        uint32_t ph01[8], ph23[8], pl01[8], pl23[8];
        float sum_g = 0.f, sum_g8 = 0.f;
        #pragma unroll
        for (int t = 0; t < 8; t++) {
            float p0 = __expf(s[t][0] - mn_g);
            float p1 = __expf(s[t][1] - mn_g);
            float p2 = __expf(s[t][2] - mn_g8);
            float p3 = __expf(s[t][3] - mn_g8);
            sum_g += p0 + p1; sum_g8 += p2 + p3;
            __nv_bfloat162 hh = __floats2bfloat162_rn(p0, p1);
            ph01[t] = bf2u(hh);
            pl01[t] = bf2u(__floats2bfloat162_rn(p0 - __bfloat162float(hh.x),
                                                 p1 - __bfloat162float(hh.y)));
            hh = __floats2bfloat162_rn(p2, p3);
            ph23[t] = bf2u(hh);
            pl23[t] = bf2u(__floats2bfloat162_rn(p2 - __bfloat162float(hh.x),
                                                 p3 - __bfloat162float(hh.y)));
        }
        sum_g  += __shfl_xor_sync(0xffffffffu, sum_g, 1);
        sum_g  += __shfl_xor_sync(0xffffffffu, sum_g, 2);
        sum_g8 += __shfl_xor_sync(0xffffffffu, sum_g8, 1);
        sum_g8 += __shfl_xor_sync(0xffffffffu, sum_g8, 2);
        l_g  = l_g  * al_g  + sum_g;
        l_g8 = l_g8 * al_g8 + sum_g8;

        #pragma unroll
        for (int t = 0; t < 8; t++) {
            o[t][0] *= al_g;  o[t][1] *= al_g;
            o[t][2] *= al_g8; o[t][3] *= al_g8;
        }

        #pragma unroll
        for (int u = 0; u < 4; u++) {
            uint32_t pah[4] = {ph01[2*u], ph23[2*u], ph01[2*u+1], ph23[2*u+1]};
            uint32_t pal[4] = {pl01[2*u], pl23[2*u], pl01[2*u+1], pl23[2*u+1]};
            int jr = u * 16 + 2 * qi;
            #pragma unroll
            for (int td = 0; td < 8; td++) {
                int dd = 8 * td + g;
                __nv_bfloat162 w;
                uint32_t bvh[2], bvl[2];
                w.x = sVh[(jr)     * LQ + dd]; w.y = sVh[(jr + 1) * LQ + dd]; bvh[0] = bf2u(w);
                w.x = sVh[(jr + 8) * LQ + dd]; w.y = sVh[(jr + 9) * LQ + dd]; bvh[1] = bf2u(w);
                w.x = sVl[(jr)     * LQ + dd]; w.y = sVl[(jr + 1) * LQ + dd]; bvl[0] = bf2u(w);
                w.x = sVl[(jr + 8) * LQ + dd]; w.y = sVl[(jr + 9) * LQ + dd]; bvl[1] = bf2u(w);
                mma16816(o[td], pah, bvh);
                mma16816(o[td], pah, bvl);
                mma16816(o[td], pal, bvh);
            }
        }
    }

    float iv_g = 1.f / l_g, iv_g8 = 1.f / l_g8;
    size_t ob  = ((size_t)(b * S_ + q0 + wr + g)     * H_ + h) * HD_;
    size_t ob8 = ((size_t)(b * S_ + q0 + wr + g + 8) * H_ + h) * HD_;
    #pragma unroll
    for (int td = 0; td < 8; td++) {
        int d = 8 * td + 2 * qi;
        float v0 = o[td][0] * iv_g,  v1 = o[td][1] * iv_g;
        float v2 = o[td][2] * iv_g8, v3 = o[td][3] * iv_g8;
        __nv_bfloat162 hh = __floats2bfloat162_rn(v0, v1);
        *(uint32_t*)&Oh_[ob + d] = bf2u(hh);
        *(uint32_t*)&Ol_[ob + d] = bf2u(__floats2bfloat162_rn(
            v0 - __bfloat162float(hh.x), v1 - __bfloat162float(hh.y)));
        hh = __floats2bfloat162_rn(v2, v3);
        *(uint32_t*)&Oh_[ob8 + d] = bf2u(hh);
        *(uint32_t*)&Ol_[ob8 + d] = bf2u(__floats2bfloat162_rn(
            v2 - __bfloat162float(hh.x), v3 - __bfloat162float(hh.y)));
    }
}

// ---------------- launcher ----------------
extern "C" void kernel_launch(void* const* d_in, const int* in_sizes, int n_in,
                              void* d_out, int out_size)
{
    const float* x        = (const float*)d_in[0];
    const float* w_qkv    = (const float*)d_in[1];
    const float* b_qkv    = (const float*)d_in[2];
    const float* w_out    = (const float*)d_in[3];
    const float* b_out    = (const float*)d_in[4];
    const float* ln_scale = (const float*)d_in[5];
    const float* ln_bias  = (const float*)d_in[6];
    const float* q_scale  = (const float*)d_in[7];
    const float* k_scale  = (const float*)d_in[8];
    float* out = (float*)d_out;

    __nv_bfloat16 *xnh, *xnl, *wqh, *wql, *woh, *wol, *ath, *atl;
    __nv_bfloat16 *qh, *ql, *kh, *kl, *vh, *vl;
    float *qkv;
    cudaGetSymbolAddress((void**)&xnh, g_xnh);
    cudaGetSymbolAddress((void**)&xnl, g_xnl);
    cudaGetSymbolAddress((void**)&wqh, g_wqT_h);
    cudaGetSymbolAddress((void**)&wql, g_wqT_l);
    cudaGetSymbolAddress((void**)&woh, g_woT_h);
    cudaGetSymbolAddress((void**)&wol, g_woT_l);
    cudaGetSymbolAddress((void**)&qkv, g_qkv);
    cudaGetSymbolAddress((void**)&qh,  g_qh);
    cudaGetSymbolAddress((void**)&ql,  g_ql);
    cudaGetSymbolAddress((void**)&kh,  g_kh);
    cudaGetSymbolAddress((void**)&kl,  g_kl);
    cudaGetSymbolAddress((void**)&vh,  g_vh);
    cudaGetSymbolAddress((void**)&vl,  g_vl);
    cudaGetSymbolAddress((void**)&ath, g_attnh);
    cudaGetSymbolAddress((void**)&atl, g_attnl);

    cudaFuncSetAttribute(gemm_mma,
        cudaFuncAttributeMaxDynamicSharedMemorySize, GEMM_SMEM);

    // 1. input layernorm -> bf16 hi/lo
    ln_kernel<<<ROWS, 256>>>(x, ln_scale, ln_bias, xnh, xnl);

    // 2. weight transpose+split
    convT_kernel<<<dim3((3 * D_) / 32, D_ / 32), dim3(32, 8)>>>(w_qkv, wqh, wql, D_, 3 * D_);
    convT_kernel<<<dim3(D_ / 32, D_ / 32), dim3(32, 8)>>>(w_out, woh, wol, D_, D_);

    // 3. QKV GEMM (pipelined mma.sync bf16x3)
    gemm_mma<<<dim3((3 * D_) / 128, ROWS / 128), 256, GEMM_SMEM>>>(
        xnh, xnl, wqh, wql, b_qkv, qkv, ROWS, 3 * D_, D_);

    // 4. split + per-head LN + RoPE -> bf16 hi/lo
    split_rope<<<dim3(ROWS, H_), 64>>>(qkv, q_scale, k_scale,
                                       qh, ql, kh, kl, vh, vl);

    // 5. flash attention on tensor cores
    const int fl_smem = (2 * 128 * LQ + 4 * 64 * LQ) * (int)sizeof(__nv_bfloat16);
    cudaFuncSetAttribute(flash_mma,
                         cudaFuncAttributeMaxDynamicSharedMemorySize, fl_smem);
    flash_mma<<<dim3(S_ / 128, B_ * H_), 256, fl_smem>>>(
        qh, ql, kh, kl, vh, vl, ath, atl);

    // 6. output GEMM (pipelined mma.sync bf16x3)
    gemm_mma<<<dim3(D_ / 128, ROWS / 128), 256, GEMM_SMEM>>>(
        ath, atl, woh, wol, b_out, out, ROWS, D_, D_);
}

// round 6
// speedup vs baseline: 4.8275x; 1.0789x over previous
#include <cuda_runtime.h>
#include <cuda_bf16.h>
#include <cstdint>
#include <math.h>

#define B_  2
#define S_  2048
#define D_  1024
#define H_  16
#define HD_ 64
#define EPS 1e-6f

#define ROWS (B_ * S_)          // 4096

// ---------------- scratch (device globals; no allocation) ----------------
__device__ __nv_bfloat16 g_xnh [ROWS * D_];
__device__ __nv_bfloat16 g_xnl [ROWS * D_];
__device__ __nv_bfloat16 g_wqT_h[3 * D_ * D_];   // [3072][1024] K-major
__device__ __nv_bfloat16 g_wqT_l[3 * D_ * D_];
__device__ __nv_bfloat16 g_woT_h[D_ * D_];       // [1024][1024] K-major
__device__ __nv_bfloat16 g_woT_l[D_ * D_];
__device__ float g_qkv [ROWS * 3 * D_];          // 48 MB
__device__ __nv_bfloat16 g_qh[B_ * H_ * S_ * HD_];
__device__ __nv_bfloat16 g_ql[B_ * H_ * S_ * HD_];
__device__ __nv_bfloat16 g_kh[B_ * H_ * S_ * HD_];
__device__ __nv_bfloat16 g_kl[B_ * H_ * S_ * HD_];
__device__ __nv_bfloat16 g_vh[B_ * H_ * S_ * HD_];
__device__ __nv_bfloat16 g_vl[B_ * H_ * S_ * HD_];
__device__ __nv_bfloat16 g_attnh[ROWS * D_];
__device__ __nv_bfloat16 g_attnl[ROWS * D_];

// ================= helpers =================
__device__ __forceinline__ uint32_t smem_to_u32(const void* p) {
    uint32_t a;
    asm("{ .reg .u64 t; cvta.to.shared.u64 t, %1; cvt.u32.u64 %0, t; }"
        : "=r"(a) : "l"(p));
    return a;
}
__device__ __forceinline__ void cp16(void* sp, const void* gp) {
    uint32_t s = smem_to_u32(sp);
    asm volatile("cp.async.cg.shared.global [%0], [%1], 16;" :: "r"(s), "l"(gp));
}
#define CP_COMMIT() asm volatile("cp.async.commit_group;" ::: "memory")
#define CP_WAIT1()  asm volatile("cp.async.wait_group 1;"  ::: "memory")
#define CP_WAIT0()  asm volatile("cp.async.wait_group 0;"  ::: "memory")

__device__ __forceinline__ void mma16816(float* c, const uint32_t* a, const uint32_t* b) {
    asm volatile(
        "mma.sync.aligned.m16n8k16.row.col.f32.bf16.bf16.f32 "
        "{%0,%1,%2,%3}, {%4,%5,%6,%7}, {%8,%9}, {%0,%1,%2,%3};"
        : "+f"(c[0]), "+f"(c[1]), "+f"(c[2]), "+f"(c[3])
        : "r"(a[0]), "r"(a[1]), "r"(a[2]), "r"(a[3]),
          "r"(b[0]), "r"(b[1]));
}
__device__ __forceinline__ void ldsm_x4(uint32_t* r, uint32_t saddr) {
    asm volatile("ldmatrix.sync.aligned.m8n8.x4.shared.b16 {%0,%1,%2,%3}, [%4];"
        : "=r"(r[0]), "=r"(r[1]), "=r"(r[2]), "=r"(r[3]) : "r"(saddr));
}
__device__ __forceinline__ void ldsm_x4_t(uint32_t* r, uint32_t saddr) {
    asm volatile("ldmatrix.sync.aligned.m8n8.x4.trans.shared.b16 {%0,%1,%2,%3}, [%4];"
        : "=r"(r[0]), "=r"(r[1]), "=r"(r[2]), "=r"(r[3]) : "r"(saddr));
}
__device__ __forceinline__ uint32_t bf2u(__nv_bfloat162 v) { return *(uint32_t*)&v; }

// ---------------- block reduce (256 threads) ----------------
__device__ __forceinline__ float block_reduce_256(float v) {
    __shared__ float sh[8];
    #pragma unroll
    for (int o = 16; o; o >>= 1) v += __shfl_down_sync(0xffffffffu, v, o);
    if ((threadIdx.x & 31) == 0) sh[threadIdx.x >> 5] = v;
    __syncthreads();
    if (threadIdx.x == 0) {
        float t = 0.f;
        #pragma unroll
        for (int i = 0; i < 8; i++) t += sh[i];
        sh[0] = t;
    }
    __syncthreads();
    float r = sh[0];
    __syncthreads();
    return r;
}

// ---------------- kernel 1: input layernorm -> bf16 hi/lo ----------------
__global__ __launch_bounds__(256) void ln_kernel(
    const float* __restrict__ x, const float* __restrict__ scale,
    const float* __restrict__ bias,
    __nv_bfloat16* __restrict__ oh, __nv_bfloat16* __restrict__ ol)
{
    int row = blockIdx.x;
    const float4* xr = (const float4*)(x + (size_t)row * D_);
    float4 v = xr[threadIdx.x];

    float s = v.x + v.y + v.z + v.w;
    float tot = block_reduce_256(s);
    float mu = tot * (1.0f / D_);

    float dx = v.x - mu, dy = v.y - mu, dz = v.z - mu, dw = v.w - mu;
    float sq = dx*dx + dy*dy + dz*dz + dw*dw;
    float vtot = block_reduce_256(sq);
    float rstd = rsqrtf(vtot * (1.0f / D_) + EPS);

    float4 sc = ((const float4*)scale)[threadIdx.x];
    float4 bi = ((const float4*)bias)[threadIdx.x];
    float ov[4];
    ov[0] = dx * rstd * sc.x + bi.x;
    ov[1] = dy * rstd * sc.y + bi.y;
    ov[2] = dz * rstd * sc.z + bi.z;
    ov[3] = dw * rstd * sc.w + bi.w;

    size_t base = (size_t)row * D_ + threadIdx.x * 4;
    #pragma unroll
    for (int j = 0; j < 4; j += 2) {
        __nv_bfloat162 hp, lp;
        __nv_bfloat16 h0 = __float2bfloat16(ov[j]);
        __nv_bfloat16 h1 = __float2bfloat16(ov[j + 1]);
        hp.x = h0; hp.y = h1;
        lp.x = __float2bfloat16(ov[j]     - __bfloat162float(h0));
        lp.y = __float2bfloat16(ov[j + 1] - __bfloat162float(h1));
        *(__nv_bfloat162*)&oh[base + j] = hp;
        *(__nv_bfloat162*)&ol[base + j] = lp;
    }
}

// ---------------- weight transpose + bf16 split: W[K][N] -> T[N][K] ----------------
__global__ __launch_bounds__(256) void convT_kernel(
    const float* __restrict__ W,
    __nv_bfloat16* __restrict__ Th, __nv_bfloat16* __restrict__ Tl,
    int K, int N)
{
    __shared__ float t[32][33];
    int tx = threadIdx.x, ty = threadIdx.y;   // 32 x 8
    int nb = blockIdx.x * 32, kb = blockIdx.y * 32;
    #pragma unroll
    for (int i = 0; i < 4; i++)
        t[ty + 8 * i][tx] = W[(size_t)(kb + ty + 8 * i) * N + nb + tx];
    __syncthreads();
    #pragma unroll
    for (int i = 0; i < 4; i++) {
        int n = nb + ty + 8 * i, k = kb + tx;
        float v = t[tx][ty + 8 * i];
        __nv_bfloat16 h = __float2bfloat16(v);
        Th[(size_t)n * K + k] = h;
        Tl[(size_t)n * K + k] = __float2bfloat16(v - __bfloat162float(h));
    }
}

// ---------------- pipelined mma.sync bf16x3 GEMM with ldmatrix ----------------
#define GLDA 40   // elements; 80B row stride -> conflict-free LDSM rows
#define GEMM_TILE (128 * GLDA)
#define GEMM_SMEM (2 * 4 * GEMM_TILE * (int)sizeof(__nv_bfloat16))   // 81920

__device__ __forceinline__ void gemm_issue_stage(
    __nv_bfloat16* sm,
    const __nv_bfloat16* __restrict__ Ah, const __nv_bfloat16* __restrict__ Al,
    const __nv_bfloat16* __restrict__ Bh, const __nv_bfloat16* __restrict__ Bl,
    int m0, int n0, int K, int kc, int tid)
{
    const __nv_bfloat16* srcs[4] = {Ah, Al, Bh, Bl};
    const int row0s[4] = {m0, m0, n0, n0};
    #pragma unroll
    for (int t = 0; t < 4; t++) {
        #pragma unroll
        for (int i = 0; i < 2; i++) {
            int u = tid + i * 256;
            int r = u >> 2, c = (u & 3) * 8;
            cp16(sm + t * GEMM_TILE + r * GLDA + c,
                 srcs[t] + (size_t)(row0s[t] + r) * K + kc + c);
        }
    }
}

__global__ __launch_bounds__(256, 2) void gemm_mma(
    const __nv_bfloat16* __restrict__ Ah, const __nv_bfloat16* __restrict__ Al,
    const __nv_bfloat16* __restrict__ Bh, const __nv_bfloat16* __restrict__ Bl,
    const float* __restrict__ bias, float* __restrict__ C, int M, int N, int K)
{
    extern __shared__ __nv_bfloat16 gsm[];
    int tid = threadIdx.x, lane = tid & 31, w = tid >> 5;
    int g = lane >> 2, qi = lane & 3;
    int wm = w >> 1, wn = w & 1;
    int m0 = blockIdx.y * 128, n0 = blockIdx.x * 128;

    uint32_t uG = smem_to_u32(gsm);
    // ldmatrix per-thread byte offsets (relative to each tile base)
    uint32_t offA[2], offB[4];
    #pragma unroll
    for (int i = 0; i < 2; i++)
        offA[i] = ((wm * 32 + i * 16 + (lane & 15)) * GLDA + (lane >> 4) * 8) * 2;
    #pragma unroll
    for (int jp = 0; jp < 4; jp++)
        offB[jp] = ((wn * 64 + jp * 16 + (lane >> 4) * 8 + (lane & 7)) * GLDA
                    + ((lane >> 3) & 1) * 8) * 2;

    float acc[2][8][4];
    #pragma unroll
    for (int i = 0; i < 2; i++)
        #pragma unroll
        for (int j = 0; j < 8; j++)
            #pragma unroll
            for (int e = 0; e < 4; e++) acc[i][j][e] = 0.f;

    gemm_issue_stage(gsm, Ah, Al, Bh, Bl, m0, n0, K, 0, tid);
    CP_COMMIT();
    gemm_issue_stage(gsm + 4 * GEMM_TILE, Ah, Al, Bh, Bl, m0, n0, K, 32, tid);
    CP_COMMIT();
    CP_WAIT1();
    __syncthreads();

    for (int kc = 0; kc < K; kc += 32) {
        uint32_t uS  = uG + (((kc >> 5) & 1) * 4 * GEMM_TILE) * 2;
        uint32_t uAh = uS;
        uint32_t uAl = uS + GEMM_TILE * 2;
        uint32_t uBh = uS + 2 * GEMM_TILE * 2;
        uint32_t uBl = uS + 3 * GEMM_TILE * 2;

        #pragma unroll
        for (int kk = 0; kk < 32; kk += 16) {
            uint32_t ah[2][4], al[2][4];
            #pragma unroll
            for (int i = 0; i < 2; i++) {
                ldsm_x4(ah[i], uAh + offA[i] + kk * 2);
                ldsm_x4(al[i], uAl + offA[i] + kk * 2);
            }
            #pragma unroll
            for (int jp = 0; jp < 4; jp++) {
                uint32_t bh4[4], bl4[4];
                ldsm_x4(bh4, uBh + offB[jp] + kk * 2);
                ldsm_x4(bl4, uBl + offB[jp] + kk * 2);
                #pragma unroll
                for (int jj = 0; jj < 2; jj++) {
                    int j = jp * 2 + jj;
                    #pragma unroll
                    for (int i = 0; i < 2; i++) {
                        mma16816(acc[i][j], ah[i], bh4 + 2 * jj);
                        mma16816(acc[i][j], ah[i], bl4 + 2 * jj);
                        mma16816(acc[i][j], al[i], bh4 + 2 * jj);
                    }
                }
            }
        }
        __syncthreads();
        if (kc + 64 < K) {
            gemm_issue_stage(gsm + ((kc >> 5) & 1) * 4 * GEMM_TILE,
                             Ah, Al, Bh, Bl, m0, n0, K, kc + 64, tid);
            CP_COMMIT();
            CP_WAIT1();
        } else {
            CP_WAIT0();
        }
        __syncthreads();
    }

    #pragma unroll
    for (int i = 0; i < 2; i++) {
        int r0 = m0 + wm * 32 + i * 16 + g;
        #pragma unroll
        for (int j = 0; j < 8; j++) {
            int col = n0 + wn * 64 + j * 8 + 2 * qi;
            float b0 = __ldg(&bias[col]), b1 = __ldg(&bias[col + 1]);
            float2 v0 = make_float2(acc[i][j][0] + b0, acc[i][j][1] + b1);
            float2 v1 = make_float2(acc[i][j][2] + b0, acc[i][j][3] + b1);
            *(float2*)&C[(size_t)r0 * N + col]       = v0;
            *(float2*)&C[(size_t)(r0 + 8) * N + col] = v1;
        }
    }
}

// ---------------- kernel 3: split qkv + per-head LN + RoPE -> bf16 hi/lo ----------------
__global__ __launch_bounds__(64) void split_rope(
    const float* __restrict__ qkv, const float* __restrict__ q_scale,
    const float* __restrict__ k_scale,
    __nv_bfloat16* __restrict__ qh, __nv_bfloat16* __restrict__ ql,
    __nv_bfloat16* __restrict__ kh, __nv_bfloat16* __restrict__ kl,
    __nv_bfloat16* __restrict__ vh, __nv_bfloat16* __restrict__ vl)
{
    __shared__ float qn[HD_], kn[HD_];
    __shared__ float red[8];

    int row = blockIdx.x;
    int h   = blockIdx.y;
    int i   = threadIdx.x;
    int b   = row / S_;
    int s   = row - b * S_;

    const float* base = qkv + (size_t)row * (3 * D_) + h * HD_;
    float qv = base[i];
    float kv = base[D_ + i];
    float vv = base[2 * D_ + i];

    float qs = qv, qsq = qv * qv, ks = kv, ksq = kv * kv;
    #pragma unroll
    for (int o = 16; o; o >>= 1) {
        qs  += __shfl_down_sync(0xffffffffu, qs, o);
        qsq += __shfl_down_sync(0xffffffffu, qsq, o);
        ks  += __shfl_down_sync(0xffffffffu, ks, o);
        ksq += __shfl_down_sync(0xffffffffu, ksq, o);
    }
    if ((i & 31) == 0) {
        int w = i >> 5;
        red[w * 4 + 0] = qs; red[w * 4 + 1] = qsq;
        red[w * 4 + 2] = ks; red[w * 4 + 3] = ksq;
    }
    __syncthreads();
    qs = red[0] + red[4]; qsq = red[1] + red[5];
    ks = red[2] + red[6]; ksq = red[3] + red[7];

    float muq = qs * (1.0f / HD_);
    float vaq = qsq * (1.0f / HD_) - muq * muq;
    float rq  = rsqrtf(vaq + EPS);
    float muk = ks * (1.0f / HD_);
    float vak = ksq * (1.0f / HD_) - muk * muk;
    float rk  = rsqrtf(vak + EPS);

    qn[i] = (qv - muq) * rq * q_scale[i];
    kn[i] = (kv - muk) * rk * k_scale[i];
    __syncthreads();

    int j = i & 31;
    float inv = expf(-(float)(2 * j) * (1.0f / 64.0f) * 9.210340371976184f);
    float ang = (float)s * inv;
    float sn, cs;
    sincosf(ang, &sn, &cs);

    float qrot = (i < 32) ? -qn[i + 32] : qn[i - 32];
    float krot = (i < 32) ? -kn[i + 32] : kn[i - 32];

    float qf = (qn[i] * cs + qrot * sn) * 0.125f;
    float kf = kn[i] * cs + krot * sn;

    size_t oidx = (((size_t)(b * H_ + h)) * S_ + s) * HD_ + i;
    __nv_bfloat16 t;
    t = __float2bfloat16(qf); qh[oidx] = t; ql[oidx] = __float2bfloat16(qf - __bfloat162float(t));
    t = __float2bfloat16(kf); kh[oidx] = t; kl[oidx] = __float2bfloat16(kf - __bfloat162float(t));
    t = __float2bfloat16(vv); vh[oidx] = t; vl[oidx] = __float2bfloat16(vv - __bfloat162float(t));
}

// ---------------- flash attention: ldmatrix + cp.async double buffer ----------------
#define LQ 72
#define KVT (64 * LQ)                      // one KV tile (elements)
#define FL_SMEM ((2 * 128 * LQ + 2 * 4 * KVT) * (int)sizeof(__nv_bfloat16))

__device__ __forceinline__ void flash_issue_kv(
    __nv_bfloat16* st,
    const __nv_bfloat16* __restrict__ Khp, const __nv_bfloat16* __restrict__ Klp,
    const __nv_bfloat16* __restrict__ Vhp, const __nv_bfloat16* __restrict__ Vlp,
    int j0, int tid)
{
    int r = tid >> 2, c = (tid & 3) * 16;
    size_t go = (size_t)(j0 + r) * HD_ + c;
    int so = r * LQ + c;
    cp16(st + so,               Khp + go);
    cp16(st + so + 8,           Khp + go + 8);
    cp16(st + KVT + so,         Klp + go);
    cp16(st + KVT + so + 8,     Klp + go + 8);
    cp16(st + 2 * KVT + so,     Vhp + go);
    cp16(st + 2 * KVT + so + 8, Vhp + go + 8);
    cp16(st + 3 * KVT + so,     Vlp + go);
    cp16(st + 3 * KVT + so + 8, Vlp + go + 8);
}

__global__ __launch_bounds__(256, 2) void flash_mma(
    const __nv_bfloat16* __restrict__ Qh_, const __nv_bfloat16* __restrict__ Ql_,
    const __nv_bfloat16* __restrict__ Kh_, const __nv_bfloat16* __restrict__ Kl_,
    const __nv_bfloat16* __restrict__ Vh_, const __nv_bfloat16* __restrict__ Vl_,
    __nv_bfloat16* __restrict__ Oh_, __nv_bfloat16* __restrict__ Ol_)
{
    extern __shared__ __nv_bfloat16 fsm[];
    __nv_bfloat16* sQh = fsm;                 // [128][LQ]
    __nv_bfloat16* sQl = sQh + 128 * LQ;
    __nv_bfloat16* sKV = sQl + 128 * LQ;      // 2 stages x {Kh,Kl,Vh,Vl}

    int tid = threadIdx.x, lane = tid & 31, wid = tid >> 5;
    int g = lane >> 2, qi = lane & 3;
    int bh = blockIdx.y;
    int b = bh >> 4, h = bh & 15;
    int q0 = blockIdx.x * 128;
    size_t hbase = (size_t)bh * S_ * HD_;
    const __nv_bfloat16* Qhp = Qh_ + hbase;
    const __nv_bfloat16* Qlp = Ql_ + hbase;
    const __nv_bfloat16* Khp = Kh_ + hbase;
    const __nv_bfloat16* Klp = Kl_ + hbase;
    const __nv_bfloat16* Vhp = Vh_ + hbase;
    const __nv_bfloat16* Vlp = Vl_ + hbase;

    int wr = wid * 16;
    uint32_t uQh = smem_to_u32(sQh), uQl = smem_to_u32(sQl);
    uint32_t uKV = smem_to_u32(sKV);

    // per-thread ldmatrix offsets (bytes)
    uint32_t offQ = ((wr + (lane & 15)) * LQ + (lane >> 4) * 8) * 2;
    uint32_t offK[4], offV[4];
    #pragma unroll
    for (int tp = 0; tp < 4; tp++)
        offK[tp] = ((tp * 16 + (lane >> 4) * 8 + (lane & 7)) * LQ
                    + ((lane >> 3) & 1) * 8) * 2;
    #pragma unroll
    for (int tdp = 0; tdp < 4; tdp++)
        offV[tdp] = ((((lane >> 3) & 1) * 8 + (lane & 7)) * LQ
                     + (2 * tdp + (lane >> 4)) * 8) * 2;

    // Q tiles (plain loads) + first KV stage via cp.async
    #pragma unroll
    for (int i = 0; i < 4; i++) {
        int u = tid + i * 256;
        int r = u >> 3, c = (u & 7) * 8;
        *(uint4*)&sQh[r * LQ + c] = *(const uint4*)&Qhp[(size_t)(q0 + r) * HD_ + c];
        *(uint4*)&sQl[r * LQ + c] = *(const uint4*)&Qlp[(size_t)(q0 + r) * HD_ + c];
    }
    flash_issue_kv(sKV, Khp, Klp, Vhp, Vlp, 0, tid);
    CP_COMMIT();

    float o[8][4];
    #pragma unroll
    for (int t = 0; t < 8; t++)
        #pragma unroll
        for (int e = 0; e < 4; e++) o[t][e] = 0.f;
    float m_g = -1e30f, m_g8 = -1e30f, l_g = 0.f, l_g8 = 0.f;

    const int NT = S_ / 64;
    for (int kt = 0; kt < NT; kt++) {
        if (kt + 1 < NT) {
            flash_issue_kv(sKV + ((kt + 1) & 1) * 4 * KVT,
                           Khp, Klp, Vhp, Vlp, (kt + 1) * 64, tid);
            CP_COMMIT();
            CP_WAIT1();
        } else {
            CP_WAIT0();
        }
        __syncthreads();

        uint32_t uS  = uKV + ((kt & 1) * 4 * KVT) * 2;
        uint32_t uKh = uS;
        uint32_t uKl = uS + KVT * 2;
        uint32_t uVh = uS + 2 * KVT * 2;
        uint32_t uVl = uS + 3 * KVT * 2;

        // ---- S = Q K^T ----
        float s[8][4];
        #pragma unroll
        for (int t = 0; t < 8; t++)
            #pragma unroll
            for (int e = 0; e < 4; e++) s[t][e] = 0.f;

        #pragma unroll
        for (int u = 0; u < 4; u++) {
            uint32_t ah[4], al[4];
            ldsm_x4(ah, uQh + offQ + u * 32);
            ldsm_x4(al, uQl + offQ + u * 32);
            #pragma unroll
            for (int tp = 0; tp < 4; tp++) {
                uint32_t bh4[4], bl4[4];
                ldsm_x4(bh4, uKh + offK[tp] + u * 32);
                ldsm_x4(bl4, uKl + offK[tp] + u * 32);
                mma16816(s[2 * tp],     ah, bh4);
                mma16816(s[2 * tp],     ah, bl4);
                mma16816(s[2 * tp],     al, bh4);
                mma16816(s[2 * tp + 1], ah, bh4 + 2);
                mma16816(s[2 * tp + 1], ah, bl4 + 2);
                mma16816(s[2 * tp + 1], al, bh4 + 2);
            }
        }

        // ---- online softmax ----
        float mt_g = -1e30f, mt_g8 = -1e30f;
        #pragma unroll
        for (int t = 0; t < 8; t++) {
            mt_g  = fmaxf(mt_g,  fmaxf(s[t][0], s[t][1]));
            mt_g8 = fmaxf(mt_g8, fmaxf(s[t][2], s[t][3]));
        }
        mt_g  = fmaxf(mt_g,  __shfl_xor_sync(0xffffffffu, mt_g, 1));
        mt_g  = fmaxf(mt_g,  __shfl_xor_sync(0xffffffffu, mt_g, 2));
        mt_g8 = fmaxf(mt_g8, __shfl_xor_sync(0xffffffffu, mt_g8, 1));
        mt_g8 = fmaxf(mt_g8, __shfl_xor_sync(0xffffffffu, mt_g8, 2));
        float mn_g = fmaxf(m_g, mt_g), mn_g8 = fmaxf(m_g8, mt_g8);
        float al_g = __expf(m_g - mn_g), al_g8 = __expf(m_g8 - mn_g8);
        m_g = mn_g; m_g8 = mn_g8;

        uint32_t ph01[8], ph23[8], pl01[8], pl23[8];
        float sum_g = 0.f, sum_g8 = 0.f;
        #pragma unroll
        for (int t = 0; t < 8; t++) {
            float p0 = __expf(s[t][0] - mn_g);
            float p1 = __expf(s[t][1] - mn_g);
            float p2 = __expf(s[t][2] - mn_g8);
            float p3 = __expf(s[t][3] - mn_g8);
            sum_g += p0 + p1; sum_g8 += p2 + p3;
            __nv_bfloat162 hh = __floats2bfloat162_rn(p0, p1);
            ph01[t] = bf2u(hh);
            pl01[t] = bf2u(__floats2bfloat162_rn(p0 - __bfloat162float(hh.x),
                                                 p1 - __bfloat162float(hh.y)));
            hh = __floats2bfloat162_rn(p2, p3);
            ph23[t] = bf2u(hh);
            pl23[t] = bf2u(__floats2bfloat162_rn(p2 - __bfloat162float(hh.x),
                                                 p3 - __bfloat162float(hh.y)));
        }
        sum_g  += __shfl_xor_sync(0xffffffffu, sum_g, 1);
        sum_g  += __shfl_xor_sync(0xffffffffu, sum_g, 2);
        sum_g8 += __shfl_xor_sync(0xffffffffu, sum_g8, 1);
        sum_g8 += __shfl_xor_sync(0xffffffffu, sum_g8, 2);
        l_g  = l_g  * al_g  + sum_g;
        l_g8 = l_g8 * al_g8 + sum_g8;

        #pragma unroll
        for (int t = 0; t < 8; t++) {
            o[t][0] *= al_g;  o[t][1] *= al_g;
            o[t][2] *= al_g8; o[t][3] *= al_g8;
        }

        // ---- O += P V (ldmatrix.trans fragments) ----
        #pragma unroll
        for (int u = 0; u < 4; u++) {
            uint32_t pah[4] = {ph01[2*u], ph23[2*u], ph01[2*u+1], ph23[2*u+1]};
            uint32_t pal[4] = {pl01[2*u], pl23[2*u], pl01[2*u+1], pl23[2*u+1]};
            uint32_t ubase = u * 16 * LQ * 2;
            #pragma unroll
            for (int tdp = 0; tdp < 4; tdp++) {
                uint32_t bvh4[4], bvl4[4];
                ldsm_x4_t(bvh4, uVh + offV[tdp] + ubase);
                ldsm_x4_t(bvl4, uVl + offV[tdp] + ubase);
                mma16816(o[2 * tdp],     pah, bvh4);
                mma16816(o[2 * tdp],     pah, bvl4);
                mma16816(o[2 * tdp],     pal, bvh4);
                mma16816(o[2 * tdp + 1], pah, bvh4 + 2);
                mma16816(o[2 * tdp + 1], pah, bvl4 + 2);
                mma16816(o[2 * tdp + 1], pal, bvh4 + 2);
            }
        }
        __syncthreads();
    }

    float iv_g = 1.f / l_g, iv_g8 = 1.f / l_g8;
    size_t ob  = ((size_t)(b * S_ + q0 + wr + g)     * H_ + h) * HD_;
    size_t ob8 = ((size_t)(b * S_ + q0 + wr + g + 8) * H_ + h) * HD_;
    #pragma unroll
    for (int td = 0; td < 8; td++) {
        int d = 8 * td + 2 * qi;
        float v0 = o[td][0] * iv_g,  v1 = o[td][1] * iv_g;
        float v2 = o[td][2] * iv_g8, v3 = o[td][3] * iv_g8;
        __nv_bfloat162 hh = __floats2bfloat162_rn(v0, v1);
        *(uint32_t*)&Oh_[ob + d] = bf2u(hh);
        *(uint32_t*)&Ol_[ob + d] = bf2u(__floats2bfloat162_rn(
            v0 - __bfloat162float(hh.x), v1 - __bfloat162float(hh.y)));
        hh = __floats2bfloat162_rn(v2, v3);
        *(uint32_t*)&Oh_[ob8 + d] = bf2u(hh);
        *(uint32_t*)&Ol_[ob8 + d] = bf2u(__floats2bfloat162_rn(
            v2 - __bfloat162float(hh.x), v3 - __bfloat162float(hh.y)));
    }
}

// ---------------- launcher ----------------
extern "C" void kernel_launch(void* const* d_in, const int* in_sizes, int n_in,
                              void* d_out, int out_size)
{
    const float* x        = (const float*)d_in[0];
    const float* w_qkv    = (const float*)d_in[1];
    const float* b_qkv    = (const float*)d_in[2];
    const float* w_out    = (const float*)d_in[3];
    const float* b_out    = (const float*)d_in[4];
    const float* ln_scale = (const float*)d_in[5];
    const float* ln_bias  = (const float*)d_in[6];
    const float* q_scale  = (const float*)d_in[7];
    const float* k_scale  = (const float*)d_in[8];
    float* out = (float*)d_out;

    __nv_bfloat16 *xnh, *xnl, *wqh, *wql, *woh, *wol, *ath, *atl;
    __nv_bfloat16 *qh, *ql, *kh, *kl, *vh, *vl;
    float *qkv;
    cudaGetSymbolAddress((void**)&xnh, g_xnh);
    cudaGetSymbolAddress((void**)&xnl, g_xnl);
    cudaGetSymbolAddress((void**)&wqh, g_wqT_h);
    cudaGetSymbolAddress((void**)&wql, g_wqT_l);
    cudaGetSymbolAddress((void**)&woh, g_woT_h);
    cudaGetSymbolAddress((void**)&wol, g_woT_l);
    cudaGetSymbolAddress((void**)&qkv, g_qkv);
    cudaGetSymbolAddress((void**)&qh,  g_qh);
    cudaGetSymbolAddress((void**)&ql,  g_ql);
    cudaGetSymbolAddress((void**)&kh,  g_kh);
    cudaGetSymbolAddress((void**)&kl,  g_kl);
    cudaGetSymbolAddress((void**)&vh,  g_vh);
    cudaGetSymbolAddress((void**)&vl,  g_vl);
    cudaGetSymbolAddress((void**)&ath, g_attnh);
    cudaGetSymbolAddress((void**)&atl, g_attnl);

    cudaFuncSetAttribute(gemm_mma,
        cudaFuncAttributeMaxDynamicSharedMemorySize, GEMM_SMEM);
    cudaFuncSetAttribute(flash_mma,
        cudaFuncAttributeMaxDynamicSharedMemorySize, FL_SMEM);

    // 1. input layernorm -> bf16 hi/lo
    ln_kernel<<<ROWS, 256>>>(x, ln_scale, ln_bias, xnh, xnl);

    // 2. weight transpose+split
    convT_kernel<<<dim3((3 * D_) / 32, D_ / 32), dim3(32, 8)>>>(w_qkv, wqh, wql, D_, 3 * D_);
    convT_kernel<<<dim3(D_ / 32, D_ / 32), dim3(32, 8)>>>(w_out, woh, wol, D_, D_);

    // 3. QKV GEMM
    gemm_mma<<<dim3((3 * D_) / 128, ROWS / 128), 256, GEMM_SMEM>>>(
        xnh, xnl, wqh, wql, b_qkv, qkv, ROWS, 3 * D_, D_);

    // 4. split + per-head LN + RoPE -> bf16 hi/lo
    split_rope<<<dim3(ROWS, H_), 64>>>(qkv, q_scale, k_scale,
                                       qh, ql, kh, kl, vh, vl);

    // 5. flash attention
    flash_mma<<<dim3(S_ / 128, B_ * H_), 256, FL_SMEM>>>(
        qh, ql, kh, kl, vh, vl, ath, atl);

    // 6. output GEMM
    gemm_mma<<<dim3(D_ / 128, ROWS / 128), 256, GEMM_SMEM>>>(
        ath, atl, woh, wol, b_out, out, ROWS, D_, D_);
}

// round 7
// speedup vs baseline: 5.4229x; 1.1233x over previous
#include <cuda_runtime.h>
#include <cuda_bf16.h>
#include <cstdint>
#include <math.h>

#define B_  2
#define S_  2048
#define D_  1024
#define H_  16
#define HD_ 64
#define EPS 1e-6f

#define ROWS (B_ * S_)          // 4096

// ---------------- scratch (device globals; no allocation) ----------------
__device__ __nv_bfloat16 g_xnh [ROWS * D_];
__device__ __nv_bfloat16 g_xnl [ROWS * D_];
__device__ __nv_bfloat16 g_wqT_h[3 * D_ * D_];   // [3072][1024] K-major
__device__ __nv_bfloat16 g_wqT_l[3 * D_ * D_];
__device__ __nv_bfloat16 g_woT_h[D_ * D_];       // [1024][1024] K-major
__device__ __nv_bfloat16 g_woT_l[D_ * D_];
__device__ float g_qkv [ROWS * 3 * D_];          // 48 MB
__device__ __nv_bfloat16 g_qh[B_ * H_ * S_ * HD_];
__device__ __nv_bfloat16 g_ql[B_ * H_ * S_ * HD_];
__device__ __nv_bfloat16 g_kh[B_ * H_ * S_ * HD_];
__device__ __nv_bfloat16 g_kl[B_ * H_ * S_ * HD_];
__device__ __nv_bfloat16 g_vh[B_ * H_ * S_ * HD_];
__device__ __nv_bfloat16 g_vl[B_ * H_ * S_ * HD_];
__device__ __nv_bfloat16 g_attnh[ROWS * D_];
__device__ __nv_bfloat16 g_attnl[ROWS * D_];

// ================= helpers =================
__device__ __forceinline__ uint32_t smem_to_u32(const void* p) {
    uint32_t a;
    asm("{ .reg .u64 t; cvta.to.shared.u64 t, %1; cvt.u32.u64 %0, t; }"
        : "=r"(a) : "l"(p));
    return a;
}
__device__ __forceinline__ void cp16(void* sp, const void* gp) {
    uint32_t s = smem_to_u32(sp);
    asm volatile("cp.async.cg.shared.global [%0], [%1], 16;" :: "r"(s), "l"(gp));
}
#define CP_COMMIT() asm volatile("cp.async.commit_group;" ::: "memory")
#define CP_WAIT1()  asm volatile("cp.async.wait_group 1;"  ::: "memory")
#define CP_WAIT0()  asm volatile("cp.async.wait_group 0;"  ::: "memory")

__device__ __forceinline__ void mma16816(float* c, const uint32_t* a, const uint32_t* b) {
    asm volatile(
        "mma.sync.aligned.m16n8k16.row.col.f32.bf16.bf16.f32 "
        "{%0,%1,%2,%3}, {%4,%5,%6,%7}, {%8,%9}, {%0,%1,%2,%3};"
        : "+f"(c[0]), "+f"(c[1]), "+f"(c[2]), "+f"(c[3])
        : "r"(a[0]), "r"(a[1]), "r"(a[2]), "r"(a[3]),
          "r"(b[0]), "r"(b[1]));
}
__device__ __forceinline__ void ldsm_x4(uint32_t* r, uint32_t saddr) {
    asm volatile("ldmatrix.sync.aligned.m8n8.x4.shared.b16 {%0,%1,%2,%3}, [%4];"
        : "=r"(r[0]), "=r"(r[1]), "=r"(r[2]), "=r"(r[3]) : "r"(saddr));
}
__device__ __forceinline__ void ldsm_x4_t(uint32_t* r, uint32_t saddr) {
    asm volatile("ldmatrix.sync.aligned.m8n8.x4.trans.shared.b16 {%0,%1,%2,%3}, [%4];"
        : "=r"(r[0]), "=r"(r[1]), "=r"(r[2]), "=r"(r[3]) : "r"(saddr));
}
__device__ __forceinline__ uint32_t bf2u(__nv_bfloat162 v) { return *(uint32_t*)&v; }

// 64B-row swizzle: XOR chunk bits [4:5] with row bits [7:8]
#define SW64(o) ((o) ^ (((o) >> 3) & 0x30))

// ---------------- block reduce (256 threads) ----------------
__device__ __forceinline__ float block_reduce_256(float v) {
    __shared__ float sh[8];
    #pragma unroll
    for (int o = 16; o; o >>= 1) v += __shfl_down_sync(0xffffffffu, v, o);
    if ((threadIdx.x & 31) == 0) sh[threadIdx.x >> 5] = v;
    __syncthreads();
    if (threadIdx.x == 0) {
        float t = 0.f;
        #pragma unroll
        for (int i = 0; i < 8; i++) t += sh[i];
        sh[0] = t;
    }
    __syncthreads();
    float r = sh[0];
    __syncthreads();
    return r;
}

// ---------------- kernel 1: input layernorm -> bf16 hi/lo ----------------
__global__ __launch_bounds__(256) void ln_kernel(
    const float* __restrict__ x, const float* __restrict__ scale,
    const float* __restrict__ bias,
    __nv_bfloat16* __restrict__ oh, __nv_bfloat16* __restrict__ ol)
{
    int row = blockIdx.x;
    const float4* xr = (const float4*)(x + (size_t)row * D_);
    float4 v = xr[threadIdx.x];

    float s = v.x + v.y + v.z + v.w;
    float tot = block_reduce_256(s);
    float mu = tot * (1.0f / D_);

    float dx = v.x - mu, dy = v.y - mu, dz = v.z - mu, dw = v.w - mu;
    float sq = dx*dx + dy*dy + dz*dz + dw*dw;
    float vtot = block_reduce_256(sq);
    float rstd = rsqrtf(vtot * (1.0f / D_) + EPS);

    float4 sc = ((const float4*)scale)[threadIdx.x];
    float4 bi = ((const float4*)bias)[threadIdx.x];
    float ov[4];
    ov[0] = dx * rstd * sc.x + bi.x;
    ov[1] = dy * rstd * sc.y + bi.y;
    ov[2] = dz * rstd * sc.z + bi.z;
    ov[3] = dw * rstd * sc.w + bi.w;

    size_t base = (size_t)row * D_ + threadIdx.x * 4;
    #pragma unroll
    for (int j = 0; j < 4; j += 2) {
        __nv_bfloat162 hp, lp;
        __nv_bfloat16 h0 = __float2bfloat16(ov[j]);
        __nv_bfloat16 h1 = __float2bfloat16(ov[j + 1]);
        hp.x = h0; hp.y = h1;
        lp.x = __float2bfloat16(ov[j]     - __bfloat162float(h0));
        lp.y = __float2bfloat16(ov[j + 1] - __bfloat162float(h1));
        *(__nv_bfloat162*)&oh[base + j] = hp;
        *(__nv_bfloat162*)&ol[base + j] = lp;
    }
}

// ---------------- weight transpose + bf16 split: W[K][N] -> T[N][K] ----------------
__global__ __launch_bounds__(256) void convT_kernel(
    const float* __restrict__ W,
    __nv_bfloat16* __restrict__ Th, __nv_bfloat16* __restrict__ Tl,
    int K, int N)
{
    __shared__ float t[32][33];
    int tx = threadIdx.x, ty = threadIdx.y;   // 32 x 8
    int nb = blockIdx.x * 32, kb = blockIdx.y * 32;
    #pragma unroll
    for (int i = 0; i < 4; i++)
        t[ty + 8 * i][tx] = W[(size_t)(kb + ty + 8 * i) * N + nb + tx];
    __syncthreads();
    #pragma unroll
    for (int i = 0; i < 4; i++) {
        int n = nb + ty + 8 * i, k = kb + tx;
        float v = t[tx][ty + 8 * i];
        __nv_bfloat16 h = __float2bfloat16(v);
        Th[(size_t)n * K + k] = h;
        Tl[(size_t)n * K + k] = __float2bfloat16(v - __bfloat162float(h));
    }
}

// ---------------- 3-stage pipelined mma.sync bf16x3 GEMM (swizzled smem) ----------------
#define GT_BYTES 8192                        // one 128x32 bf16 tile
#define GSTAGE   (4 * GT_BYTES)              // Ah,Al,Bh,Bl
#define GEMM_SMEM (3 * GSTAGE)               // 98304

__device__ __forceinline__ void gemm_issue_stage(
    char* st,
    const __nv_bfloat16* __restrict__ Ah, const __nv_bfloat16* __restrict__ Al,
    const __nv_bfloat16* __restrict__ Bh, const __nv_bfloat16* __restrict__ Bl,
    int m0, int n0, int K, int kc, int tid)
{
    const __nv_bfloat16* srcs[4] = {Ah, Al, Bh, Bl};
    const int row0s[4] = {m0, m0, n0, n0};
    #pragma unroll
    for (int t = 0; t < 4; t++) {
        #pragma unroll
        for (int i = 0; i < 2; i++) {
            int u = tid + i * 256;
            int r = u >> 2, c = u & 3;
            uint32_t off = (uint32_t)(r * 64 + c * 16);
            cp16(st + t * GT_BYTES + SW64(off),
                 srcs[t] + (size_t)(row0s[t] + r) * K + kc + c * 8);
        }
    }
}

__global__ __launch_bounds__(256, 2) void gemm_mma(
    const __nv_bfloat16* __restrict__ Ah, const __nv_bfloat16* __restrict__ Al,
    const __nv_bfloat16* __restrict__ Bh, const __nv_bfloat16* __restrict__ Bl,
    const float* __restrict__ bias, float* __restrict__ C, int M, int N, int K)
{
    extern __shared__ char gsm[];
    int tid = threadIdx.x, lane = tid & 31, w = tid >> 5;
    int g = lane >> 2, qi = lane & 3;
    int wm = w >> 1, wn = w & 1;
    int m0 = blockIdx.y * 128, n0 = blockIdx.x * 128;

    uint32_t uG = smem_to_u32(gsm);
    // logical (pre-swizzle) byte offsets within a tile
    uint32_t baseA[2], baseB[4];
    #pragma unroll
    for (int i = 0; i < 2; i++)
        baseA[i] = (uint32_t)((wm * 32 + i * 16 + (lane & 15)) * 64
                              + (lane >> 4) * 16);
    #pragma unroll
    for (int jp = 0; jp < 4; jp++)
        baseB[jp] = (uint32_t)((wn * 64 + jp * 16 + (lane >> 4) * 8 + (lane & 7)) * 64
                               + ((lane >> 3) & 1) * 16);

    float acc[2][8][4];
    #pragma unroll
    for (int i = 0; i < 2; i++)
        #pragma unroll
        for (int j = 0; j < 8; j++)
            #pragma unroll
            for (int e = 0; e < 4; e++) acc[i][j][e] = 0.f;

    gemm_issue_stage(gsm,          Ah, Al, Bh, Bl, m0, n0, K, 0,  tid);
    CP_COMMIT();
    gemm_issue_stage(gsm + GSTAGE, Ah, Al, Bh, Bl, m0, n0, K, 32, tid);
    CP_COMMIT();

    int st = 0;
    for (int kc = 0; kc < K; kc += 32) {
        if (kc + 32 < K) { CP_WAIT1(); } else { CP_WAIT0(); }
        __syncthreads();

        // prefetch slab kc+64 into stage (st+2)%3 (that buffer was consumed last iter)
        if (kc + 64 < K) {
            int nst = st + 2; if (nst >= 3) nst -= 3;
            gemm_issue_stage(gsm + nst * GSTAGE, Ah, Al, Bh, Bl, m0, n0, K, kc + 64, tid);
            CP_COMMIT();
        }

        uint32_t uS  = uG + (uint32_t)(st * GSTAGE);
        uint32_t uAh = uS;
        uint32_t uAl = uS + GT_BYTES;
        uint32_t uBh = uS + 2 * GT_BYTES;
        uint32_t uBl = uS + 3 * GT_BYTES;

        #pragma unroll
        for (int kk = 0; kk < 2; kk++) {
            uint32_t kb = kk * 32;   // kk*16 elems * 2B
            uint32_t ah[2][4], al[2][4];
            #pragma unroll
            for (int i = 0; i < 2; i++) {
                ldsm_x4(ah[i], uAh + SW64(baseA[i] + kb));
                ldsm_x4(al[i], uAl + SW64(baseA[i] + kb));
            }
            #pragma unroll
            for (int jp = 0; jp < 4; jp++) {
                uint32_t bh4[4], bl4[4];
                ldsm_x4(bh4, uBh + SW64(baseB[jp] + kb));
                ldsm_x4(bl4, uBl + SW64(baseB[jp] + kb));
                #pragma unroll
                for (int jj = 0; jj < 2; jj++) {
                    int j = jp * 2 + jj;
                    #pragma unroll
                    for (int i = 0; i < 2; i++) {
                        mma16816(acc[i][j], ah[i], bh4 + 2 * jj);
                        mma16816(acc[i][j], ah[i], bl4 + 2 * jj);
                        mma16816(acc[i][j], al[i], bh4 + 2 * jj);
                    }
                }
            }
        }
        st = st + 1; if (st >= 3) st = 0;
    }

    #pragma unroll
    for (int i = 0; i < 2; i++) {
        int r0 = m0 + wm * 32 + i * 16 + g;
        #pragma unroll
        for (int j = 0; j < 8; j++) {
            int col = n0 + wn * 64 + j * 8 + 2 * qi;
            float b0 = __ldg(&bias[col]), b1 = __ldg(&bias[col + 1]);
            float2 v0 = make_float2(acc[i][j][0] + b0, acc[i][j][1] + b1);
            float2 v1 = make_float2(acc[i][j][2] + b0, acc[i][j][3] + b1);
            *(float2*)&C[(size_t)r0 * N + col]       = v0;
            *(float2*)&C[(size_t)(r0 + 8) * N + col] = v1;
        }
    }
}

// ---------------- kernel 3: split qkv + per-head LN + RoPE (warp per row-head) ----------------
__global__ __launch_bounds__(256) void split_rope(
    const float* __restrict__ qkv, const float* __restrict__ q_scale,
    const float* __restrict__ k_scale,
    __nv_bfloat16* __restrict__ qh, __nv_bfloat16* __restrict__ ql,
    __nv_bfloat16* __restrict__ kh, __nv_bfloat16* __restrict__ kl,
    __nv_bfloat16* __restrict__ vh, __nv_bfloat16* __restrict__ vl)
{
    int lane = threadIdx.x & 31;
    int wl   = threadIdx.x >> 5;
    int pair = blockIdx.x * 8 + wl;     // row * H + h
    int row  = pair >> 4;
    int h    = pair & 15;
    int b    = row >> 11;               // / S_
    int s    = row & (S_ - 1);

    const float* base = qkv + (size_t)row * (3 * D_) + h * HD_;
    float q0 = base[lane],          q1 = base[lane + 32];
    float k0 = base[D_ + lane],     k1 = base[D_ + lane + 32];
    float v0 = base[2 * D_ + lane], v1 = base[2 * D_ + lane + 32];

    float qs = q0 + q1, qq = q0 * q0 + q1 * q1;
    float ks = k0 + k1, kq = k0 * k0 + k1 * k1;
    #pragma unroll
    for (int o = 16; o; o >>= 1) {
        qs += __shfl_xor_sync(0xffffffffu, qs, o);
        qq += __shfl_xor_sync(0xffffffffu, qq, o);
        ks += __shfl_xor_sync(0xffffffffu, ks, o);
        kq += __shfl_xor_sync(0xffffffffu, kq, o);
    }
    float muq = qs * (1.0f / HD_);
    float rq  = rsqrtf(qq * (1.0f / HD_) - muq * muq + EPS);
    float muk = ks * (1.0f / HD_);
    float rk  = rsqrtf(kq * (1.0f / HD_) - muk * muk + EPS);

    float qn0 = (q0 - muq) * rq * q_scale[lane];
    float qn1 = (q1 - muq) * rq * q_scale[lane + 32];
    float kn0 = (k0 - muk) * rk * k_scale[lane];
    float kn1 = (k1 - muk) * rk * k_scale[lane + 32];

    float inv = expf(-(float)(2 * lane) * (1.0f / 64.0f) * 9.210340371976184f);
    float sn, cs;
    sincosf((float)s * inv, &sn, &cs);

    float qf0 = (qn0 * cs - qn1 * sn) * 0.125f;   // fold 1/sqrt(64)
    float qf1 = (qn1 * cs + qn0 * sn) * 0.125f;
    float kf0 = kn0 * cs - kn1 * sn;
    float kf1 = kn1 * cs + kn0 * sn;

    size_t oidx = (((size_t)(b * H_ + h)) * S_ + s) * HD_ + lane;
    __nv_bfloat16 t;
    t = __float2bfloat16(qf0); qh[oidx]      = t; ql[oidx]      = __float2bfloat16(qf0 - __bfloat162float(t));
    t = __float2bfloat16(qf1); qh[oidx + 32] = t; ql[oidx + 32] = __float2bfloat16(qf1 - __bfloat162float(t));
    t = __float2bfloat16(kf0); kh[oidx]      = t; kl[oidx]      = __float2bfloat16(kf0 - __bfloat162float(t));
    t = __float2bfloat16(kf1); kh[oidx + 32] = t; kl[oidx + 32] = __float2bfloat16(kf1 - __bfloat162float(t));
    t = __float2bfloat16(v0);  vh[oidx]      = t; vl[oidx]      = __float2bfloat16(v0  - __bfloat162float(t));
    t = __float2bfloat16(v1);  vh[oidx + 32] = t; vl[oidx + 32] = __float2bfloat16(v1  - __bfloat162float(t));
}

// ---------------- flash attention: ldmatrix + cp.async double buffer ----------------
#define LQ 72
#define KVT (64 * LQ)                      // one KV tile (elements)
#define FL_SMEM ((2 * 128 * LQ + 2 * 4 * KVT) * (int)sizeof(__nv_bfloat16))

__device__ __forceinline__ void flash_issue_kv(
    __nv_bfloat16* st,
    const __nv_bfloat16* __restrict__ Khp, const __nv_bfloat16* __restrict__ Klp,
    const __nv_bfloat16* __restrict__ Vhp, const __nv_bfloat16* __restrict__ Vlp,
    int j0, int tid)
{
    int r = tid >> 2, c = (tid & 3) * 16;
    size_t go = (size_t)(j0 + r) * HD_ + c;
    int so = r * LQ + c;
    cp16(st + so,               Khp + go);
    cp16(st + so + 8,           Khp + go + 8);
    cp16(st + KVT + so,         Klp + go);
    cp16(st + KVT + so + 8,     Klp + go + 8);
    cp16(st + 2 * KVT + so,     Vhp + go);
    cp16(st + 2 * KVT + so + 8, Vhp + go + 8);
    cp16(st + 3 * KVT + so,     Vlp + go);
    cp16(st + 3 * KVT + so + 8, Vlp + go + 8);
}

__global__ __launch_bounds__(256, 2) void flash_mma(
    const __nv_bfloat16* __restrict__ Qh_, const __nv_bfloat16* __restrict__ Ql_,
    const __nv_bfloat16* __restrict__ Kh_, const __nv_bfloat16* __restrict__ Kl_,
    const __nv_bfloat16* __restrict__ Vh_, const __nv_bfloat16* __restrict__ Vl_,
    __nv_bfloat16* __restrict__ Oh_, __nv_bfloat16* __restrict__ Ol_)
{
    extern __shared__ __nv_bfloat16 fsm[];
    __nv_bfloat16* sQh = fsm;                 // [128][LQ]
    __nv_bfloat16* sQl = sQh + 128 * LQ;
    __nv_bfloat16* sKV = sQl + 128 * LQ;      // 2 stages x {Kh,Kl,Vh,Vl}

    int tid = threadIdx.x, lane = tid & 31, wid = tid >> 5;
    int g = lane >> 2, qi = lane & 3;
    int bh = blockIdx.y;
    int b = bh >> 4, h = bh & 15;
    int q0 = blockIdx.x * 128;
    size_t hbase = (size_t)bh * S_ * HD_;
    const __nv_bfloat16* Qhp = Qh_ + hbase;
    const __nv_bfloat16* Qlp = Ql_ + hbase;
    const __nv_bfloat16* Khp = Kh_ + hbase;
    const __nv_bfloat16* Klp = Kl_ + hbase;
    const __nv_bfloat16* Vhp = Vh_ + hbase;
    const __nv_bfloat16* Vlp = Vl_ + hbase;

    int wr = wid * 16;
    uint32_t uQh = smem_to_u32(sQh), uQl = smem_to_u32(sQl);
    uint32_t uKV = smem_to_u32(sKV);

    uint32_t offQ = ((wr + (lane & 15)) * LQ + (lane >> 4) * 8) * 2;
    uint32_t offK[4], offV[4];
    #pragma unroll
    for (int tp = 0; tp < 4; tp++)
        offK[tp] = ((tp * 16 + (lane >> 4) * 8 + (lane & 7)) * LQ
                    + ((lane >> 3) & 1) * 8) * 2;
    #pragma unroll
    for (int tdp = 0; tdp < 4; tdp++)
        offV[tdp] = ((((lane >> 3) & 1) * 8 + (lane & 7)) * LQ
                     + (2 * tdp + (lane >> 4)) * 8) * 2;

    #pragma unroll
    for (int i = 0; i < 4; i++) {
        int u = tid + i * 256;
        int r = u >> 3, c = (u & 7) * 8;
        *(uint4*)&sQh[r * LQ + c] = *(const uint4*)&Qhp[(size_t)(q0 + r) * HD_ + c];
        *(uint4*)&sQl[r * LQ + c] = *(const uint4*)&Qlp[(size_t)(q0 + r) * HD_ + c];
    }
    flash_issue_kv(sKV, Khp, Klp, Vhp, Vlp, 0, tid);
    CP_COMMIT();

    float o[8][4];
    #pragma unroll
    for (int t = 0; t < 8; t++)
        #pragma unroll
        for (int e = 0; e < 4; e++) o[t][e] = 0.f;
    float m_g = -1e30f, m_g8 = -1e30f, l_g = 0.f, l_g8 = 0.f;

    const int NT = S_ / 64;
    for (int kt = 0; kt < NT; kt++) {
        if (kt + 1 < NT) {
            flash_issue_kv(sKV + ((kt + 1) & 1) * 4 * KVT,
                           Khp, Klp, Vhp, Vlp, (kt + 1) * 64, tid);
            CP_COMMIT();
            CP_WAIT1();
        } else {
            CP_WAIT0();
        }
        __syncthreads();

        uint32_t uS  = uKV + ((kt & 1) * 4 * KVT) * 2;
        uint32_t uKh = uS;
        uint32_t uKl = uS + KVT * 2;
        uint32_t uVh = uS + 2 * KVT * 2;
        uint32_t uVl = uS + 3 * KVT * 2;

        float s[8][4];
        #pragma unroll
        for (int t = 0; t < 8; t++)
            #pragma unroll
            for (int e = 0; e < 4; e++) s[t][e] = 0.f;

        #pragma unroll
        for (int u = 0; u < 4; u++) {
            uint32_t ah[4], al[4];
            ldsm_x4(ah, uQh + offQ + u * 32);
            ldsm_x4(al, uQl + offQ + u * 32);
            #pragma unroll
            for (int tp = 0; tp < 4; tp++) {
                uint32_t bh4[4], bl4[4];
                ldsm_x4(bh4, uKh + offK[tp] + u * 32);
                ldsm_x4(bl4, uKl + offK[tp] + u * 32);
                mma16816(s[2 * tp],     ah, bh4);
                mma16816(s[2 * tp],     ah, bl4);
                mma16816(s[2 * tp],     al, bh4);
                mma16816(s[2 * tp + 1], ah, bh4 + 2);
                mma16816(s[2 * tp + 1], ah, bl4 + 2);
                mma16816(s[2 * tp + 1], al, bh4 + 2);
            }
        }

        float mt_g = -1e30f, mt_g8 = -1e30f;
        #pragma unroll
        for (int t = 0; t < 8; t++) {
            mt_g  = fmaxf(mt_g,  fmaxf(s[t][0], s[t][1]));
            mt_g8 = fmaxf(mt_g8, fmaxf(s[t][2], s[t][3]));
        }
        mt_g  = fmaxf(mt_g,  __shfl_xor_sync(0xffffffffu, mt_g, 1));
        mt_g  = fmaxf(mt_g,  __shfl_xor_sync(0xffffffffu, mt_g, 2));
        mt_g8 = fmaxf(mt_g8, __shfl_xor_sync(0xffffffffu, mt_g8, 1));
        mt_g8 = fmaxf(mt_g8, __shfl_xor_sync(0xffffffffu, mt_g8, 2));
        float mn_g = fmaxf(m_g, mt_g), mn_g8 = fmaxf(m_g8, mt_g8);
        float al_g = __expf(m_g - mn_g), al_g8 = __expf(m_g8 - mn_g8);
        m_g = mn_g; m_g8 = mn_g8;

        uint32_t ph01[8], ph23[8], pl01[8], pl23[8];
        float sum_g = 0.f, sum_g8 = 0.f;
        #pragma unroll
        for (int t = 0; t < 8; t++) {
            float p0 = __expf(s[t][0] - mn_g);
            float p1 = __expf(s[t][1] - mn_g);
            float p2 = __expf(s[t][2] - mn_g8);
            float p3 = __expf(s[t][3] - mn_g8);
            sum_g += p0 + p1; sum_g8 += p2 + p3;
            __nv_bfloat162 hh = __floats2bfloat162_rn(p0, p1);
            ph01[t] = bf2u(hh);
            pl01[t] = bf2u(__floats2bfloat162_rn(p0 - __bfloat162float(hh.x),
                                                 p1 - __bfloat162float(hh.y)));
            hh = __floats2bfloat162_rn(p2, p3);
            ph23[t] = bf2u(hh);
            pl23[t] = bf2u(__floats2bfloat162_rn(p2 - __bfloat162float(hh.x),
                                                 p3 - __bfloat162float(hh.y)));
        }
        sum_g  += __shfl_xor_sync(0xffffffffu, sum_g, 1);
        sum_g  += __shfl_xor_sync(0xffffffffu, sum_g, 2);
        sum_g8 += __shfl_xor_sync(0xffffffffu, sum_g8, 1);
        sum_g8 += __shfl_xor_sync(0xffffffffu, sum_g8, 2);
        l_g  = l_g  * al_g  + sum_g;
        l_g8 = l_g8 * al_g8 + sum_g8;

        #pragma unroll
        for (int t = 0; t < 8; t++) {
            o[t][0] *= al_g;  o[t][1] *= al_g;
            o[t][2] *= al_g8; o[t][3] *= al_g8;
        }

        #pragma unroll
        for (int u = 0; u < 4; u++) {
            uint32_t pah[4] = {ph01[2*u], ph23[2*u], ph01[2*u+1], ph23[2*u+1]};
            uint32_t pal[4] = {pl01[2*u], pl23[2*u], pl01[2*u+1], pl23[2*u+1]};
            uint32_t ubase = u * 16 * LQ * 2;
            #pragma unroll
            for (int tdp = 0; tdp < 4; tdp++) {
                uint32_t bvh4[4], bvl4[4];
                ldsm_x4_t(bvh4, uVh + offV[tdp] + ubase);
                ldsm_x4_t(bvl4, uVl + offV[tdp] + ubase);
                mma16816(o[2 * tdp],     pah, bvh4);
                mma16816(o[2 * tdp],     pah, bvl4);
                mma16816(o[2 * tdp],     pal, bvh4);
                mma16816(o[2 * tdp + 1], pah, bvh4 + 2);
                mma16816(o[2 * tdp + 1], pah, bvl4 + 2);
                mma16816(o[2 * tdp + 1], pal, bvh4 + 2);
            }
        }
        __syncthreads();
    }

    float iv_g = 1.f / l_g, iv_g8 = 1.f / l_g8;
    size_t ob  = ((size_t)(b * S_ + q0 + wr + g)     * H_ + h) * HD_;
    size_t ob8 = ((size_t)(b * S_ + q0 + wr + g + 8) * H_ + h) * HD_;
    #pragma unroll
    for (int td = 0; td < 8; td++) {
        int d = 8 * td + 2 * qi;
        float v0 = o[td][0] * iv_g,  v1 = o[td][1] * iv_g;
        float v2 = o[td][2] * iv_g8, v3 = o[td][3] * iv_g8;
        __nv_bfloat162 hh = __floats2bfloat162_rn(v0, v1);
        *(uint32_t*)&Oh_[ob + d] = bf2u(hh);
        *(uint32_t*)&Ol_[ob + d] = bf2u(__floats2bfloat162_rn(
            v0 - __bfloat162float(hh.x), v1 - __bfloat162float(hh.y)));
        hh = __floats2bfloat162_rn(v2, v3);
        *(uint32_t*)&Oh_[ob8 + d] = bf2u(hh);
        *(uint32_t*)&Ol_[ob8 + d] = bf2u(__floats2bfloat162_rn(
            v2 - __bfloat162float(hh.x), v3 - __bfloat162float(hh.y)));
    }
}

// ---------------- launcher ----------------
extern "C" void kernel_launch(void* const* d_in, const int* in_sizes, int n_in,
                              void* d_out, int out_size)
{
    const float* x        = (const float*)d_in[0];
    const float* w_qkv    = (const float*)d_in[1];
    const float* b_qkv    = (const float*)d_in[2];
    const float* w_out    = (const float*)d_in[3];
    const float* b_out    = (const float*)d_in[4];
    const float* ln_scale = (const float*)d_in[5];
    const float* ln_bias  = (const float*)d_in[6];
    const float* q_scale  = (const float*)d_in[7];
    const float* k_scale  = (const float*)d_in[8];
    float* out = (float*)d_out;

    __nv_bfloat16 *xnh, *xnl, *wqh, *wql, *woh, *wol, *ath, *atl;
    __nv_bfloat16 *qh, *ql, *kh, *kl, *vh, *vl;
    float *qkv;
    cudaGetSymbolAddress((void**)&xnh, g_xnh);
    cudaGetSymbolAddress((void**)&xnl, g_xnl);
    cudaGetSymbolAddress((void**)&wqh, g_wqT_h);
    cudaGetSymbolAddress((void**)&wql, g_wqT_l);
    cudaGetSymbolAddress((void**)&woh, g_woT_h);
    cudaGetSymbolAddress((void**)&wol, g_woT_l);
    cudaGetSymbolAddress((void**)&qkv, g_qkv);
    cudaGetSymbolAddress((void**)&qh,  g_qh);
    cudaGetSymbolAddress((void**)&ql,  g_ql);
    cudaGetSymbolAddress((void**)&kh,  g_kh);
    cudaGetSymbolAddress((void**)&kl,  g_kl);
    cudaGetSymbolAddress((void**)&vh,  g_vh);
    cudaGetSymbolAddress((void**)&vl,  g_vl);
    cudaGetSymbolAddress((void**)&ath, g_attnh);
    cudaGetSymbolAddress((void**)&atl, g_attnl);

    cudaFuncSetAttribute(gemm_mma,
        cudaFuncAttributeMaxDynamicSharedMemorySize, GEMM_SMEM);
    cudaFuncSetAttribute(flash_mma,
        cudaFuncAttributeMaxDynamicSharedMemorySize, FL_SMEM);

    // 1. input layernorm -> bf16 hi/lo
    ln_kernel<<<ROWS, 256>>>(x, ln_scale, ln_bias, xnh, xnl);

    // 2. weight transpose+split
    convT_kernel<<<dim3((3 * D_) / 32, D_ / 32), dim3(32, 8)>>>(w_qkv, wqh, wql, D_, 3 * D_);
    convT_kernel<<<dim3(D_ / 32, D_ / 32), dim3(32, 8)>>>(w_out, woh, wol, D_, D_);

    // 3. QKV GEMM
    gemm_mma<<<dim3((3 * D_) / 128, ROWS / 128), 256, GEMM_SMEM>>>(
        xnh, xnl, wqh, wql, b_qkv, qkv, ROWS, 3 * D_, D_);

    // 4. split + per-head LN + RoPE -> bf16 hi/lo
    split_rope<<<ROWS * H_ / 8, 256>>>(qkv, q_scale, k_scale,
                                       qh, ql, kh, kl, vh, vl);

    // 5. flash attention
    flash_mma<<<dim3(S_ / 128, B_ * H_), 256, FL_SMEM>>>(
        qh, ql, kh, kl, vh, vl, ath, atl);

    // 6. output GEMM
    gemm_mma<<<dim3(D_ / 128, ROWS / 128), 256, GEMM_SMEM>>>(
        ath, atl, woh, wol, b_out, out, ROWS, D_, D_);
}

// round 8
// speedup vs baseline: 7.7470x; 1.4286x over previous
#include <cuda_runtime.h>
#include <cuda_fp16.h>
#include <cstdint>
#include <math.h>

#define B_  2
#define S_  2048
#define D_  1024
#define H_  16
#define HD_ 64
#define EPS 1e-6f

#define ROWS (B_ * S_)          // 4096

// ---------------- scratch (device globals; no allocation) ----------------
__device__ __half g_xnh [ROWS * D_];
__device__ __half g_xnl [ROWS * D_];
__device__ __half g_wqT [3 * D_ * D_];   // [3072][1024] K-major, single fp16
__device__ __half g_woT [D_ * D_];       // [1024][1024] K-major
__device__ float  g_qkv [ROWS * 3 * D_];
__device__ __half g_qh[B_ * H_ * S_ * HD_];
__device__ __half g_ql[B_ * H_ * S_ * HD_];
__device__ __half g_kf[B_ * H_ * S_ * HD_];
__device__ __half g_vf[B_ * H_ * S_ * HD_];
__device__ __half g_attnh[ROWS * D_];
__device__ __half g_attnl[ROWS * D_];

// ================= helpers =================
__device__ __forceinline__ uint32_t smem_to_u32(const void* p) {
    uint32_t a;
    asm("{ .reg .u64 t; cvta.to.shared.u64 t, %1; cvt.u32.u64 %0, t; }"
        : "=r"(a) : "l"(p));
    return a;
}
__device__ __forceinline__ void cp16(void* sp, const void* gp) {
    uint32_t s = smem_to_u32(sp);
    asm volatile("cp.async.cg.shared.global [%0], [%1], 16;" :: "r"(s), "l"(gp));
}
#define CP_COMMIT() asm volatile("cp.async.commit_group;" ::: "memory")
#define CP_WAIT1()  asm volatile("cp.async.wait_group 1;"  ::: "memory")
#define CP_WAIT0()  asm volatile("cp.async.wait_group 0;"  ::: "memory")

__device__ __forceinline__ void mma16816(float* c, const uint32_t* a, const uint32_t* b) {
    asm volatile(
        "mma.sync.aligned.m16n8k16.row.col.f32.f16.f16.f32 "
        "{%0,%1,%2,%3}, {%4,%5,%6,%7}, {%8,%9}, {%0,%1,%2,%3};"
        : "+f"(c[0]), "+f"(c[1]), "+f"(c[2]), "+f"(c[3])
        : "r"(a[0]), "r"(a[1]), "r"(a[2]), "r"(a[3]),
          "r"(b[0]), "r"(b[1]));
}
__device__ __forceinline__ void ldsm_x4(uint32_t* r, uint32_t saddr) {
    asm volatile("ldmatrix.sync.aligned.m8n8.x4.shared.b16 {%0,%1,%2,%3}, [%4];"
        : "=r"(r[0]), "=r"(r[1]), "=r"(r[2]), "=r"(r[3]) : "r"(saddr));
}
__device__ __forceinline__ void ldsm_x4_t(uint32_t* r, uint32_t saddr) {
    asm volatile("ldmatrix.sync.aligned.m8n8.x4.trans.shared.b16 {%0,%1,%2,%3}, [%4];"
        : "=r"(r[0]), "=r"(r[1]), "=r"(r[2]), "=r"(r[3]) : "r"(saddr));
}
__device__ __forceinline__ uint32_t h2u(__half2 v) { return *(uint32_t*)&v; }

// 64B-row swizzle
#define SW64(o) ((o) ^ (((o) >> 3) & 0x30))

// ---------------- block reduce (256 threads) ----------------
__device__ __forceinline__ float block_reduce_256(float v) {
    __shared__ float sh[8];
    #pragma unroll
    for (int o = 16; o; o >>= 1) v += __shfl_down_sync(0xffffffffu, v, o);
    if ((threadIdx.x & 31) == 0) sh[threadIdx.x >> 5] = v;
    __syncthreads();
    if (threadIdx.x == 0) {
        float t = 0.f;
        #pragma unroll
        for (int i = 0; i < 8; i++) t += sh[i];
        sh[0] = t;
    }
    __syncthreads();
    float r = sh[0];
    __syncthreads();
    return r;
}

// ---------------- kernel 1: input layernorm -> fp16 hi/lo ----------------
__global__ __launch_bounds__(256) void ln_kernel(
    const float* __restrict__ x, const float* __restrict__ scale,
    const float* __restrict__ bias,
    __half* __restrict__ oh, __half* __restrict__ ol)
{
    int row = blockIdx.x;
    const float4* xr = (const float4*)(x + (size_t)row * D_);
    float4 v = xr[threadIdx.x];

    float s = v.x + v.y + v.z + v.w;
    float tot = block_reduce_256(s);
    float mu = tot * (1.0f / D_);

    float dx = v.x - mu, dy = v.y - mu, dz = v.z - mu, dw = v.w - mu;
    float sq = dx*dx + dy*dy + dz*dz + dw*dw;
    float vtot = block_reduce_256(sq);
    float rstd = rsqrtf(vtot * (1.0f / D_) + EPS);

    float4 sc = ((const float4*)scale)[threadIdx.x];
    float4 bi = ((const float4*)bias)[threadIdx.x];
    float ov[4];
    ov[0] = dx * rstd * sc.x + bi.x;
    ov[1] = dy * rstd * sc.y + bi.y;
    ov[2] = dz * rstd * sc.z + bi.z;
    ov[3] = dw * rstd * sc.w + bi.w;

    size_t base = (size_t)row * D_ + threadIdx.x * 4;
    #pragma unroll
    for (int j = 0; j < 4; j += 2) {
        __half h0 = __float2half(ov[j]);
        __half h1 = __float2half(ov[j + 1]);
        __half2 hp; hp.x = h0; hp.y = h1;
        __half2 lp;
        lp.x = __float2half(ov[j]     - __half2float(h0));
        lp.y = __float2half(ov[j + 1] - __half2float(h1));
        *(__half2*)&oh[base + j] = hp;
        *(__half2*)&ol[base + j] = lp;
    }
}

// ---------------- weight transpose: W[K][N] -> T[N][K] fp16 ----------------
__global__ __launch_bounds__(256) void convT_kernel(
    const float* __restrict__ W, __half* __restrict__ Th, int K, int N)
{
    __shared__ float t[32][33];
    int tx = threadIdx.x, ty = threadIdx.y;   // 32 x 8
    int nb = blockIdx.x * 32, kb = blockIdx.y * 32;
    #pragma unroll
    for (int i = 0; i < 4; i++)
        t[ty + 8 * i][tx] = W[(size_t)(kb + ty + 8 * i) * N + nb + tx];
    __syncthreads();
    #pragma unroll
    for (int i = 0; i < 4; i++) {
        int n = nb + ty + 8 * i, k = kb + tx;
        Th[(size_t)n * K + k] = __float2half(t[tx][ty + 8 * i]);
    }
}

// ---------------- 3-stage pipelined fp16x2 GEMM ----------------
// C[M,N] = (Ah+Al)[M,K] @ Bf[N,K]^T + bias
#define GT_BYTES 8192                        // one 128x32 fp16 tile
#define GSTAGE   (3 * GT_BYTES)              // Ah, Al, Bf
#define GEMM_SMEM (3 * GSTAGE)               // 73728

__device__ __forceinline__ void gemm_issue_stage(
    char* st,
    const __half* __restrict__ Ah, const __half* __restrict__ Al,
    const __half* __restrict__ Bf,
    int m0, int n0, int K, int kc, int tid)
{
    const __half* srcs[3] = {Ah, Al, Bf};
    const int row0s[3] = {m0, m0, n0};
    #pragma unroll
    for (int t = 0; t < 3; t++) {
        #pragma unroll
        for (int i = 0; i < 2; i++) {
            int u = tid + i * 256;
            int r = u >> 2, c = u & 3;
            uint32_t off = (uint32_t)(r * 64 + c * 16);
            cp16(st + t * GT_BYTES + SW64(off),
                 srcs[t] + (size_t)(row0s[t] + r) * K + kc + c * 8);
        }
    }
}

__global__ __launch_bounds__(256, 2) void gemm_mma(
    const __half* __restrict__ Ah, const __half* __restrict__ Al,
    const __half* __restrict__ Bf,
    const float* __restrict__ bias, float* __restrict__ C, int M, int N, int K)
{
    extern __shared__ char gsm[];
    int tid = threadIdx.x, lane = tid & 31, w = tid >> 5;
    int g = lane >> 2, qi = lane & 3;
    int wm = w >> 1, wn = w & 1;
    int m0 = blockIdx.y * 128, n0 = blockIdx.x * 128;

    uint32_t uG = smem_to_u32(gsm);
    uint32_t baseA[2], baseB[4];
    #pragma unroll
    for (int i = 0; i < 2; i++)
        baseA[i] = (uint32_t)((wm * 32 + i * 16 + (lane & 15)) * 64
                              + (lane >> 4) * 16);
    #pragma unroll
    for (int jp = 0; jp < 4; jp++)
        baseB[jp] = (uint32_t)((wn * 64 + jp * 16 + (lane >> 4) * 8 + (lane & 7)) * 64
                               + ((lane >> 3) & 1) * 16);

    float acc[2][8][4];
    #pragma unroll
    for (int i = 0; i < 2; i++)
        #pragma unroll
        for (int j = 0; j < 8; j++)
            #pragma unroll
            for (int e = 0; e < 4; e++) acc[i][j][e] = 0.f;

    gemm_issue_stage(gsm,          Ah, Al, Bf, m0, n0, K, 0,  tid);
    CP_COMMIT();
    gemm_issue_stage(gsm + GSTAGE, Ah, Al, Bf, m0, n0, K, 32, tid);
    CP_COMMIT();

    int st = 0;
    for (int kc = 0; kc < K; kc += 32) {
        if (kc + 32 < K) { CP_WAIT1(); } else { CP_WAIT0(); }
        __syncthreads();

        if (kc + 64 < K) {
            int nst = st + 2; if (nst >= 3) nst -= 3;
            gemm_issue_stage(gsm + nst * GSTAGE, Ah, Al, Bf, m0, n0, K, kc + 64, tid);
            CP_COMMIT();
        }

        uint32_t uS  = uG + (uint32_t)(st * GSTAGE);
        uint32_t uAh = uS;
        uint32_t uAl = uS + GT_BYTES;
        uint32_t uBf = uS + 2 * GT_BYTES;

        #pragma unroll
        for (int kk = 0; kk < 2; kk++) {
            uint32_t kb = kk * 32;
            uint32_t ah[2][4], al[2][4];
            #pragma unroll
            for (int i = 0; i < 2; i++) {
                ldsm_x4(ah[i], uAh + SW64(baseA[i] + kb));
                ldsm_x4(al[i], uAl + SW64(baseA[i] + kb));
            }
            #pragma unroll
            for (int jp = 0; jp < 4; jp++) {
                uint32_t b4[4];
                ldsm_x4(b4, uBf + SW64(baseB[jp] + kb));
                #pragma unroll
                for (int jj = 0; jj < 2; jj++) {
                    int j = jp * 2 + jj;
                    #pragma unroll
                    for (int i = 0; i < 2; i++) {
                        mma16816(acc[i][j], ah[i], b4 + 2 * jj);
                        mma16816(acc[i][j], al[i], b4 + 2 * jj);
                    }
                }
            }
        }
        st = st + 1; if (st >= 3) st = 0;
    }

    #pragma unroll
    for (int i = 0; i < 2; i++) {
        int r0 = m0 + wm * 32 + i * 16 + g;
        #pragma unroll
        for (int j = 0; j < 8; j++) {
            int col = n0 + wn * 64 + j * 8 + 2 * qi;
            float b0 = __ldg(&bias[col]), b1 = __ldg(&bias[col + 1]);
            float2 v0 = make_float2(acc[i][j][0] + b0, acc[i][j][1] + b1);
            float2 v1 = make_float2(acc[i][j][2] + b0, acc[i][j][3] + b1);
            *(float2*)&C[(size_t)r0 * N + col]       = v0;
            *(float2*)&C[(size_t)(r0 + 8) * N + col] = v1;
        }
    }
}

// ---------------- kernel 3: split qkv + per-head LN + RoPE ----------------
__global__ __launch_bounds__(256) void split_rope(
    const float* __restrict__ qkv, const float* __restrict__ q_scale,
    const float* __restrict__ k_scale,
    __half* __restrict__ qh, __half* __restrict__ ql,
    __half* __restrict__ kf, __half* __restrict__ vf)
{
    int lane = threadIdx.x & 31;
    int wl   = threadIdx.x >> 5;
    int pair = blockIdx.x * 8 + wl;     // row * H + h
    int row  = pair >> 4;
    int h    = pair & 15;
    int b    = row >> 11;
    int s    = row & (S_ - 1);

    const float* base = qkv + (size_t)row * (3 * D_) + h * HD_;
    float q0 = base[lane],          q1 = base[lane + 32];
    float k0 = base[D_ + lane],     k1 = base[D_ + lane + 32];
    float v0 = base[2 * D_ + lane], v1 = base[2 * D_ + lane + 32];

    float qs = q0 + q1, qq = q0 * q0 + q1 * q1;
    float ks = k0 + k1, kq = k0 * k0 + k1 * k1;
    #pragma unroll
    for (int o = 16; o; o >>= 1) {
        qs += __shfl_xor_sync(0xffffffffu, qs, o);
        qq += __shfl_xor_sync(0xffffffffu, qq, o);
        ks += __shfl_xor_sync(0xffffffffu, ks, o);
        kq += __shfl_xor_sync(0xffffffffu, kq, o);
    }
    float muq = qs * (1.0f / HD_);
    float rq  = rsqrtf(qq * (1.0f / HD_) - muq * muq + EPS);
    float muk = ks * (1.0f / HD_);
    float rk  = rsqrtf(kq * (1.0f / HD_) - muk * muk + EPS);

    float qn0 = (q0 - muq) * rq * q_scale[lane];
    float qn1 = (q1 - muq) * rq * q_scale[lane + 32];
    float kn0 = (k0 - muk) * rk * k_scale[lane];
    float kn1 = (k1 - muk) * rk * k_scale[lane + 32];

    float inv = expf(-(float)(2 * lane) * (1.0f / 64.0f) * 9.210340371976184f);
    float sn, cs;
    sincosf((float)s * inv, &sn, &cs);

    float qf0 = (qn0 * cs - qn1 * sn) * 0.125f;
    float qf1 = (qn1 * cs + qn0 * sn) * 0.125f;
    float kf0 = kn0 * cs - kn1 * sn;
    float kf1 = kn1 * cs + kn0 * sn;

    size_t oidx = (((size_t)(b * H_ + h)) * S_ + s) * HD_ + lane;
    __half t;
    t = __float2half(qf0); qh[oidx]      = t; ql[oidx]      = __float2half(qf0 - __half2float(t));
    t = __float2half(qf1); qh[oidx + 32] = t; ql[oidx + 32] = __float2half(qf1 - __half2float(t));
    kf[oidx]      = __float2half(kf0);
    kf[oidx + 32] = __float2half(kf1);
    vf[oidx]      = __float2half(v0);
    vf[oidx + 32] = __float2half(v1);
}

// ---------------- flash attention: fp16x2, ldmatrix + cp.async double buffer ----------------
#define LQ 72
#define KVT (64 * LQ)
#define FL_SMEM ((2 * 128 * LQ + 2 * 2 * KVT) * (int)sizeof(__half))

__device__ __forceinline__ void flash_issue_kv(
    __half* st,
    const __half* __restrict__ Kp, const __half* __restrict__ Vp,
    int j0, int tid)
{
    int r = tid >> 2, c = (tid & 3) * 16;
    size_t go = (size_t)(j0 + r) * HD_ + c;
    int so = r * LQ + c;
    cp16(st + so,           Kp + go);
    cp16(st + so + 8,       Kp + go + 8);
    cp16(st + KVT + so,     Vp + go);
    cp16(st + KVT + so + 8, Vp + go + 8);
}

__global__ __launch_bounds__(256, 2) void flash_mma(
    const __half* __restrict__ Qh_, const __half* __restrict__ Ql_,
    const __half* __restrict__ Kf_, const __half* __restrict__ Vf_,
    __half* __restrict__ Oh_, __half* __restrict__ Ol_)
{
    extern __shared__ __half fsm[];
    __half* sQh = fsm;                 // [128][LQ]
    __half* sQl = sQh + 128 * LQ;
    __half* sKV = sQl + 128 * LQ;      // 2 stages x {K, V}

    int tid = threadIdx.x, lane = tid & 31, wid = tid >> 5;
    int g = lane >> 2, qi = lane & 3;
    int bh = blockIdx.y;
    int b = bh >> 4, h = bh & 15;
    int q0 = blockIdx.x * 128;
    size_t hbase = (size_t)bh * S_ * HD_;
    const __half* Qhp = Qh_ + hbase;
    const __half* Qlp = Ql_ + hbase;
    const __half* Kfp = Kf_ + hbase;
    const __half* Vfp = Vf_ + hbase;

    int wr = wid * 16;
    uint32_t uQh = smem_to_u32(sQh), uQl = smem_to_u32(sQl);
    uint32_t uKV = smem_to_u32(sKV);

    uint32_t offQ = ((wr + (lane & 15)) * LQ + (lane >> 4) * 8) * 2;
    uint32_t offK[4], offV[4];
    #pragma unroll
    for (int tp = 0; tp < 4; tp++)
        offK[tp] = ((tp * 16 + (lane >> 4) * 8 + (lane & 7)) * LQ
                    + ((lane >> 3) & 1) * 8) * 2;
    #pragma unroll
    for (int tdp = 0; tdp < 4; tdp++)
        offV[tdp] = ((((lane >> 3) & 1) * 8 + (lane & 7)) * LQ
                     + (2 * tdp + (lane >> 4)) * 8) * 2;

    #pragma unroll
    for (int i = 0; i < 4; i++) {
        int u = tid + i * 256;
        int r = u >> 3, c = (u & 7) * 8;
        *(uint4*)&sQh[r * LQ + c] = *(const uint4*)&Qhp[(size_t)(q0 + r) * HD_ + c];
        *(uint4*)&sQl[r * LQ + c] = *(const uint4*)&Qlp[(size_t)(q0 + r) * HD_ + c];
    }
    flash_issue_kv(sKV, Kfp, Vfp, 0, tid);
    CP_COMMIT();

    float o[8][4];
    #pragma unroll
    for (int t = 0; t < 8; t++)
        #pragma unroll
        for (int e = 0; e < 4; e++) o[t][e] = 0.f;
    float m_g = -1e30f, m_g8 = -1e30f, l_g = 0.f, l_g8 = 0.f;

    const int NT = S_ / 64;
    for (int kt = 0; kt < NT; kt++) {
        if (kt + 1 < NT) {
            flash_issue_kv(sKV + ((kt + 1) & 1) * 2 * KVT, Kfp, Vfp, (kt + 1) * 64, tid);
            CP_COMMIT();
            CP_WAIT1();
        } else {
            CP_WAIT0();
        }
        __syncthreads();

        uint32_t uS = uKV + ((kt & 1) * 2 * KVT) * 2;
        uint32_t uK = uS;
        uint32_t uV = uS + KVT * 2;

        float s[8][4];
        #pragma unroll
        for (int t = 0; t < 8; t++)
            #pragma unroll
            for (int e = 0; e < 4; e++) s[t][e] = 0.f;

        #pragma unroll
        for (int u = 0; u < 4; u++) {
            uint32_t ah[4], al[4];
            ldsm_x4(ah, uQh + offQ + u * 32);
            ldsm_x4(al, uQl + offQ + u * 32);
            #pragma unroll
            for (int tp = 0; tp < 4; tp++) {
                uint32_t b4[4];
                ldsm_x4(b4, uK + offK[tp] + u * 32);
                mma16816(s[2 * tp],     ah, b4);
                mma16816(s[2 * tp],     al, b4);
                mma16816(s[2 * tp + 1], ah, b4 + 2);
                mma16816(s[2 * tp + 1], al, b4 + 2);
            }
        }

        float mt_g = -1e30f, mt_g8 = -1e30f;
        #pragma unroll
        for (int t = 0; t < 8; t++) {
            mt_g  = fmaxf(mt_g,  fmaxf(s[t][0], s[t][1]));
            mt_g8 = fmaxf(mt_g8, fmaxf(s[t][2], s[t][3]));
        }
        mt_g  = fmaxf(mt_g,  __shfl_xor_sync(0xffffffffu, mt_g, 1));
        mt_g  = fmaxf(mt_g,  __shfl_xor_sync(0xffffffffu, mt_g, 2));
        mt_g8 = fmaxf(mt_g8, __shfl_xor_sync(0xffffffffu, mt_g8, 1));
        mt_g8 = fmaxf(mt_g8, __shfl_xor_sync(0xffffffffu, mt_g8, 2));
        float mn_g = fmaxf(m_g, mt_g), mn_g8 = fmaxf(m_g8, mt_g8);
        float al_g = __expf(m_g - mn_g), al_g8 = __expf(m_g8 - mn_g8);
        m_g = mn_g; m_g8 = mn_g8;

        uint32_t ph01[8], ph23[8], pl01[8], pl23[8];
        float sum_g = 0.f, sum_g8 = 0.f;
        #pragma unroll
        for (int t = 0; t < 8; t++) {
            float p0 = __expf(s[t][0] - mn_g);
            float p1 = __expf(s[t][1] - mn_g);
            float p2 = __expf(s[t][2] - mn_g8);
            float p3 = __expf(s[t][3] - mn_g8);
            sum_g += p0 + p1; sum_g8 += p2 + p3;
            __half2 hh = __floats2half2_rn(p0, p1);
            ph01[t] = h2u(hh);
            pl01[t] = h2u(__floats2half2_rn(p0 - __half2float(hh.x),
                                            p1 - __half2float(hh.y)));
            hh = __floats2half2_rn(p2, p3);
            ph23[t] = h2u(hh);
            pl23[t] = h2u(__floats2half2_rn(p2 - __half2float(hh.x),
                                            p3 - __half2float(hh.y)));
        }
        sum_g  += __shfl_xor_sync(0xffffffffu, sum_g, 1);
        sum_g  += __shfl_xor_sync(0xffffffffu, sum_g, 2);
        sum_g8 += __shfl_xor_sync(0xffffffffu, sum_g8, 1);
        sum_g8 += __shfl_xor_sync(0xffffffffu, sum_g8, 2);
        l_g  = l_g  * al_g  + sum_g;
        l_g8 = l_g8 * al_g8 + sum_g8;

        #pragma unroll
        for (int t = 0; t < 8; t++) {
            o[t][0] *= al_g;  o[t][1] *= al_g;
            o[t][2] *= al_g8; o[t][3] *= al_g8;
        }

        #pragma unroll
        for (int u = 0; u < 4; u++) {
            uint32_t pah[4] = {ph01[2*u], ph23[2*u], ph01[2*u+1], ph23[2*u+1]};
            uint32_t pal[4] = {pl01[2*u], pl23[2*u], pl01[2*u+1], pl23[2*u+1]};
            uint32_t ubase = u * 16 * LQ * 2;
            #pragma unroll
            for (int tdp = 0; tdp < 4; tdp++) {
                uint32_t bv4[4];
                ldsm_x4_t(bv4, uV + offV[tdp] + ubase);
                mma16816(o[2 * tdp],     pah, bv4);
                mma16816(o[2 * tdp],     pal, bv4);
                mma16816(o[2 * tdp + 1], pah, bv4 + 2);
                mma16816(o[2 * tdp + 1], pal, bv4 + 2);
            }
        }
        __syncthreads();
    }

    float iv_g = 1.f / l_g, iv_g8 = 1.f / l_g8;
    size_t ob  = ((size_t)(b * S_ + q0 + wr + g)     * H_ + h) * HD_;
    size_t ob8 = ((size_t)(b * S_ + q0 + wr + g + 8) * H_ + h) * HD_;
    #pragma unroll
    for (int td = 0; td < 8; td++) {
        int d = 8 * td + 2 * qi;
        float v0 = o[td][0] * iv_g,  v1 = o[td][1] * iv_g;
        float v2 = o[td][2] * iv_g8, v3 = o[td][3] * iv_g8;
        __half2 hh = __floats2half2_rn(v0, v1);
        *(uint32_t*)&Oh_[ob + d] = h2u(hh);
        *(uint32_t*)&Ol_[ob + d] = h2u(__floats2half2_rn(
            v0 - __half2float(hh.x), v1 - __half2float(hh.y)));
        hh = __floats2half2_rn(v2, v3);
        *(uint32_t*)&Oh_[ob8 + d] = h2u(hh);
        *(uint32_t*)&Ol_[ob8 + d] = h2u(__floats2half2_rn(
            v2 - __half2float(hh.x), v3 - __half2float(hh.y)));
    }
}

// ---------------- launcher ----------------
extern "C" void kernel_launch(void* const* d_in, const int* in_sizes, int n_in,
                              void* d_out, int out_size)
{
    const float* x        = (const float*)d_in[0];
    const float* w_qkv    = (const float*)d_in[1];
    const float* b_qkv    = (const float*)d_in[2];
    const float* w_out    = (const float*)d_in[3];
    const float* b_out    = (const float*)d_in[4];
    const float* ln_scale = (const float*)d_in[5];
    const float* ln_bias  = (const float*)d_in[6];
    const float* q_scale  = (const float*)d_in[7];
    const float* k_scale  = (const float*)d_in[8];
    float* out = (float*)d_out;

    __half *xnh, *xnl, *wq, *wo, *ath, *atl, *qh, *ql, *kf, *vf;
    float *qkv;
    cudaGetSymbolAddress((void**)&xnh, g_xnh);
    cudaGetSymbolAddress((void**)&xnl, g_xnl);
    cudaGetSymbolAddress((void**)&wq,  g_wqT);
    cudaGetSymbolAddress((void**)&wo,  g_woT);
    cudaGetSymbolAddress((void**)&qkv, g_qkv);
    cudaGetSymbolAddress((void**)&qh,  g_qh);
    cudaGetSymbolAddress((void**)&ql,  g_ql);
    cudaGetSymbolAddress((void**)&kf,  g_kf);
    cudaGetSymbolAddress((void**)&vf,  g_vf);
    cudaGetSymbolAddress((void**)&ath, g_attnh);
    cudaGetSymbolAddress((void**)&atl, g_attnl);

    cudaFuncSetAttribute(gemm_mma,
        cudaFuncAttributeMaxDynamicSharedMemorySize, GEMM_SMEM);
    cudaFuncSetAttribute(flash_mma,
        cudaFuncAttributeMaxDynamicSharedMemorySize, FL_SMEM);

    // 1. input layernorm -> fp16 hi/lo
    ln_kernel<<<ROWS, 256>>>(x, ln_scale, ln_bias, xnh, xnl);

    // 2. weight transpose -> fp16
    convT_kernel<<<dim3((3 * D_) / 32, D_ / 32), dim3(32, 8)>>>(w_qkv, wq, D_, 3 * D_);
    convT_kernel<<<dim3(D_ / 32, D_ / 32), dim3(32, 8)>>>(w_out, wo, D_, D_);

    // 3. QKV GEMM (fp16 2-term)
    gemm_mma<<<dim3((3 * D_) / 128, ROWS / 128), 256, GEMM_SMEM>>>(
        xnh, xnl, wq, b_qkv, qkv, ROWS, 3 * D_, D_);

    // 4. split + per-head LN + RoPE
    split_rope<<<ROWS * H_ / 8, 256>>>(qkv, q_scale, k_scale, qh, ql, kf, vf);

    // 5. flash attention (fp16 2-term)
    flash_mma<<<dim3(S_ / 128, B_ * H_), 256, FL_SMEM>>>(
        qh, ql, kf, vf, ath, atl);

    // 6. output GEMM (fp16 2-term)
    gemm_mma<<<dim3(D_ / 128, ROWS / 128), 256, GEMM_SMEM>>>(
        ath, atl, wo, b_out, out, ROWS, D_, D_);
}

// round 10
// speedup vs baseline: 8.4318x; 1.0884x over previous
#include <cuda_runtime.h>
#include <cuda_fp16.h>
#include <cstdint>
#include <math.h>

#define B_  2
#define S_  2048
#define D_  1024
#define H_  16
#define HD_ 64
#define EPS 1e-6f

#define ROWS (B_ * S_)          // 4096

// ---------------- scratch (device globals; no allocation) ----------------
__device__ __half g_xnh [ROWS * D_];
__device__ __half g_xnl [ROWS * D_];
__device__ __half g_wqT [3 * D_ * D_];   // [3072][1024] K-major fp16
__device__ __half g_woT [D_ * D_];       // [1024][1024] K-major
__device__ float  g_qkv [ROWS * 3 * D_];
__device__ __half g_qh[B_ * H_ * S_ * HD_];
__device__ __half g_ql[B_ * H_ * S_ * HD_];
__device__ __half g_kf[B_ * H_ * S_ * HD_];
__device__ __half g_vf[B_ * H_ * S_ * HD_];
__device__ __half g_attnh[ROWS * D_];
__device__ __half g_attnl[ROWS * D_];

// ================= helpers =================
__device__ __forceinline__ uint32_t smem_to_u32(const void* p) {
    uint32_t a;
    asm("{ .reg .u64 t; cvta.to.shared.u64 t, %1; cvt.u32.u64 %0, t; }"
        : "=r"(a) : "l"(p));
    return a;
}
__device__ __forceinline__ void cp16(void* sp, const void* gp) {
    uint32_t s = smem_to_u32(sp);
    asm volatile("cp.async.cg.shared.global [%0], [%1], 16;" :: "r"(s), "l"(gp));
}
#define CP_COMMIT() asm volatile("cp.async.commit_group;" ::: "memory")
#define CP_WAIT2()  asm volatile("cp.async.wait_group 2;"  ::: "memory")
#define CP_WAIT1()  asm volatile("cp.async.wait_group 1;"  ::: "memory")
#define CP_WAIT0()  asm volatile("cp.async.wait_group 0;"  ::: "memory")

__device__ __forceinline__ void mma16816(float* c, const uint32_t* a, const uint32_t* b) {
    asm volatile(
        "mma.sync.aligned.m16n8k16.row.col.f32.f16.f16.f32 "
        "{%0,%1,%2,%3}, {%4,%5,%6,%7}, {%8,%9}, {%0,%1,%2,%3};"
        : "+f"(c[0]), "+f"(c[1]), "+f"(c[2]), "+f"(c[3])
        : "r"(a[0]), "r"(a[1]), "r"(a[2]), "r"(a[3]),
          "r"(b[0]), "r"(b[1]));
}
__device__ __forceinline__ void ldsm_x4(uint32_t* r, uint32_t saddr) {
    asm volatile("ldmatrix.sync.aligned.m8n8.x4.shared.b16 {%0,%1,%2,%3}, [%4];"
        : "=r"(r[0]), "=r"(r[1]), "=r"(r[2]), "=r"(r[3]) : "r"(saddr));
}
__device__ __forceinline__ void ldsm_x4_t(uint32_t* r, uint32_t saddr) {
    asm volatile("ldmatrix.sync.aligned.m8n8.x4.trans.shared.b16 {%0,%1,%2,%3}, [%4];"
        : "=r"(r[0]), "=r"(r[1]), "=r"(r[2]), "=r"(r[3]) : "r"(saddr));
}
__device__ __forceinline__ uint32_t h2u(__half2 v) { return *(uint32_t*)&v; }

// 64B-row swizzle
#define SW64(o) ((o) ^ (((o) >> 3) & 0x30))

// ---------------- block reduce (256 threads) ----------------
__device__ __forceinline__ float block_reduce_256(float v) {
    __shared__ float sh[8];
    #pragma unroll
    for (int o = 16; o; o >>= 1) v += __shfl_down_sync(0xffffffffu, v, o);
    if ((threadIdx.x & 31) == 0) sh[threadIdx.x >> 5] = v;
    __syncthreads();
    if (threadIdx.x == 0) {
        float t = 0.f;
        #pragma unroll
        for (int i = 0; i < 8; i++) t += sh[i];
        sh[0] = t;
    }
    __syncthreads();
    float r = sh[0];
    __syncthreads();
    return r;
}

// ---------------- kernel 1: input layernorm -> fp16 hi/lo ----------------
__global__ __launch_bounds__(256) void ln_kernel(
    const float* __restrict__ x, const float* __restrict__ scale,
    const float* __restrict__ bias,
    __half* __restrict__ oh, __half* __restrict__ ol)
{
    int row = blockIdx.x;
    const float4* xr = (const float4*)(x + (size_t)row * D_);
    float4 v = xr[threadIdx.x];

    float s = v.x + v.y + v.z + v.w;
    float tot = block_reduce_256(s);
    float mu = tot * (1.0f / D_);

    float dx = v.x - mu, dy = v.y - mu, dz = v.z - mu, dw = v.w - mu;
    float sq = dx*dx + dy*dy + dz*dz + dw*dw;
    float vtot = block_reduce_256(sq);
    float rstd = rsqrtf(vtot * (1.0f / D_) + EPS);

    float4 sc = ((const float4*)scale)[threadIdx.x];
    float4 bi = ((const float4*)bias)[threadIdx.x];
    float ov[4];
    ov[0] = dx * rstd * sc.x + bi.x;
    ov[1] = dy * rstd * sc.y + bi.y;
    ov[2] = dz * rstd * sc.z + bi.z;
    ov[3] = dw * rstd * sc.w + bi.w;

    size_t base = (size_t)row * D_ + threadIdx.x * 4;
    #pragma unroll
    for (int j = 0; j < 4; j += 2) {
        __half h0 = __float2half(ov[j]);
        __half h1 = __float2half(ov[j + 1]);
        __half2 hp; hp.x = h0; hp.y = h1;
        __half2 lp;
        lp.x = __float2half(ov[j]     - __half2float(h0));
        lp.y = __float2half(ov[j + 1] - __half2float(h1));
        *(__half2*)&oh[base + j] = hp;
        *(__half2*)&ol[base + j] = lp;
    }
}

// ---------------- weight transpose: W[K][N] -> T[N][K] fp16 ----------------
__global__ __launch_bounds__(256) void convT_kernel(
    const float* __restrict__ W, __half* __restrict__ Th, int K, int N)
{
    __shared__ float t[32][33];
    int tx = threadIdx.x, ty = threadIdx.y;   // 32 x 8
    int nb = blockIdx.x * 32, kb = blockIdx.y * 32;
    #pragma unroll
    for (int i = 0; i < 4; i++)
        t[ty + 8 * i][tx] = W[(size_t)(kb + ty + 8 * i) * N + nb + tx];
    __syncthreads();
    #pragma unroll
    for (int i = 0; i < 4; i++) {
        int n = nb + ty + 8 * i, k = kb + tx;
        Th[(size_t)n * K + k] = __float2half(t[tx][ty + 8 * i]);
    }
}

// ---------------- 4-stage pipelined fp16x2 GEMM ----------------
// C[M,N] = (Ah+Al)[M,K] @ Bf[N,K]^T + bias
#define GT_BYTES 8192                        // one 128x32 fp16 tile
#define GSTAGE   (3 * GT_BYTES)              // Ah, Al, Bf
#define GEMM_SMEM (4 * GSTAGE)               // 98304

__device__ __forceinline__ void gemm_issue_stage(
    char* st,
    const __half* __restrict__ Ah, const __half* __restrict__ Al,
    const __half* __restrict__ Bf,
    int m0, int n0, int K, int kc, int tid)
{
    const __half* srcs[3] = {Ah, Al, Bf};
    const int row0s[3] = {m0, m0, n0};
    #pragma unroll
    for (int t = 0; t < 3; t++) {
        #pragma unroll
        for (int i = 0; i < 2; i++) {
            int u = tid + i * 256;
            int r = u >> 2, c = u & 3;
            uint32_t off = (uint32_t)(r * 64 + c * 16);
            cp16(st + t * GT_BYTES + SW64(off),
                 srcs[t] + (size_t)(row0s[t] + r) * K + kc + c * 8);
        }
    }
}

__global__ __launch_bounds__(256, 2) void gemm_mma(
    const __half* __restrict__ Ah, const __half* __restrict__ Al,
    const __half* __restrict__ Bf,
    const float* __restrict__ bias, float* __restrict__ C, int M, int N, int K)
{
    extern __shared__ char gsm[];
    int tid = threadIdx.x, lane = tid & 31, w = tid >> 5;
    int g = lane >> 2, qi = lane & 3;
    int wm = w >> 1, wn = w & 1;
    int m0 = blockIdx.y * 128, n0 = blockIdx.x * 128;

    uint32_t uG = smem_to_u32(gsm);
    uint32_t baseA[2], baseB[4];
    #pragma unroll
    for (int i = 0; i < 2; i++)
        baseA[i] = (uint32_t)((wm * 32 + i * 16 + (lane & 15)) * 64
                              + (lane >> 4) * 16);
    #pragma unroll
    for (int jp = 0; jp < 4; jp++)
        baseB[jp] = (uint32_t)((wn * 64 + jp * 16 + (lane >> 4) * 8 + (lane & 7)) * 64
                               + ((lane >> 3) & 1) * 16);

    float acc[2][8][4];
    #pragma unroll
    for (int i = 0; i < 2; i++)
        #pragma unroll
        for (int j = 0; j < 8; j++)
            #pragma unroll
            for (int e = 0; e < 4; e++) acc[i][j][e] = 0.f;

    const int NK = K >> 5;
    gemm_issue_stage(gsm,              Ah, Al, Bf, m0, n0, K, 0,  tid);
    CP_COMMIT();
    gemm_issue_stage(gsm + GSTAGE,     Ah, Al, Bf, m0, n0, K, 32, tid);
    CP_COMMIT();
    gemm_issue_stage(gsm + 2 * GSTAGE, Ah, Al, Bf, m0, n0, K, 64, tid);
    CP_COMMIT();

    for (int i = 0; i < NK; i++) {
        int rem = NK - 1 - i;
        if (rem >= 2) { CP_WAIT2(); } else if (rem == 1) { CP_WAIT1(); } else { CP_WAIT0(); }
        __syncthreads();

        if (i + 3 < NK) {
            gemm_issue_stage(gsm + ((i + 3) & 3) * GSTAGE,
                             Ah, Al, Bf, m0, n0, K, (i + 3) * 32, tid);
            CP_COMMIT();
        }

        uint32_t uS  = uG + (uint32_t)((i & 3) * GSTAGE);
        uint32_t uAh = uS;
        uint32_t uAl = uS + GT_BYTES;
        uint32_t uBf = uS + 2 * GT_BYTES;

        #pragma unroll
        for (int kk = 0; kk < 2; kk++) {
            uint32_t kb = kk * 32;
            uint32_t ah[2][4], al[2][4];
            #pragma unroll
            for (int ii = 0; ii < 2; ii++) {
                ldsm_x4(ah[ii], uAh + SW64(baseA[ii] + kb));
                ldsm_x4(al[ii], uAl + SW64(baseA[ii] + kb));
            }
            #pragma unroll
            for (int jp = 0; jp < 4; jp++) {
                uint32_t b4[4];
                ldsm_x4(b4, uBf + SW64(baseB[jp] + kb));
                #pragma unroll
                for (int jj = 0; jj < 2; jj++) {
                    int j = jp * 2 + jj;
                    #pragma unroll
                    for (int ii = 0; ii < 2; ii++) {
                        mma16816(acc[ii][j], ah[ii], b4 + 2 * jj);
                        mma16816(acc[ii][j], al[ii], b4 + 2 * jj);
                    }
                }
            }
        }
    }

    #pragma unroll
    for (int i = 0; i < 2; i++) {
        int r0 = m0 + wm * 32 + i * 16 + g;
        #pragma unroll
        for (int j = 0; j < 8; j++) {
            int col = n0 + wn * 64 + j * 8 + 2 * qi;
            float b0 = __ldg(&bias[col]), b1 = __ldg(&bias[col + 1]);
            float2 v0 = make_float2(acc[i][j][0] + b0, acc[i][j][1] + b1);
            float2 v1 = make_float2(acc[i][j][2] + b0, acc[i][j][3] + b1);
            *(float2*)&C[(size_t)r0 * N + col]       = v0;
            *(float2*)&C[(size_t)(r0 + 8) * N + col] = v1;
        }
    }
}

// ---------------- kernel 3: split qkv + per-head LN + RoPE ----------------
__global__ __launch_bounds__(256) void split_rope(
    const float* __restrict__ qkv, const float* __restrict__ q_scale,
    const float* __restrict__ k_scale,
    __half* __restrict__ qh, __half* __restrict__ ql,
    __half* __restrict__ kf, __half* __restrict__ vf)
{
    int lane = threadIdx.x & 31;
    int wl   = threadIdx.x >> 5;
    int pair = blockIdx.x * 8 + wl;     // row * H + h
    int row  = pair >> 4;
    int h    = pair & 15;
    int b    = row >> 11;
    int s    = row & (S_ - 1);

    const float* base = qkv + (size_t)row * (3 * D_) + h * HD_;
    float q0 = base[lane],          q1 = base[lane + 32];
    float k0 = base[D_ + lane],     k1 = base[D_ + lane + 32];
    float v0 = base[2 * D_ + lane], v1 = base[2 * D_ + lane + 32];

    float qs = q0 + q1, qq = q0 * q0 + q1 * q1;
    float ks = k0 + k1, kq = k0 * k0 + k1 * k1;
    #pragma unroll
    for (int o = 16; o; o >>= 1) {
        qs += __shfl_xor_sync(0xffffffffu, qs, o);
        qq += __shfl_xor_sync(0xffffffffu, qq, o);
        ks += __shfl_xor_sync(0xffffffffu, ks, o);
        kq += __shfl_xor_sync(0xffffffffu, kq, o);
    }
    float muq = qs * (1.0f / HD_);
    float rq  = rsqrtf(qq * (1.0f / HD_) - muq * muq + EPS);
    float muk = ks * (1.0f / HD_);
    float rk  = rsqrtf(kq * (1.0f / HD_) - muk * muk + EPS);

    float qn0 = (q0 - muq) * rq * q_scale[lane];
    float qn1 = (q1 - muq) * rq * q_scale[lane + 32];
    float kn0 = (k0 - muk) * rk * k_scale[lane];
    float kn1 = (k1 - muk) * rk * k_scale[lane + 32];

    float inv = expf(-(float)(2 * lane) * (1.0f / 64.0f) * 9.210340371976184f);
    float sn, cs;
    sincosf((float)s * inv, &sn, &cs);

    float qf0 = (qn0 * cs - qn1 * sn) * 0.125f;
    float qf1 = (qn1 * cs + qn0 * sn) * 0.125f;
    float kf0 = kn0 * cs - kn1 * sn;
    float kf1 = kn1 * cs + kn0 * sn;

    size_t oidx = (((size_t)(b * H_ + h)) * S_ + s) * HD_ + lane;
    __half t;
    t = __float2half(qf0); qh[oidx]      = t; ql[oidx]      = __float2half(qf0 - __half2float(t));
    t = __float2half(qf1); qh[oidx + 32] = t; ql[oidx + 32] = __float2half(qf1 - __half2float(t));
    kf[oidx]      = __float2half(kf0);
    kf[oidx + 32] = __float2half(kf1);
    vf[oidx]      = __float2half(v0);
    vf[oidx + 32] = __float2half(v1);
}

// ---------------- flash attention: 3-stage KV ring, single sync/tile ----------------
#define LQ 72
#define KVT (64 * LQ)
#define KVSTG (2 * KVT)                    // K + V, one stage (elements)
#define FL_SMEM ((2 * 128 * LQ + 3 * KVSTG) * (int)sizeof(__half))

__device__ __forceinline__ void flash_issue_kv(
    __half* st,
    const __half* __restrict__ Kp, const __half* __restrict__ Vp,
    int j0, int tid)
{
    int r = tid >> 2, c = (tid & 3) * 16;
    size_t go = (size_t)(j0 + r) * HD_ + c;
    int so = r * LQ + c;
    cp16(st + so,           Kp + go);
    cp16(st + so + 8,       Kp + go + 8);
    cp16(st + KVT + so,     Vp + go);
    cp16(st + KVT + so + 8, Vp + go + 8);
}

__global__ __launch_bounds__(256, 2) void flash_mma(
    const __half* __restrict__ Qh_, const __half* __restrict__ Ql_,
    const __half* __restrict__ Kf_, const __half* __restrict__ Vf_,
    __half* __restrict__ Oh_, __half* __restrict__ Ol_)
{
    extern __shared__ __half fsm[];
    __half* sQh = fsm;                 // [128][LQ]
    __half* sQl = sQh + 128 * LQ;
    __half* sKV = sQl + 128 * LQ;      // 3 stages x {K, V}

    int tid = threadIdx.x, lane = tid & 31, wid = tid >> 5;
    int g = lane >> 2, qi = lane & 3;
    int bh = blockIdx.y;
    int b = bh >> 4, h = bh & 15;
    int q0 = blockIdx.x * 128;
    size_t hbase = (size_t)bh * S_ * HD_;
    const __half* Qhp = Qh_ + hbase;
    const __half* Qlp = Ql_ + hbase;
    const __half* Kfp = Kf_ + hbase;
    const __half* Vfp = Vf_ + hbase;

    int wr = wid * 16;
    uint32_t uQh = smem_to_u32(sQh), uQl = smem_to_u32(sQl);
    uint32_t uKV = smem_to_u32(sKV);

    uint32_t offQ = ((wr + (lane & 15)) * LQ + (lane >> 4) * 8) * 2;
    uint32_t offK[4], offV[4];
    #pragma unroll
    for (int tp = 0; tp < 4; tp++)
        offK[tp] = ((tp * 16 + (lane >> 4) * 8 + (lane & 7)) * LQ
                    + ((lane >> 3) & 1) * 8) * 2;
    #pragma unroll
    for (int tdp = 0; tdp < 4; tdp++)
        offV[tdp] = ((((lane >> 3) & 1) * 8 + (lane & 7)) * LQ
                     + (2 * tdp + (lane >> 4)) * 8) * 2;

    #pragma unroll
    for (int i = 0; i < 4; i++) {
        int u = tid + i * 256;
        int r = u >> 3, c = (u & 7) * 8;
        *(uint4*)&sQh[r * LQ + c] = *(const uint4*)&Qhp[(size_t)(q0 + r) * HD_ + c];
        *(uint4*)&sQl[r * LQ + c] = *(const uint4*)&Qlp[(size_t)(q0 + r) * HD_ + c];
    }
    flash_issue_kv(sKV,         Kfp, Vfp, 0,  tid);
    CP_COMMIT();
    flash_issue_kv(sKV + KVSTG, Kfp, Vfp, 64, tid);
    CP_COMMIT();

    float o[8][4];
    #pragma unroll
    for (int t = 0; t < 8; t++)
        #pragma unroll
        for (int e = 0; e < 4; e++) o[t][e] = 0.f;
    float m_g = -1e30f, m_g8 = -1e30f, l_g = 0.f, l_g8 = 0.f;

    const int NT = S_ / 64;
    int stg = 0;                       // stage index = kt % 3
    for (int kt = 0; kt < NT; kt++) {
        if (kt + 1 < NT) { CP_WAIT1(); } else { CP_WAIT0(); }
        __syncthreads();

        if (kt + 2 < NT) {
            int nst = stg + 2; if (nst >= 3) nst -= 3;
            flash_issue_kv(sKV + nst * KVSTG, Kfp, Vfp, (kt + 2) * 64, tid);
            CP_COMMIT();
        }

        uint32_t uS = uKV + (uint32_t)(stg * KVSTG) * 2;
        uint32_t uK = uS;
        uint32_t uV = uS + KVT * 2;

        float s[8][4];
        #pragma unroll
        for (int t = 0; t < 8; t++)
            #pragma unroll
            for (int e = 0; e < 4; e++) s[t][e] = 0.f;

        #pragma unroll
        for (int u = 0; u < 4; u++) {
            uint32_t ah[4], al[4];
            ldsm_x4(ah, uQh + offQ + u * 32);
            ldsm_x4(al, uQl + offQ + u * 32);
            #pragma unroll
            for (int tp = 0; tp < 4; tp++) {
                uint32_t b4[4];
                ldsm_x4(b4, uK + offK[tp] + u * 32);
                mma16816(s[2 * tp],     ah, b4);
                mma16816(s[2 * tp],     al, b4);
                mma16816(s[2 * tp + 1], ah, b4 + 2);
                mma16816(s[2 * tp + 1], al, b4 + 2);
            }
        }

        float mt_g = -1e30f, mt_g8 = -1e30f;
        #pragma unroll
        for (int t = 0; t < 8; t++) {
            mt_g  = fmaxf(mt_g,  fmaxf(s[t][0], s[t][1]));
            mt_g8 = fmaxf(mt_g8, fmaxf(s[t][2], s[t][3]));
        }
        mt_g  = fmaxf(mt_g,  __shfl_xor_sync(0xffffffffu, mt_g, 1));
        mt_g  = fmaxf(mt_g,  __shfl_xor_sync(0xffffffffu, mt_g, 2));
        mt_g8 = fmaxf(mt_g8, __shfl_xor_sync(0xffffffffu, mt_g8, 1));
        mt_g8 = fmaxf(mt_g8, __shfl_xor_sync(0xffffffffu, mt_g8, 2));
        float mn_g = fmaxf(m_g, mt_g), mn_g8 = fmaxf(m_g8, mt_g8);
        float al_g = __expf(m_g - mn_g), al_g8 = __expf(m_g8 - mn_g8);
        m_g = mn_g; m_g8 = mn_g8;

        uint32_t ph01[8], ph23[8];
        float sum_g = 0.f, sum_g8 = 0.f;
        #pragma unroll
        for (int t = 0; t < 8; t++) {
            float p0 = __expf(s[t][0] - mn_g);
            float p1 = __expf(s[t][1] - mn_g);
            float p2 = __expf(s[t][2] - mn_g8);
            float p3 = __expf(s[t][3] - mn_g8);
            sum_g += p0 + p1; sum_g8 += p2 + p3;
            ph01[t] = h2u(__floats2half2_rn(p0, p1));
            ph23[t] = h2u(__floats2half2_rn(p2, p3));
        }
        sum_g  += __shfl_xor_sync(0xffffffffu, sum_g, 1);
        sum_g  += __shfl_xor_sync(0xffffffffu, sum_g, 2);
        sum_g8 += __shfl_xor_sync(0xffffffffu, sum_g8, 1);
        sum_g8 += __shfl_xor_sync(0xffffffffu, sum_g8, 2);
        l_g  = l_g  * al_g  + sum_g;
        l_g8 = l_g8 * al_g8 + sum_g8;

        #pragma unroll
        for (int t = 0; t < 8; t++) {
            o[t][0] *= al_g;  o[t][1] *= al_g;
            o[t][2] *= al_g8; o[t][3] *= al_g8;
        }

        #pragma unroll
        for (int u = 0; u < 4; u++) {
            uint32_t pah[4] = {ph01[2*u], ph23[2*u], ph01[2*u+1], ph23[2*u+1]};
            uint32_t ubase = u * 16 * LQ * 2;
            #pragma unroll
            for (int tdp = 0; tdp < 4; tdp++) {
                uint32_t bv4[4];
                ldsm_x4_t(bv4, uV + offV[tdp] + ubase);
                mma16816(o[2 * tdp],     pah, bv4);
                mma16816(o[2 * tdp + 1], pah, bv4 + 2);
            }
        }

        stg = stg + 1; if (stg >= 3) stg = 0;
    }

    float iv_g = 1.f / l_g, iv_g8 = 1.f / l_g8;
    size_t ob  = ((size_t)(b * S_ + q0 + wr + g)     * H_ + h) * HD_;
    size_t ob8 = ((size_t)(b * S_ + q0 + wr + g + 8) * H_ + h) * HD_;
    #pragma unroll
    for (int td = 0; td < 8; td++) {
        int d = 8 * td + 2 * qi;
        float v0 = o[td][0] * iv_g,  v1 = o[td][1] * iv_g;
        float v2 = o[td][2] * iv_g8, v3 = o[td][3] * iv_g8;
        __half2 hh = __floats2half2_rn(v0, v1);
        *(uint32_t*)&Oh_[ob + d] = h2u(hh);
        *(uint32_t*)&Ol_[ob + d] = h2u(__floats2half2_rn(
            v0 - __half2float(hh.x), v1 - __half2float(hh.y)));
        hh = __floats2half2_rn(v2, v3);
        *(uint32_t*)&Oh_[ob8 + d] = h2u(hh);
        *(uint32_t*)&Ol_[ob8 + d] = h2u(__floats2half2_rn(
            v2 - __half2float(hh.x), v3 - __half2float(hh.y)));
    }
}

// ---------------- launcher ----------------
extern "C" void kernel_launch(void* const* d_in, const int* in_sizes, int n_in,
                              void* d_out, int out_size)
{
    const float* x        = (const float*)d_in[0];
    const float* w_qkv    = (const float*)d_in[1];
    const float* b_qkv    = (const float*)d_in[2];
    const float* w_out    = (const float*)d_in[3];
    const float* b_out    = (const float*)d_in[4];
    const float* ln_scale = (const float*)d_in[5];
    const float* ln_bias  = (const float*)d_in[6];
    const float* q_scale  = (const float*)d_in[7];
    const float* k_scale  = (const float*)d_in[8];
    float* out = (float*)d_out;

    __half *xnh, *xnl, *wq, *wo, *ath, *atl, *qh, *ql, *kf, *vf;
    float *qkv;
    cudaGetSymbolAddress((void**)&xnh, g_xnh);
    cudaGetSymbolAddress((void**)&xnl, g_xnl);
    cudaGetSymbolAddress((void**)&wq,  g_wqT);
    cudaGetSymbolAddress((void**)&wo,  g_woT);
    cudaGetSymbolAddress((void**)&qkv, g_qkv);
    cudaGetSymbolAddress((void**)&qh,  g_qh);
    cudaGetSymbolAddress((void**)&ql,  g_ql);
    cudaGetSymbolAddress((void**)&kf,  g_kf);
    cudaGetSymbolAddress((void**)&vf,  g_vf);
    cudaGetSymbolAddress((void**)&ath, g_attnh);
    cudaGetSymbolAddress((void**)&atl, g_attnl);

    cudaFuncSetAttribute(gemm_mma,
        cudaFuncAttributeMaxDynamicSharedMemorySize, GEMM_SMEM);
    cudaFuncSetAttribute(flash_mma,
        cudaFuncAttributeMaxDynamicSharedMemorySize, FL_SMEM);

    // 1. input layernorm -> fp16 hi/lo
    ln_kernel<<<ROWS, 256>>>(x, ln_scale, ln_bias, xnh, xnl);

    // 2. weight transpose -> fp16
    convT_kernel<<<dim3((3 * D_) / 32, D_ / 32), dim3(32, 8)>>>(w_qkv, wq, D_, 3 * D_);
    convT_kernel<<<dim3(D_ / 32, D_ / 32), dim3(32, 8)>>>(w_out, wo, D_, D_);

    // 3. QKV GEMM (fp16 2-term, 4-stage)
    gemm_mma<<<dim3((3 * D_) / 128, ROWS / 128), 256, GEMM_SMEM>>>(
        xnh, xnl, wq, b_qkv, qkv, ROWS, 3 * D_, D_);

    // 4. split + per-head LN + RoPE
    split_rope<<<ROWS * H_ / 8, 256>>>(qkv, q_scale, k_scale, qh, ql, kf, vf);

    // 5. flash attention (fp16, single-P PV)
    flash_mma<<<dim3(S_ / 128, B_ * H_), 256, FL_SMEM>>>(
        qh, ql, kf, vf, ath, atl);

    // 6. output GEMM
    gemm_mma<<<dim3(D_ / 128, ROWS / 128), 256, GEMM_SMEM>>>(
        ath, atl, wo, b_out, out, ROWS, D_, D_);
}

// round 11
// speedup vs baseline: 8.6088x; 1.0210x over previous
#include <cuda_runtime.h>
#include <cuda_fp16.h>
#include <cstdint>
#include <math.h>

#define B_  2
#define S_  2048
#define D_  1024
#define H_  16
#define HD_ 64
#define EPS 1e-6f

#define ROWS (B_ * S_)          // 4096

// ---------------- scratch (device globals; no allocation) ----------------
__device__ __half g_xnh [ROWS * D_];
__device__ __half g_xnl [ROWS * D_];
__device__ __half g_wqT [3 * D_ * D_];   // [3072][1024] K-major fp16
__device__ __half g_woT [D_ * D_];       // [1024][1024] K-major
__device__ __half g_qh[B_ * H_ * S_ * HD_];
__device__ __half g_ql[B_ * H_ * S_ * HD_];
__device__ __half g_kf[B_ * H_ * S_ * HD_];
__device__ __half g_vf[B_ * H_ * S_ * HD_];
__device__ __half g_attnh[ROWS * D_];
__device__ __half g_attnl[ROWS * D_];

// ================= helpers =================
__device__ __forceinline__ uint32_t smem_to_u32(const void* p) {
    uint32_t a;
    asm("{ .reg .u64 t; cvta.to.shared.u64 t, %1; cvt.u32.u64 %0, t; }"
        : "=r"(a) : "l"(p));
    return a;
}
__device__ __forceinline__ void cp16(void* sp, const void* gp) {
    uint32_t s = smem_to_u32(sp);
    asm volatile("cp.async.cg.shared.global [%0], [%1], 16;" :: "r"(s), "l"(gp));
}
#define CP_COMMIT() asm volatile("cp.async.commit_group;" ::: "memory")
#define CP_WAIT2()  asm volatile("cp.async.wait_group 2;"  ::: "memory")
#define CP_WAIT1()  asm volatile("cp.async.wait_group 1;"  ::: "memory")
#define CP_WAIT0()  asm volatile("cp.async.wait_group 0;"  ::: "memory")

__device__ __forceinline__ void mma16816(float* c, const uint32_t* a, const uint32_t* b) {
    asm volatile(
        "mma.sync.aligned.m16n8k16.row.col.f32.f16.f16.f32 "
        "{%0,%1,%2,%3}, {%4,%5,%6,%7}, {%8,%9}, {%0,%1,%2,%3};"
        : "+f"(c[0]), "+f"(c[1]), "+f"(c[2]), "+f"(c[3])
        : "r"(a[0]), "r"(a[1]), "r"(a[2]), "r"(a[3]),
          "r"(b[0]), "r"(b[1]));
}
__device__ __forceinline__ void ldsm_x4(uint32_t* r, uint32_t saddr) {
    asm volatile("ldmatrix.sync.aligned.m8n8.x4.shared.b16 {%0,%1,%2,%3}, [%4];"
        : "=r"(r[0]), "=r"(r[1]), "=r"(r[2]), "=r"(r[3]) : "r"(saddr));
}
__device__ __forceinline__ void ldsm_x4_t(uint32_t* r, uint32_t saddr) {
    asm volatile("ldmatrix.sync.aligned.m8n8.x4.trans.shared.b16 {%0,%1,%2,%3}, [%4];"
        : "=r"(r[0]), "=r"(r[1]), "=r"(r[2]), "=r"(r[3]) : "r"(saddr));
}
__device__ __forceinline__ uint32_t h2u(__half2 v) { return *(uint32_t*)&v; }

// 64B-row swizzle
#define SW64(o) ((o) ^ (((o) >> 3) & 0x30))

// ---------------- block reduce (256 threads) ----------------
__device__ __forceinline__ float block_reduce_256(float v) {
    __shared__ float sh[8];
    #pragma unroll
    for (int o = 16; o; o >>= 1) v += __shfl_down_sync(0xffffffffu, v, o);
    if ((threadIdx.x & 31) == 0) sh[threadIdx.x >> 5] = v;
    __syncthreads();
    if (threadIdx.x == 0) {
        float t = 0.f;
        #pragma unroll
        for (int i = 0; i < 8; i++) t += sh[i];
        sh[0] = t;
    }
    __syncthreads();
    float r = sh[0];
    __syncthreads();
    return r;
}

// ---------------- kernel 1: input layernorm -> fp16 hi/lo ----------------
__global__ __launch_bounds__(256) void ln_kernel(
    const float* __restrict__ x, const float* __restrict__ scale,
    const float* __restrict__ bias,
    __half* __restrict__ oh, __half* __restrict__ ol)
{
    int row = blockIdx.x;
    const float4* xr = (const float4*)(x + (size_t)row * D_);
    float4 v = xr[threadIdx.x];

    float s = v.x + v.y + v.z + v.w;
    float tot = block_reduce_256(s);
    float mu = tot * (1.0f / D_);

    float dx = v.x - mu, dy = v.y - mu, dz = v.z - mu, dw = v.w - mu;
    float sq = dx*dx + dy*dy + dz*dz + dw*dw;
    float vtot = block_reduce_256(sq);
    float rstd = rsqrtf(vtot * (1.0f / D_) + EPS);

    float4 sc = ((const float4*)scale)[threadIdx.x];
    float4 bi = ((const float4*)bias)[threadIdx.x];
    float ov[4];
    ov[0] = dx * rstd * sc.x + bi.x;
    ov[1] = dy * rstd * sc.y + bi.y;
    ov[2] = dz * rstd * sc.z + bi.z;
    ov[3] = dw * rstd * sc.w + bi.w;

    size_t base = (size_t)row * D_ + threadIdx.x * 4;
    #pragma unroll
    for (int j = 0; j < 4; j += 2) {
        __half h0 = __float2half(ov[j]);
        __half h1 = __float2half(ov[j + 1]);
        __half2 hp; hp.x = h0; hp.y = h1;
        __half2 lp;
        lp.x = __float2half(ov[j]     - __half2float(h0));
        lp.y = __float2half(ov[j + 1] - __half2float(h1));
        *(__half2*)&oh[base + j] = hp;
        *(__half2*)&ol[base + j] = lp;
    }
}

// ---------------- weight transpose: W[K][N] -> T[N][K] fp16 ----------------
__global__ __launch_bounds__(256) void convT_kernel(
    const float* __restrict__ W, __half* __restrict__ Th, int K, int N)
{
    __shared__ float t[32][33];
    int tx = threadIdx.x, ty = threadIdx.y;   // 32 x 8
    int nb = blockIdx.x * 32, kb = blockIdx.y * 32;
    #pragma unroll
    for (int i = 0; i < 4; i++)
        t[ty + 8 * i][tx] = W[(size_t)(kb + ty + 8 * i) * N + nb + tx];
    __syncthreads();
    #pragma unroll
    for (int i = 0; i < 4; i++) {
        int n = nb + ty + 8 * i, k = kb + tx;
        Th[(size_t)n * K + k] = __float2half(t[tx][ty + 8 * i]);
    }
}

// ---------------- shared GEMM machinery ----------------
#define GT_BYTES 8192                        // one 128x32 fp16 tile
#define GSTAGE   (3 * GT_BYTES)              // Ah, Al, Bf
#define GEMM_SMEM (4 * GSTAGE)               // 98304

__device__ __forceinline__ void gemm_issue_stage(
    char* st,
    const __half* __restrict__ Ah, const __half* __restrict__ Al,
    const __half* __restrict__ Bf,
    int m0, int n0, int K, int kc, int tid)
{
    const __half* srcs[3] = {Ah, Al, Bf};
    const int row0s[3] = {m0, m0, n0};
    #pragma unroll
    for (int t = 0; t < 3; t++) {
        #pragma unroll
        for (int i = 0; i < 2; i++) {
            int u = tid + i * 256;
            int r = u >> 2, c = u & 3;
            uint32_t off = (uint32_t)(r * 64 + c * 16);
            cp16(st + t * GT_BYTES + SW64(off),
                 srcs[t] + (size_t)(row0s[t] + r) * K + kc + c * 8);
        }
    }
}

// mainloop as a macro-ish inline: fills acc[2][8][4]
#define GEMM_MAINLOOP(Ah, Al, Bf, m0, n0, Kv)                                  \
    do {                                                                       \
        const int NK = (Kv) >> 5;                                              \
        gemm_issue_stage(gsm,              Ah, Al, Bf, m0, n0, Kv, 0,  tid);   \
        CP_COMMIT();                                                           \
        gemm_issue_stage(gsm + GSTAGE,     Ah, Al, Bf, m0, n0, Kv, 32, tid);   \
        CP_COMMIT();                                                           \
        gemm_issue_stage(gsm + 2 * GSTAGE, Ah, Al, Bf, m0, n0, Kv, 64, tid);   \
        CP_COMMIT();                                                           \
        for (int i = 0; i < NK; i++) {                                         \
            int rem = NK - 1 - i;                                              \
            if (rem >= 2) { CP_WAIT2(); } else if (rem == 1) { CP_WAIT1(); }   \
            else { CP_WAIT0(); }                                               \
            __syncthreads();                                                   \
            if (i + 3 < NK) {                                                  \
                gemm_issue_stage(gsm + ((i + 3) & 3) * GSTAGE,                 \
                                 Ah, Al, Bf, m0, n0, Kv, (i + 3) * 32, tid);   \
                CP_COMMIT();                                                   \
            }                                                                  \
            uint32_t uS  = uG + (uint32_t)((i & 3) * GSTAGE);                  \
            uint32_t uAh = uS;                                                 \
            uint32_t uAl = uS + GT_BYTES;                                      \
            uint32_t uBf = uS + 2 * GT_BYTES;                                  \
            _Pragma("unroll")                                                  \
            for (int kk = 0; kk < 2; kk++) {                                   \
                uint32_t kb = kk * 32;                                         \
                uint32_t ah[2][4], al[2][4];                                   \
                _Pragma("unroll")                                              \
                for (int ii = 0; ii < 2; ii++) {                               \
                    ldsm_x4(ah[ii], uAh + SW64(baseA[ii] + kb));               \
                    ldsm_x4(al[ii], uAl + SW64(baseA[ii] + kb));               \
                }                                                              \
                _Pragma("unroll")                                              \
                for (int jp = 0; jp < 4; jp++) {                               \
                    uint32_t b4[4];                                            \
                    ldsm_x4(b4, uBf + SW64(baseB[jp] + kb));                   \
                    _Pragma("unroll")                                          \
                    for (int jj = 0; jj < 2; jj++) {                           \
                        int j = jp * 2 + jj;                                   \
                        _Pragma("unroll")                                      \
                        for (int ii = 0; ii < 2; ii++) {                       \
                            mma16816(acc[ii][j], ah[ii], b4 + 2 * jj);         \
                            mma16816(acc[ii][j], al[ii], b4 + 2 * jj);         \
                        }                                                      \
                    }                                                          \
                }                                                              \
            }                                                                  \
        }                                                                      \
    } while (0)

#define GEMM_PROLOG()                                                          \
    extern __shared__ char gsm[];                                              \
    int tid = threadIdx.x, lane = tid & 31, w = tid >> 5;                      \
    int g = lane >> 2, qi = lane & 3;                                          \
    int wm = w >> 1, wn = w & 1;                                               \
    int m0 = blockIdx.y * 128, n0 = blockIdx.x * 128;                          \
    uint32_t uG = smem_to_u32(gsm);                                            \
    uint32_t baseA[2], baseB[4];                                               \
    _Pragma("unroll")                                                          \
    for (int i = 0; i < 2; i++)                                                \
        baseA[i] = (uint32_t)((wm * 32 + i * 16 + (lane & 15)) * 64            \
                              + (lane >> 4) * 16);                             \
    _Pragma("unroll")                                                          \
    for (int jp = 0; jp < 4; jp++)                                             \
        baseB[jp] = (uint32_t)((wn * 64 + jp * 16 + (lane >> 4) * 8            \
                                + (lane & 7)) * 64 + ((lane >> 3) & 1) * 16);  \
    float acc[2][8][4];                                                        \
    _Pragma("unroll")                                                          \
    for (int i = 0; i < 2; i++)                                                \
        _Pragma("unroll")                                                      \
        for (int j = 0; j < 8; j++)                                            \
            _Pragma("unroll")                                                  \
            for (int e = 0; e < 4; e++) acc[i][j][e] = 0.f;

// ---------------- generic GEMM (used for out-proj): fp32 C + bias ----------------
__global__ __launch_bounds__(256, 2) void gemm_mma(
    const __half* __restrict__ Ah, const __half* __restrict__ Al,
    const __half* __restrict__ Bf,
    const float* __restrict__ bias, float* __restrict__ C, int M, int N, int K)
{
    GEMM_PROLOG();
    GEMM_MAINLOOP(Ah, Al, Bf, m0, n0, K);

    #pragma unroll
    for (int i = 0; i < 2; i++) {
        int r0 = m0 + wm * 32 + i * 16 + g;
        #pragma unroll
        for (int j = 0; j < 8; j++) {
            int col = n0 + wn * 64 + j * 8 + 2 * qi;
            float b0 = __ldg(&bias[col]), b1 = __ldg(&bias[col + 1]);
            float2 v0 = make_float2(acc[i][j][0] + b0, acc[i][j][1] + b1);
            float2 v1 = make_float2(acc[i][j][2] + b0, acc[i][j][3] + b1);
            *(float2*)&C[(size_t)r0 * N + col]       = v0;
            *(float2*)&C[(size_t)(r0 + 8) * N + col] = v1;
        }
    }
}

// ---------------- fused QKV GEMM: bias + per-head LN + RoPE epilogue ----------------
// N = 3072 fixed: region = n0>>10 (0=q,1=k,2=v); each warp's 64 cols = one head.
__global__ __launch_bounds__(256, 2) void gemm_qkv(
    const __half* __restrict__ Ah, const __half* __restrict__ Al,
    const __half* __restrict__ Bf,
    const float* __restrict__ bias,
    const float* __restrict__ q_scale, const float* __restrict__ k_scale,
    __half* __restrict__ qh, __half* __restrict__ ql,
    __half* __restrict__ kf, __half* __restrict__ vf)
{
    GEMM_PROLOG();
    GEMM_MAINLOOP(Ah, Al, Bf, m0, n0, D_);

    int region = n0 >> 10;                  // 0=q, 1=k, 2=v
    int hh = ((n0 & 1023) >> 6) + wn;       // head
    #pragma unroll
    for (int i = 0; i < 2; i++) {
        #pragma unroll
        for (int half = 0; half < 2; half++) {
            int r = m0 + wm * 32 + i * 16 + g + half * 8;
            int s = r & (S_ - 1), bb = r >> 11;
            size_t obase = (((size_t)(bb * H_ + hh)) * S_ + s) * HD_;

            float x[16];
            #pragma unroll
            for (int j = 0; j < 8; j++) {
                int col = n0 + wn * 64 + j * 8 + 2 * qi;
                x[2 * j]     = acc[i][j][half * 2]     + __ldg(&bias[col]);
                x[2 * j + 1] = acc[i][j][half * 2 + 1] + __ldg(&bias[col + 1]);
            }

            if (region == 2) {
                #pragma unroll
                for (int j = 0; j < 8; j++) {
                    int d = j * 8 + 2 * qi;
                    *(__half2*)&vf[obase + d] = __floats2half2_rn(x[2*j], x[2*j+1]);
                }
            } else {
                // per-head LN over 64 cols (4-lane group reduction)
                float sum = 0.f, sq = 0.f;
                #pragma unroll
                for (int t = 0; t < 16; t++) { sum += x[t]; sq += x[t] * x[t]; }
                sum += __shfl_xor_sync(0xffffffffu, sum, 1);
                sum += __shfl_xor_sync(0xffffffffu, sum, 2);
                sq  += __shfl_xor_sync(0xffffffffu, sq, 1);
                sq  += __shfl_xor_sync(0xffffffffu, sq, 2);
                float mu = sum * (1.0f / HD_);
                float rstd = rsqrtf(sq * (1.0f / HD_) - mu * mu + EPS);
                const float* sc = (region == 0) ? q_scale : k_scale;
                #pragma unroll
                for (int j = 0; j < 8; j++) {
                    int d = j * 8 + 2 * qi;
                    x[2 * j]     = (x[2 * j]     - mu) * rstd * __ldg(&sc[d]);
                    x[2 * j + 1] = (x[2 * j + 1] - mu) * rstd * __ldg(&sc[d + 1]);
                }
                // RoPE: pairs (d, d+32) = (j, j+4)
                #pragma unroll
                for (int j = 0; j < 4; j++) {
                    int d = j * 8 + 2 * qi;      // < 32
                    #pragma unroll
                    for (int c = 0; c < 2; c++) {
                        float inv = expf(-(float)(2 * (d + c)) * (1.0f / 64.0f)
                                         * 9.210340371976184f);
                        float sn, cs;
                        sincosf((float)s * inv, &sn, &cs);
                        float lo = x[2 * j + c], hi = x[2 * (j + 4) + c];
                        x[2 * j + c]       = lo * cs - hi * sn;
                        x[2 * (j + 4) + c] = hi * cs + lo * sn;
                    }
                }
                if (region == 0) {
                    #pragma unroll
                    for (int j = 0; j < 8; j++) {
                        int d = j * 8 + 2 * qi;
                        float v0 = x[2*j] * 0.125f, v1 = x[2*j+1] * 0.125f;
                        __half2 hp = __floats2half2_rn(v0, v1);
                        *(__half2*)&qh[obase + d] = hp;
                        *(__half2*)&ql[obase + d] = __floats2half2_rn(
                            v0 - __half2float(hp.x), v1 - __half2float(hp.y));
                    }
                } else {
                    #pragma unroll
                    for (int j = 0; j < 8; j++) {
                        int d = j * 8 + 2 * qi;
                        *(__half2*)&kf[obase + d] = __floats2half2_rn(x[2*j], x[2*j+1]);
                    }
                }
            }
        }
    }
}

// ---------------- flash attention: 3-stage KV ring, single sync/tile ----------------
#define LQ 72
#define KVT (64 * LQ)
#define KVSTG (2 * KVT)                    // K + V, one stage (elements)
#define FL_SMEM ((2 * 128 * LQ + 3 * KVSTG) * (int)sizeof(__half))

__device__ __forceinline__ void flash_issue_kv(
    __half* st,
    const __half* __restrict__ Kp, const __half* __restrict__ Vp,
    int j0, int tid)
{
    int r = tid >> 2, c = (tid & 3) * 16;
    size_t go = (size_t)(j0 + r) * HD_ + c;
    int so = r * LQ + c;
    cp16(st + so,           Kp + go);
    cp16(st + so + 8,       Kp + go + 8);
    cp16(st + KVT + so,     Vp + go);
    cp16(st + KVT + so + 8, Vp + go + 8);
}

__global__ __launch_bounds__(256, 2) void flash_mma(
    const __half* __restrict__ Qh_, const __half* __restrict__ Ql_,
    const __half* __restrict__ Kf_, const __half* __restrict__ Vf_,
    __half* __restrict__ Oh_, __half* __restrict__ Ol_)
{
    extern __shared__ __half fsm[];
    __half* sQh = fsm;                 // [128][LQ]
    __half* sQl = sQh + 128 * LQ;
    __half* sKV = sQl + 128 * LQ;      // 3 stages x {K, V}

    int tid = threadIdx.x, lane = tid & 31, wid = tid >> 5;
    int g = lane >> 2, qi = lane & 3;
    int bh = blockIdx.y;
    int b = bh >> 4, h = bh & 15;
    int q0 = blockIdx.x * 128;
    size_t hbase = (size_t)bh * S_ * HD_;
    const __half* Qhp = Qh_ + hbase;
    const __half* Qlp = Ql_ + hbase;
    const __half* Kfp = Kf_ + hbase;
    const __half* Vfp = Vf_ + hbase;

    int wr = wid * 16;
    uint32_t uQh = smem_to_u32(sQh), uQl = smem_to_u32(sQl);
    uint32_t uKV = smem_to_u32(sKV);

    uint32_t offQ = ((wr + (lane & 15)) * LQ + (lane >> 4) * 8) * 2;
    uint32_t offK[4], offV[4];
    #pragma unroll
    for (int tp = 0; tp < 4; tp++)
        offK[tp] = ((tp * 16 + (lane >> 4) * 8 + (lane & 7)) * LQ
                    + ((lane >> 3) & 1) * 8) * 2;
    #pragma unroll
    for (int tdp = 0; tdp < 4; tdp++)
        offV[tdp] = ((((lane >> 3) & 1) * 8 + (lane & 7)) * LQ
                     + (2 * tdp + (lane >> 4)) * 8) * 2;

    #pragma unroll
    for (int i = 0; i < 4; i++) {
        int u = tid + i * 256;
        int r = u >> 3, c = (u & 7) * 8;
        *(uint4*)&sQh[r * LQ + c] = *(const uint4*)&Qhp[(size_t)(q0 + r) * HD_ + c];
        *(uint4*)&sQl[r * LQ + c] = *(const uint4*)&Qlp[(size_t)(q0 + r) * HD_ + c];
    }
    flash_issue_kv(sKV,         Kfp, Vfp, 0,  tid);
    CP_COMMIT();
    flash_issue_kv(sKV + KVSTG, Kfp, Vfp, 64, tid);
    CP_COMMIT();

    float o[8][4];
    #pragma unroll
    for (int t = 0; t < 8; t++)
        #pragma unroll
        for (int e = 0; e < 4; e++) o[t][e] = 0.f;
    float m_g = -1e30f, m_g8 = -1e30f, l_g = 0.f, l_g8 = 0.f;

    const int NT = S_ / 64;
    int stg = 0;                       // stage index = kt % 3
    for (int kt = 0; kt < NT; kt++) {
        if (kt + 1 < NT) { CP_WAIT1(); } else { CP_WAIT0(); }
        __syncthreads();

        if (kt + 2 < NT) {
            int nst = stg + 2; if (nst >= 3) nst -= 3;
            flash_issue_kv(sKV + nst * KVSTG, Kfp, Vfp, (kt + 2) * 64, tid);
            CP_COMMIT();
        }

        uint32_t uS = uKV + (uint32_t)(stg * KVSTG) * 2;
        uint32_t uK = uS;
        uint32_t uV = uS + KVT * 2;

        float s[8][4];
        #pragma unroll
        for (int t = 0; t < 8; t++)
            #pragma unroll
            for (int e = 0; e < 4; e++) s[t][e] = 0.f;

        #pragma unroll
        for (int u = 0; u < 4; u++) {
            uint32_t ah[4], al[4];
            ldsm_x4(ah, uQh + offQ + u * 32);
            ldsm_x4(al, uQl + offQ + u * 32);
            #pragma unroll
            for (int tp = 0; tp < 4; tp++) {
                uint32_t b4[4];
                ldsm_x4(b4, uK + offK[tp] + u * 32);
                mma16816(s[2 * tp],     ah, b4);
                mma16816(s[2 * tp],     al, b4);
                mma16816(s[2 * tp + 1], ah, b4 + 2);
                mma16816(s[2 * tp + 1], al, b4 + 2);
            }
        }

        float mt_g = -1e30f, mt_g8 = -1e30f;
        #pragma unroll
        for (int t = 0; t < 8; t++) {
            mt_g  = fmaxf(mt_g,  fmaxf(s[t][0], s[t][1]));
            mt_g8 = fmaxf(mt_g8, fmaxf(s[t][2], s[t][3]));
        }
        mt_g  = fmaxf(mt_g,  __shfl_xor_sync(0xffffffffu, mt_g, 1));
        mt_g  = fmaxf(mt_g,  __shfl_xor_sync(0xffffffffu, mt_g, 2));
        mt_g8 = fmaxf(mt_g8, __shfl_xor_sync(0xffffffffu, mt_g8, 1));
        mt_g8 = fmaxf(mt_g8, __shfl_xor_sync(0xffffffffu, mt_g8, 2));
        float mn_g = fmaxf(m_g, mt_g), mn_g8 = fmaxf(m_g8, mt_g8);
        float al_g = __expf(m_g - mn_g), al_g8 = __expf(m_g8 - mn_g8);
        m_g = mn_g; m_g8 = mn_g8;

        uint32_t ph01[8], ph23[8];
        float sum_g = 0.f, sum_g8 = 0.f;
        #pragma unroll
        for (int t = 0; t < 8; t++) {
            float p0 = __expf(s[t][0] - mn_g);
            float p1 = __expf(s[t][1] - mn_g);
            float p2 = __expf(s[t][2] - mn_g8);
            float p3 = __expf(s[t][3] - mn_g8);
            sum_g += p0 + p1; sum_g8 += p2 + p3;
            ph01[t] = h2u(__floats2half2_rn(p0, p1));
            ph23[t] = h2u(__floats2half2_rn(p2, p3));
        }
        sum_g  += __shfl_xor_sync(0xffffffffu, sum_g, 1);
        sum_g  += __shfl_xor_sync(0xffffffffu, sum_g, 2);
        sum_g8 += __shfl_xor_sync(0xffffffffu, sum_g8, 1);
        sum_g8 += __shfl_xor_sync(0xffffffffu, sum_g8, 2);
        l_g  = l_g  * al_g  + sum_g;
        l_g8 = l_g8 * al_g8 + sum_g8;

        #pragma unroll
        for (int t = 0; t < 8; t++) {
            o[t][0] *= al_g;  o[t][1] *= al_g;
            o[t][2] *= al_g8; o[t][3] *= al_g8;
        }

        #pragma unroll
        for (int u = 0; u < 4; u++) {
            uint32_t pah[4] = {ph01[2*u], ph23[2*u], ph01[2*u+1], ph23[2*u+1]};
            uint32_t ubase = u * 16 * LQ * 2;
            #pragma unroll
            for (int tdp = 0; tdp < 4; tdp++) {
                uint32_t bv4[4];
                ldsm_x4_t(bv4, uV + offV[tdp] + ubase);
                mma16816(o[2 * tdp],     pah, bv4);
                mma16816(o[2 * tdp + 1], pah, bv4 + 2);
            }
        }

        stg = stg + 1; if (stg >= 3) stg = 0;
    }

    float iv_g = 1.f / l_g, iv_g8 = 1.f / l_g8;
    size_t ob  = ((size_t)(b * S_ + q0 + wr + g)     * H_ + h) * HD_;
    size_t ob8 = ((size_t)(b * S_ + q0 + wr + g + 8) * H_ + h) * HD_;
    #pragma unroll
    for (int td = 0; td < 8; td++) {
        int d = 8 * td + 2 * qi;
        float v0 = o[td][0] * iv_g,  v1 = o[td][1] * iv_g;
        float v2 = o[td][2] * iv_g8, v3 = o[td][3] * iv_g8;
        __half2 hh = __floats2half2_rn(v0, v1);
        *(uint32_t*)&Oh_[ob + d] = h2u(hh);
        *(uint32_t*)&Ol_[ob + d] = h2u(__floats2half2_rn(
            v0 - __half2float(hh.x), v1 - __half2float(hh.y)));
        hh = __floats2half2_rn(v2, v3);
        *(uint32_t*)&Oh_[ob8 + d] = h2u(hh);
        *(uint32_t*)&Ol_[ob8 + d] = h2u(__floats2half2_rn(
            v2 - __half2float(hh.x), v3 - __half2float(hh.y)));
    }
}

// ---------------- launcher ----------------
extern "C" void kernel_launch(void* const* d_in, const int* in_sizes, int n_in,
                              void* d_out, int out_size)
{
    const float* x        = (const float*)d_in[0];
    const float* w_qkv    = (const float*)d_in[1];
    const float* b_qkv    = (const float*)d_in[2];
    const float* w_out    = (const float*)d_in[3];
    const float* b_out    = (const float*)d_in[4];
    const float* ln_scale = (const float*)d_in[5];
    const float* ln_bias  = (const float*)d_in[6];
    const float* q_scale  = (const float*)d_in[7];
    const float* k_scale  = (const float*)d_in[8];
    float* out = (float*)d_out;

    __half *xnh, *xnl, *wq, *wo, *ath, *atl, *qh, *ql, *kf, *vf;
    cudaGetSymbolAddress((void**)&xnh, g_xnh);
    cudaGetSymbolAddress((void**)&xnl, g_xnl);
    cudaGetSymbolAddress((void**)&wq,  g_wqT);
    cudaGetSymbolAddress((void**)&wo,  g_woT);
    cudaGetSymbolAddress((void**)&qh,  g_qh);
    cudaGetSymbolAddress((void**)&ql,  g_ql);
    cudaGetSymbolAddress((void**)&kf,  g_kf);
    cudaGetSymbolAddress((void**)&vf,  g_vf);
    cudaGetSymbolAddress((void**)&ath, g_attnh);
    cudaGetSymbolAddress((void**)&atl, g_attnl);

    cudaFuncSetAttribute(gemm_mma,
        cudaFuncAttributeMaxDynamicSharedMemorySize, GEMM_SMEM);
    cudaFuncSetAttribute(gemm_qkv,
        cudaFuncAttributeMaxDynamicSharedMemorySize, GEMM_SMEM);
    cudaFuncSetAttribute(flash_mma,
        cudaFuncAttributeMaxDynamicSharedMemorySize, FL_SMEM);

    // 1. input layernorm -> fp16 hi/lo
    ln_kernel<<<ROWS, 256>>>(x, ln_scale, ln_bias, xnh, xnl);

    // 2. weight transpose -> fp16
    convT_kernel<<<dim3((3 * D_) / 32, D_ / 32), dim3(32, 8)>>>(w_qkv, wq, D_, 3 * D_);
    convT_kernel<<<dim3(D_ / 32, D_ / 32), dim3(32, 8)>>>(w_out, wo, D_, D_);

    // 3. fused QKV GEMM + per-head LN + RoPE + fp16 split
    gemm_qkv<<<dim3((3 * D_) / 128, ROWS / 128), 256, GEMM_SMEM>>>(
        xnh, xnl, wq, b_qkv, q_scale, k_scale, qh, ql, kf, vf);

    // 4. flash attention
    flash_mma<<<dim3(S_ / 128, B_ * H_), 256, FL_SMEM>>>(
        qh, ql, kf, vf, ath, atl);

    // 5. output GEMM
    gemm_mma<<<dim3(D_ / 128, ROWS / 128), 256, GEMM_SMEM>>>(
        ath, atl, wo, b_out, out, ROWS, D_, D_);
}

// round 12
// speedup vs baseline: 11.0262x; 1.2808x over previous
#include <cuda_runtime.h>
#include <cuda_fp16.h>
#include <cstdint>
#include <math.h>

#define B_  2
#define S_  2048
#define D_  1024
#define H_  16
#define HD_ 64
#define EPS 1e-6f

#define ROWS (B_ * S_)          // 4096

// ---------------- scratch (device globals; no allocation) ----------------
__device__ __half g_xn  [ROWS * D_];
__device__ __half g_wqT [3 * D_ * D_];   // [3072][1024] K-major fp16
__device__ __half g_woT [D_ * D_];       // [1024][1024] K-major
__device__ __half g_qh[B_ * H_ * S_ * HD_];
__device__ __half g_ql[B_ * H_ * S_ * HD_];
__device__ __half g_kf[B_ * H_ * S_ * HD_];
__device__ __half g_vf[B_ * H_ * S_ * HD_];
__device__ __half g_attn[ROWS * D_];

// ================= helpers =================
__device__ __forceinline__ uint32_t smem_to_u32(const void* p) {
    uint32_t a;
    asm("{ .reg .u64 t; cvta.to.shared.u64 t, %1; cvt.u32.u64 %0, t; }"
        : "=r"(a) : "l"(p));
    return a;
}
__device__ __forceinline__ void cp16(void* sp, const void* gp) {
    uint32_t s = smem_to_u32(sp);
    asm volatile("cp.async.cg.shared.global [%0], [%1], 16;" :: "r"(s), "l"(gp));
}
#define CP_COMMIT() asm volatile("cp.async.commit_group;" ::: "memory")
#define CP_WAIT2()  asm volatile("cp.async.wait_group 2;"  ::: "memory")
#define CP_WAIT1()  asm volatile("cp.async.wait_group 1;"  ::: "memory")
#define CP_WAIT0()  asm volatile("cp.async.wait_group 0;"  ::: "memory")

__device__ __forceinline__ void mma16816(float* c, const uint32_t* a, const uint32_t* b) {
    asm volatile(
        "mma.sync.aligned.m16n8k16.row.col.f32.f16.f16.f32 "
        "{%0,%1,%2,%3}, {%4,%5,%6,%7}, {%8,%9}, {%0,%1,%2,%3};"
        : "+f"(c[0]), "+f"(c[1]), "+f"(c[2]), "+f"(c[3])
        : "r"(a[0]), "r"(a[1]), "r"(a[2]), "r"(a[3]),
          "r"(b[0]), "r"(b[1]));
}
__device__ __forceinline__ void ldsm_x4(uint32_t* r, uint32_t saddr) {
    asm volatile("ldmatrix.sync.aligned.m8n8.x4.shared.b16 {%0,%1,%2,%3}, [%4];"
        : "=r"(r[0]), "=r"(r[1]), "=r"(r[2]), "=r"(r[3]) : "r"(saddr));
}
__device__ __forceinline__ void ldsm_x4_t(uint32_t* r, uint32_t saddr) {
    asm volatile("ldmatrix.sync.aligned.m8n8.x4.trans.shared.b16 {%0,%1,%2,%3}, [%4];"
        : "=r"(r[0]), "=r"(r[1]), "=r"(r[2]), "=r"(r[3]) : "r"(saddr));
}
__device__ __forceinline__ uint32_t h2u(__half2 v) { return *(uint32_t*)&v; }

// 64B-row swizzle
#define SW64(o) ((o) ^ (((o) >> 3) & 0x30))

// ---------------- block reduce (256 threads) ----------------
__device__ __forceinline__ float block_reduce_256(float v) {
    __shared__ float sh[8];
    #pragma unroll
    for (int o = 16; o; o >>= 1) v += __shfl_down_sync(0xffffffffu, v, o);
    if ((threadIdx.x & 31) == 0) sh[threadIdx.x >> 5] = v;
    __syncthreads();
    if (threadIdx.x == 0) {
        float t = 0.f;
        #pragma unroll
        for (int i = 0; i < 8; i++) t += sh[i];
        sh[0] = t;
    }
    __syncthreads();
    float r = sh[0];
    __syncthreads();
    return r;
}

// ---------------- kernel 1: input layernorm -> fp16 ----------------
__global__ __launch_bounds__(256) void ln_kernel(
    const float* __restrict__ x, const float* __restrict__ scale,
    const float* __restrict__ bias, __half* __restrict__ oh)
{
    int row = blockIdx.x;
    const float4* xr = (const float4*)(x + (size_t)row * D_);
    float4 v = xr[threadIdx.x];

    float s = v.x + v.y + v.z + v.w;
    float tot = block_reduce_256(s);
    float mu = tot * (1.0f / D_);

    float dx = v.x - mu, dy = v.y - mu, dz = v.z - mu, dw = v.w - mu;
    float sq = dx*dx + dy*dy + dz*dz + dw*dw;
    float vtot = block_reduce_256(sq);
    float rstd = rsqrtf(vtot * (1.0f / D_) + EPS);

    float4 sc = ((const float4*)scale)[threadIdx.x];
    float4 bi = ((const float4*)bias)[threadIdx.x];
    float ov[4];
    ov[0] = dx * rstd * sc.x + bi.x;
    ov[1] = dy * rstd * sc.y + bi.y;
    ov[2] = dz * rstd * sc.z + bi.z;
    ov[3] = dw * rstd * sc.w + bi.w;

    size_t base = (size_t)row * D_ + threadIdx.x * 4;
    *(__half2*)&oh[base + 0] = __floats2half2_rn(ov[0], ov[1]);
    *(__half2*)&oh[base + 2] = __floats2half2_rn(ov[2], ov[3]);
}

// ---------------- weight transpose: W[K][N] -> T[N][K] fp16 ----------------
__global__ __launch_bounds__(256) void convT_kernel(
    const float* __restrict__ W, __half* __restrict__ Th, int K, int N)
{
    __shared__ float t[32][33];
    int tx = threadIdx.x, ty = threadIdx.y;   // 32 x 8
    int nb = blockIdx.x * 32, kb = blockIdx.y * 32;
    #pragma unroll
    for (int i = 0; i < 4; i++)
        t[ty + 8 * i][tx] = W[(size_t)(kb + ty + 8 * i) * N + nb + tx];
    __syncthreads();
    #pragma unroll
    for (int i = 0; i < 4; i++) {
        int n = nb + ty + 8 * i, k = kb + tx;
        Th[(size_t)n * K + k] = __float2half(t[tx][ty + 8 * i]);
    }
}

// ---------------- shared GEMM machinery (single-A fp16) ----------------
#define GT_BYTES 8192                        // one 128x32 fp16 tile
#define GSTAGE   (2 * GT_BYTES)              // Af, Bf
#define GEMM_SMEM (4 * GSTAGE)               // 65536

__device__ __forceinline__ void gemm_issue_stage(
    char* st,
    const __half* __restrict__ Af, const __half* __restrict__ Bf,
    int m0, int n0, int K, int kc, int tid)
{
    const __half* srcs[2] = {Af, Bf};
    const int row0s[2] = {m0, n0};
    #pragma unroll
    for (int t = 0; t < 2; t++) {
        #pragma unroll
        for (int i = 0; i < 2; i++) {
            int u = tid + i * 256;
            int r = u >> 2, c = u & 3;
            uint32_t off = (uint32_t)(r * 64 + c * 16);
            cp16(st + t * GT_BYTES + SW64(off),
                 srcs[t] + (size_t)(row0s[t] + r) * K + kc + c * 8);
        }
    }
}

#define GEMM_MAINLOOP(Af, Bf, m0, n0, Kv)                                      \
    do {                                                                       \
        const int NK = (Kv) >> 5;                                              \
        gemm_issue_stage(gsm,              Af, Bf, m0, n0, Kv, 0,  tid);       \
        CP_COMMIT();                                                           \
        gemm_issue_stage(gsm + GSTAGE,     Af, Bf, m0, n0, Kv, 32, tid);       \
        CP_COMMIT();                                                           \
        gemm_issue_stage(gsm + 2 * GSTAGE, Af, Bf, m0, n0, Kv, 64, tid);       \
        CP_COMMIT();                                                           \
        for (int i = 0; i < NK; i++) {                                         \
            int rem = NK - 1 - i;                                              \
            if (rem >= 2) { CP_WAIT2(); } else if (rem == 1) { CP_WAIT1(); }   \
            else { CP_WAIT0(); }                                               \
            __syncthreads();                                                   \
            if (i + 3 < NK) {                                                  \
                gemm_issue_stage(gsm + ((i + 3) & 3) * GSTAGE,                 \
                                 Af, Bf, m0, n0, Kv, (i + 3) * 32, tid);       \
                CP_COMMIT();                                                   \
            }                                                                  \
            uint32_t uS  = uG + (uint32_t)((i & 3) * GSTAGE);                  \
            uint32_t uAf = uS;                                                 \
            uint32_t uBf = uS + GT_BYTES;                                      \
            _Pragma("unroll")                                                  \
            for (int kk = 0; kk < 2; kk++) {                                   \
                uint32_t kb = kk * 32;                                         \
                uint32_t a4[2][4];                                             \
                _Pragma("unroll")                                              \
                for (int ii = 0; ii < 2; ii++)                                 \
                    ldsm_x4(a4[ii], uAf + SW64(baseA[ii] + kb));               \
                _Pragma("unroll")                                              \
                for (int jp = 0; jp < 4; jp++) {                               \
                    uint32_t b4[4];                                            \
                    ldsm_x4(b4, uBf + SW64(baseB[jp] + kb));                   \
                    _Pragma("unroll")                                          \
                    for (int jj = 0; jj < 2; jj++) {                           \
                        int j = jp * 2 + jj;                                   \
                        _Pragma("unroll")                                      \
                        for (int ii = 0; ii < 2; ii++)                         \
                            mma16816(acc[ii][j], a4[ii], b4 + 2 * jj);         \
                    }                                                          \
                }                                                              \
            }                                                                  \
        }                                                                      \
    } while (0)

#define GEMM_PROLOG()                                                          \
    extern __shared__ char gsm[];                                              \
    int tid = threadIdx.x, lane = tid & 31, w = tid >> 5;                      \
    int g = lane >> 2, qi = lane & 3;                                          \
    int wm = w >> 1, wn = w & 1;                                               \
    int m0 = blockIdx.y * 128, n0 = blockIdx.x * 128;                          \
    uint32_t uG = smem_to_u32(gsm);                                            \
    uint32_t baseA[2], baseB[4];                                               \
    _Pragma("unroll")                                                          \
    for (int i = 0; i < 2; i++)                                                \
        baseA[i] = (uint32_t)((wm * 32 + i * 16 + (lane & 15)) * 64            \
                              + (lane >> 4) * 16);                             \
    _Pragma("unroll")                                                          \
    for (int jp = 0; jp < 4; jp++)                                             \
        baseB[jp] = (uint32_t)((wn * 64 + jp * 16 + (lane >> 4) * 8            \
                                + (lane & 7)) * 64 + ((lane >> 3) & 1) * 16);  \
    float acc[2][8][4];                                                        \
    _Pragma("unroll")                                                          \
    for (int i = 0; i < 2; i++)                                                \
        _Pragma("unroll")                                                      \
        for (int j = 0; j < 8; j++)                                            \
            _Pragma("unroll")                                                  \
            for (int e = 0; e < 4; e++) acc[i][j][e] = 0.f;

// ---------------- generic GEMM (out-proj): fp32 C + bias ----------------
__global__ __launch_bounds__(256, 2) void gemm_mma(
    const __half* __restrict__ Af, const __half* __restrict__ Bf,
    const float* __restrict__ bias, float* __restrict__ C, int M, int N, int K)
{
    GEMM_PROLOG();
    GEMM_MAINLOOP(Af, Bf, m0, n0, K);

    #pragma unroll
    for (int i = 0; i < 2; i++) {
        int r0 = m0 + wm * 32 + i * 16 + g;
        #pragma unroll
        for (int j = 0; j < 8; j++) {
            int col = n0 + wn * 64 + j * 8 + 2 * qi;
            float b0 = __ldg(&bias[col]), b1 = __ldg(&bias[col + 1]);
            float2 v0 = make_float2(acc[i][j][0] + b0, acc[i][j][1] + b1);
            float2 v1 = make_float2(acc[i][j][2] + b0, acc[i][j][3] + b1);
            *(float2*)&C[(size_t)r0 * N + col]       = v0;
            *(float2*)&C[(size_t)(r0 + 8) * N + col] = v1;
        }
    }
}

// ---------------- fused QKV GEMM: bias + per-head LN + RoPE epilogue ----------------
__global__ __launch_bounds__(256, 2) void gemm_qkv(
    const __half* __restrict__ Af, const __half* __restrict__ Bf,
    const float* __restrict__ bias,
    const float* __restrict__ q_scale, const float* __restrict__ k_scale,
    __half* __restrict__ qh, __half* __restrict__ ql,
    __half* __restrict__ kf, __half* __restrict__ vf)
{
    GEMM_PROLOG();
    GEMM_MAINLOOP(Af, Bf, m0, n0, D_);

    int region = n0 >> 10;                  // 0=q, 1=k, 2=v
    int hh = ((n0 & 1023) >> 6) + wn;       // head
    #pragma unroll
    for (int i = 0; i < 2; i++) {
        #pragma unroll
        for (int half = 0; half < 2; half++) {
            int r = m0 + wm * 32 + i * 16 + g + half * 8;
            int s = r & (S_ - 1), bb = r >> 11;
            size_t obase = (((size_t)(bb * H_ + hh)) * S_ + s) * HD_;

            float x[16];
            #pragma unroll
            for (int j = 0; j < 8; j++) {
                int col = n0 + wn * 64 + j * 8 + 2 * qi;
                x[2 * j]     = acc[i][j][half * 2]     + __ldg(&bias[col]);
                x[2 * j + 1] = acc[i][j][half * 2 + 1] + __ldg(&bias[col + 1]);
            }

            if (region == 2) {
                #pragma unroll
                for (int j = 0; j < 8; j++) {
                    int d = j * 8 + 2 * qi;
                    *(__half2*)&vf[obase + d] = __floats2half2_rn(x[2*j], x[2*j+1]);
                }
            } else {
                float sum = 0.f, sq = 0.f;
                #pragma unroll
                for (int t = 0; t < 16; t++) { sum += x[t]; sq += x[t] * x[t]; }
                sum += __shfl_xor_sync(0xffffffffu, sum, 1);
                sum += __shfl_xor_sync(0xffffffffu, sum, 2);
                sq  += __shfl_xor_sync(0xffffffffu, sq, 1);
                sq  += __shfl_xor_sync(0xffffffffu, sq, 2);
                float mu = sum * (1.0f / HD_);
                float rstd = rsqrtf(sq * (1.0f / HD_) - mu * mu + EPS);
                const float* sc = (region == 0) ? q_scale : k_scale;
                #pragma unroll
                for (int j = 0; j < 8; j++) {
                    int d = j * 8 + 2 * qi;
                    x[2 * j]     = (x[2 * j]     - mu) * rstd * __ldg(&sc[d]);
                    x[2 * j + 1] = (x[2 * j + 1] - mu) * rstd * __ldg(&sc[d + 1]);
                }
                #pragma unroll
                for (int j = 0; j < 4; j++) {
                    int d = j * 8 + 2 * qi;      // < 32
                    #pragma unroll
                    for (int c = 0; c < 2; c++) {
                        float inv = expf(-(float)(2 * (d + c)) * (1.0f / 64.0f)
                                         * 9.210340371976184f);
                        float sn, cs;
                        sincosf((float)s * inv, &sn, &cs);
                        float lo = x[2 * j + c], hi = x[2 * (j + 4) + c];
                        x[2 * j + c]       = lo * cs - hi * sn;
                        x[2 * (j + 4) + c] = hi * cs + lo * sn;
                    }
                }
                if (region == 0) {
                    #pragma unroll
                    for (int j = 0; j < 8; j++) {
                        int d = j * 8 + 2 * qi;
                        float v0 = x[2*j] * 0.125f, v1 = x[2*j+1] * 0.125f;
                        __half2 hp = __floats2half2_rn(v0, v1);
                        *(__half2*)&qh[obase + d] = hp;
                        *(__half2*)&ql[obase + d] = __floats2half2_rn(
                            v0 - __half2float(hp.x), v1 - __half2float(hp.y));
                    }
                } else {
                    #pragma unroll
                    for (int j = 0; j < 8; j++) {
                        int d = j * 8 + 2 * qi;
                        *(__half2*)&kf[obase + d] = __floats2half2_rn(x[2*j], x[2*j+1]);
                    }
                }
            }
        }
    }
}

// ---------------- flash attention: 3-stage KV ring, single sync/tile ----------------
#define LQ 72
#define KVT (64 * LQ)
#define KVSTG (2 * KVT)                    // K + V, one stage (elements)
#define FL_SMEM ((2 * 128 * LQ + 3 * KVSTG) * (int)sizeof(__half))

__device__ __forceinline__ void flash_issue_kv(
    __half* st,
    const __half* __restrict__ Kp, const __half* __restrict__ Vp,
    int j0, int tid)
{
    int r = tid >> 2, c = (tid & 3) * 16;
    size_t go = (size_t)(j0 + r) * HD_ + c;
    int so = r * LQ + c;
    cp16(st + so,           Kp + go);
    cp16(st + so + 8,       Kp + go + 8);
    cp16(st + KVT + so,     Vp + go);
    cp16(st + KVT + so + 8, Vp + go + 8);
}

__global__ __launch_bounds__(256, 2) void flash_mma(
    const __half* __restrict__ Qh_, const __half* __restrict__ Ql_,
    const __half* __restrict__ Kf_, const __half* __restrict__ Vf_,
    __half* __restrict__ O_)
{
    extern __shared__ __half fsm[];
    __half* sQh = fsm;                 // [128][LQ]
    __half* sQl = sQh + 128 * LQ;
    __half* sKV = sQl + 128 * LQ;      // 3 stages x {K, V}

    int tid = threadIdx.x, lane = tid & 31, wid = tid >> 5;
    int g = lane >> 2, qi = lane & 3;
    int bh = blockIdx.y;
    int b = bh >> 4, h = bh & 15;
    int q0 = blockIdx.x * 128;
    size_t hbase = (size_t)bh * S_ * HD_;
    const __half* Qhp = Qh_ + hbase;
    const __half* Qlp = Ql_ + hbase;
    const __half* Kfp = Kf_ + hbase;
    const __half* Vfp = Vf_ + hbase;

    int wr = wid * 16;
    uint32_t uQh = smem_to_u32(sQh), uQl = smem_to_u32(sQl);
    uint32_t uKV = smem_to_u32(sKV);

    uint32_t offQ = ((wr + (lane & 15)) * LQ + (lane >> 4) * 8) * 2;
    uint32_t offK[4], offV[4];
    #pragma unroll
    for (int tp = 0; tp < 4; tp++)
        offK[tp] = ((tp * 16 + (lane >> 4) * 8 + (lane & 7)) * LQ
                    + ((lane >> 3) & 1) * 8) * 2;
    #pragma unroll
    for (int tdp = 0; tdp < 4; tdp++)
        offV[tdp] = ((((lane >> 3) & 1) * 8 + (lane & 7)) * LQ
                     + (2 * tdp + (lane >> 4)) * 8) * 2;

    #pragma unroll
    for (int i = 0; i < 4; i++) {
        int u = tid + i * 256;
        int r = u >> 3, c = (u & 7) * 8;
        *(uint4*)&sQh[r * LQ + c] = *(const uint4*)&Qhp[(size_t)(q0 + r) * HD_ + c];
        *(uint4*)&sQl[r * LQ + c] = *(const uint4*)&Qlp[(size_t)(q0 + r) * HD_ + c];
    }
    flash_issue_kv(sKV,         Kfp, Vfp, 0,  tid);
    CP_COMMIT();
    flash_issue_kv(sKV + KVSTG, Kfp, Vfp, 64, tid);
    CP_COMMIT();

    float o[8][4];
    #pragma unroll
    for (int t = 0; t < 8; t++)
        #pragma unroll
        for (int e = 0; e < 4; e++) o[t][e] = 0.f;
    float m_g = -1e30f, m_g8 = -1e30f, l_g = 0.f, l_g8 = 0.f;

    const int NT = S_ / 64;
    int stg = 0;
    for (int kt = 0; kt < NT; kt++) {
        if (kt + 1 < NT) { CP_WAIT1(); } else { CP_WAIT0(); }
        __syncthreads();

        if (kt + 2 < NT) {
            int nst = stg + 2; if (nst >= 3) nst -= 3;
            flash_issue_kv(sKV + nst * KVSTG, Kfp, Vfp, (kt + 2) * 64, tid);
            CP_COMMIT();
        }

        uint32_t uS = uKV + (uint32_t)(stg * KVSTG) * 2;
        uint32_t uK = uS;
        uint32_t uV = uS + KVT * 2;

        float s[8][4];
        #pragma unroll
        for (int t = 0; t < 8; t++)
            #pragma unroll
            for (int e = 0; e < 4; e++) s[t][e] = 0.f;

        #pragma unroll
        for (int u = 0; u < 4; u++) {
            uint32_t ah[4], al[4];
            ldsm_x4(ah, uQh + offQ + u * 32);
            ldsm_x4(al, uQl + offQ + u * 32);
            #pragma unroll
            for (int tp = 0; tp < 4; tp++) {
                uint32_t b4[4];
                ldsm_x4(b4, uK + offK[tp] + u * 32);
                mma16816(s[2 * tp],     ah, b4);
                mma16816(s[2 * tp],     al, b4);
                mma16816(s[2 * tp + 1], ah, b4 + 2);
                mma16816(s[2 * tp + 1], al, b4 + 2);
            }
        }

        float mt_g = -1e30f, mt_g8 = -1e30f;
        #pragma unroll
        for (int t = 0; t < 8; t++) {
            mt_g  = fmaxf(mt_g,  fmaxf(s[t][0], s[t][1]));
            mt_g8 = fmaxf(mt_g8, fmaxf(s[t][2], s[t][3]));
        }
        mt_g  = fmaxf(mt_g,  __shfl_xor_sync(0xffffffffu, mt_g, 1));
        mt_g  = fmaxf(mt_g,  __shfl_xor_sync(0xffffffffu, mt_g, 2));
        mt_g8 = fmaxf(mt_g8, __shfl_xor_sync(0xffffffffu, mt_g8, 1));
        mt_g8 = fmaxf(mt_g8, __shfl_xor_sync(0xffffffffu, mt_g8, 2));
        float mn_g = fmaxf(m_g, mt_g), mn_g8 = fmaxf(m_g8, mt_g8);
        float al_g = __expf(m_g - mn_g), al_g8 = __expf(m_g8 - mn_g8);
        m_g = mn_g; m_g8 = mn_g8;

        uint32_t ph01[8], ph23[8];
        float sum_g = 0.f, sum_g8 = 0.f;
        #pragma unroll
        for (int t = 0; t < 8; t++) {
            float p0 = __expf(s[t][0] - mn_g);
            float p1 = __expf(s[t][1] - mn_g);
            float p2 = __expf(s[t][2] - mn_g8);
            float p3 = __expf(s[t][3] - mn_g8);
            sum_g += p0 + p1; sum_g8 += p2 + p3;
            ph01[t] = h2u(__floats2half2_rn(p0, p1));
            ph23[t] = h2u(__floats2half2_rn(p2, p3));
        }
        sum_g  += __shfl_xor_sync(0xffffffffu, sum_g, 1);
        sum_g  += __shfl_xor_sync(0xffffffffu, sum_g, 2);
        sum_g8 += __shfl_xor_sync(0xffffffffu, sum_g8, 1);
        sum_g8 += __shfl_xor_sync(0xffffffffu, sum_g8, 2);
        l_g  = l_g  * al_g  + sum_g;
        l_g8 = l_g8 * al_g8 + sum_g8;

        #pragma unroll
        for (int t = 0; t < 8; t++) {
            o[t][0] *= al_g;  o[t][1] *= al_g;
            o[t][2] *= al_g8; o[t][3] *= al_g8;
        }

        #pragma unroll
        for (int u = 0; u < 4; u++) {
            uint32_t pah[4] = {ph01[2*u], ph23[2*u], ph01[2*u+1], ph23[2*u+1]};
            uint32_t ubase = u * 16 * LQ * 2;
            #pragma unroll
            for (int tdp = 0; tdp < 4; tdp++) {
                uint32_t bv4[4];
                ldsm_x4_t(bv4, uV + offV[tdp] + ubase);
                mma16816(o[2 * tdp],     pah, bv4);
                mma16816(o[2 * tdp + 1], pah, bv4 + 2);
            }
        }

        stg = stg + 1; if (stg >= 3) stg = 0;
    }

    float iv_g = 1.f / l_g, iv_g8 = 1.f / l_g8;
    size_t ob  = ((size_t)(b * S_ + q0 + wr + g)     * H_ + h) * HD_;
    size_t ob8 = ((size_t)(b * S_ + q0 + wr + g + 8) * H_ + h) * HD_;
    #pragma unroll
    for (int td = 0; td < 8; td++) {
        int d = 8 * td + 2 * qi;
        *(uint32_t*)&O_[ob + d]  = h2u(__floats2half2_rn(o[td][0] * iv_g,
                                                         o[td][1] * iv_g));
        *(uint32_t*)&O_[ob8 + d] = h2u(__floats2half2_rn(o[td][2] * iv_g8,
                                                         o[td][3] * iv_g8));
    }
}

// ---------------- launcher ----------------
extern "C" void kernel_launch(void* const* d_in, const int* in_sizes, int n_in,
                              void* d_out, int out_size)
{
    const float* x        = (const float*)d_in[0];
    const float* w_qkv    = (const float*)d_in[1];
    const float* b_qkv    = (const float*)d_in[2];
    const float* w_out    = (const float*)d_in[3];
    const float* b_out    = (const float*)d_in[4];
    const float* ln_scale = (const float*)d_in[5];
    const float* ln_bias  = (const float*)d_in[6];
    const float* q_scale  = (const float*)d_in[7];
    const float* k_scale  = (const float*)d_in[8];
    float* out = (float*)d_out;

    __half *xn, *wq, *wo, *attn, *qh, *ql, *kf, *vf;
    cudaGetSymbolAddress((void**)&xn,   g_xn);
    cudaGetSymbolAddress((void**)&wq,   g_wqT);
    cudaGetSymbolAddress((void**)&wo,   g_woT);
    cudaGetSymbolAddress((void**)&qh,   g_qh);
    cudaGetSymbolAddress((void**)&ql,   g_ql);
    cudaGetSymbolAddress((void**)&kf,   g_kf);
    cudaGetSymbolAddress((void**)&vf,   g_vf);
    cudaGetSymbolAddress((void**)&attn, g_attn);

    cudaFuncSetAttribute(gemm_mma,
        cudaFuncAttributeMaxDynamicSharedMemorySize, GEMM_SMEM);
    cudaFuncSetAttribute(gemm_qkv,
        cudaFuncAttributeMaxDynamicSharedMemorySize, GEMM_SMEM);
    cudaFuncSetAttribute(flash_mma,
        cudaFuncAttributeMaxDynamicSharedMemorySize, FL_SMEM);

    // 1. input layernorm -> fp16
    ln_kernel<<<ROWS, 256>>>(x, ln_scale, ln_bias, xn);

    // 2. weight transpose -> fp16
    convT_kernel<<<dim3((3 * D_) / 32, D_ / 32), dim3(32, 8)>>>(w_qkv, wq, D_, 3 * D_);
    convT_kernel<<<dim3(D_ / 32, D_ / 32), dim3(32, 8)>>>(w_out, wo, D_, D_);

    // 3. fused QKV GEMM + per-head LN + RoPE (single-A fp16)
    gemm_qkv<<<dim3((3 * D_) / 128, ROWS / 128), 256, GEMM_SMEM>>>(
        xn, wq, b_qkv, q_scale, k_scale, qh, ql, kf, vf);

    // 4. flash attention (Q hi/lo, K/V/P single fp16)
    flash_mma<<<dim3(S_ / 128, B_ * H_), 256, FL_SMEM>>>(
        qh, ql, kf, vf, attn);

    // 5. output GEMM (single-A fp16)
    gemm_mma<<<dim3(D_ / 128, ROWS / 128), 256, GEMM_SMEM>>>(
        attn, wo, b_out, out, ROWS, D_, D_);
}

// round 13
// speedup vs baseline: 12.3711x; 1.1220x over previous
#include <cuda_runtime.h>
#include <cuda_fp16.h>
#include <cstdint>
#include <math.h>

#define B_  2
#define S_  2048
#define D_  1024
#define H_  16
#define HD_ 64
#define EPS 1e-6f

#define ROWS (B_ * S_)          // 4096

// ---------------- scratch (device globals; no allocation) ----------------
__device__ __half g_xn  [ROWS * D_];
__device__ __half g_wqT [3 * D_ * D_];   // [3072][1024] K-major fp16
__device__ __half g_woT [D_ * D_];       // [1024][1024] K-major
__device__ __half g_qf[B_ * H_ * S_ * HD_];
__device__ __half g_kf[B_ * H_ * S_ * HD_];
__device__ __half g_vf[B_ * H_ * S_ * HD_];
__device__ __half g_attn[ROWS * D_];

// ================= helpers =================
__device__ __forceinline__ uint32_t smem_to_u32(const void* p) {
    uint32_t a;
    asm("{ .reg .u64 t; cvta.to.shared.u64 t, %1; cvt.u32.u64 %0, t; }"
        : "=r"(a) : "l"(p));
    return a;
}
__device__ __forceinline__ void cp16(void* sp, const void* gp) {
    uint32_t s = smem_to_u32(sp);
    asm volatile("cp.async.cg.shared.global [%0], [%1], 16;" :: "r"(s), "l"(gp));
}
#define CP_COMMIT() asm volatile("cp.async.commit_group;" ::: "memory")
#define CP_WAIT2()  asm volatile("cp.async.wait_group 2;"  ::: "memory")
#define CP_WAIT1()  asm volatile("cp.async.wait_group 1;"  ::: "memory")
#define CP_WAIT0()  asm volatile("cp.async.wait_group 0;"  ::: "memory")

__device__ __forceinline__ void mma16816(float* c, const uint32_t* a, const uint32_t* b) {
    asm volatile(
        "mma.sync.aligned.m16n8k16.row.col.f32.f16.f16.f32 "
        "{%0,%1,%2,%3}, {%4,%5,%6,%7}, {%8,%9}, {%0,%1,%2,%3};"
        : "+f"(c[0]), "+f"(c[1]), "+f"(c[2]), "+f"(c[3])
        : "r"(a[0]), "r"(a[1]), "r"(a[2]), "r"(a[3]),
          "r"(b[0]), "r"(b[1]));
}
__device__ __forceinline__ void ldsm_x4(uint32_t* r, uint32_t saddr) {
    asm volatile("ldmatrix.sync.aligned.m8n8.x4.shared.b16 {%0,%1,%2,%3}, [%4];"
        : "=r"(r[0]), "=r"(r[1]), "=r"(r[2]), "=r"(r[3]) : "r"(saddr));
}
__device__ __forceinline__ void ldsm_x4_t(uint32_t* r, uint32_t saddr) {
    asm volatile("ldmatrix.sync.aligned.m8n8.x4.trans.shared.b16 {%0,%1,%2,%3}, [%4];"
        : "=r"(r[0]), "=r"(r[1]), "=r"(r[2]), "=r"(r[3]) : "r"(saddr));
}
__device__ __forceinline__ uint32_t h2u(__half2 v) { return *(uint32_t*)&v; }

// 64B-row swizzle
#define SW64(o) ((o) ^ (((o) >> 3) & 0x30))

// ---------------- block reduce (256 threads) ----------------
__device__ __forceinline__ float block_reduce_256(float v) {
    __shared__ float sh[8];
    #pragma unroll
    for (int o = 16; o; o >>= 1) v += __shfl_down_sync(0xffffffffu, v, o);
    if ((threadIdx.x & 31) == 0) sh[threadIdx.x >> 5] = v;
    __syncthreads();
    if (threadIdx.x == 0) {
        float t = 0.f;
        #pragma unroll
        for (int i = 0; i < 8; i++) t += sh[i];
        sh[0] = t;
    }
    __syncthreads();
    float r = sh[0];
    __syncthreads();
    return r;
}

// ---------------- kernel 1: input layernorm -> fp16 ----------------
__global__ __launch_bounds__(256) void ln_kernel(
    const float* __restrict__ x, const float* __restrict__ scale,
    const float* __restrict__ bias, __half* __restrict__ oh)
{
    int row = blockIdx.x;
    const float4* xr = (const float4*)(x + (size_t)row * D_);
    float4 v = xr[threadIdx.x];

    float s = v.x + v.y + v.z + v.w;
    float tot = block_reduce_256(s);
    float mu = tot * (1.0f / D_);

    float dx = v.x - mu, dy = v.y - mu, dz = v.z - mu, dw = v.w - mu;
    float sq = dx*dx + dy*dy + dz*dz + dw*dw;
    float vtot = block_reduce_256(sq);
    float rstd = rsqrtf(vtot * (1.0f / D_) + EPS);

    float4 sc = ((const float4*)scale)[threadIdx.x];
    float4 bi = ((const float4*)bias)[threadIdx.x];
    float ov[4];
    ov[0] = dx * rstd * sc.x + bi.x;
    ov[1] = dy * rstd * sc.y + bi.y;
    ov[2] = dz * rstd * sc.z + bi.z;
    ov[3] = dw * rstd * sc.w + bi.w;

    size_t base = (size_t)row * D_ + threadIdx.x * 4;
    *(__half2*)&oh[base + 0] = __floats2half2_rn(ov[0], ov[1]);
    *(__half2*)&oh[base + 2] = __floats2half2_rn(ov[2], ov[3]);
}

// ---------------- weight transpose: W[K][N] -> T[N][K] fp16 ----------------
__global__ __launch_bounds__(256) void convT_kernel(
    const float* __restrict__ W, __half* __restrict__ Th, int K, int N)
{
    __shared__ float t[32][33];
    int tx = threadIdx.x, ty = threadIdx.y;   // 32 x 8
    int nb = blockIdx.x * 32, kb = blockIdx.y * 32;
    #pragma unroll
    for (int i = 0; i < 4; i++)
        t[ty + 8 * i][tx] = W[(size_t)(kb + ty + 8 * i) * N + nb + tx];
    __syncthreads();
    #pragma unroll
    for (int i = 0; i < 4; i++) {
        int n = nb + ty + 8 * i, k = kb + tx;
        Th[(size_t)n * K + k] = __float2half(t[tx][ty + 8 * i]);
    }
}

// ---------------- shared GEMM machinery (single-A fp16) ----------------
#define GT_BYTES 8192                        // one 128x32 fp16 tile
#define GSTAGE   (2 * GT_BYTES)              // Af, Bf
#define GEMM_SMEM (4 * GSTAGE)               // 65536

__device__ __forceinline__ void gemm_issue_stage(
    char* st,
    const __half* __restrict__ Af, const __half* __restrict__ Bf,
    int m0, int n0, int K, int kc, int tid)
{
    const __half* srcs[2] = {Af, Bf};
    const int row0s[2] = {m0, n0};
    #pragma unroll
    for (int t = 0; t < 2; t++) {
        #pragma unroll
        for (int i = 0; i < 2; i++) {
            int u = tid + i * 256;
            int r = u >> 2, c = u & 3;
            uint32_t off = (uint32_t)(r * 64 + c * 16);
            cp16(st + t * GT_BYTES + SW64(off),
                 srcs[t] + (size_t)(row0s[t] + r) * K + kc + c * 8);
        }
    }
}

#define GEMM_MAINLOOP(Af, Bf, m0, n0, Kv)                                      \
    do {                                                                       \
        const int NK = (Kv) >> 5;                                              \
        gemm_issue_stage(gsm,              Af, Bf, m0, n0, Kv, 0,  tid);       \
        CP_COMMIT();                                                           \
        gemm_issue_stage(gsm + GSTAGE,     Af, Bf, m0, n0, Kv, 32, tid);       \
        CP_COMMIT();                                                           \
        gemm_issue_stage(gsm + 2 * GSTAGE, Af, Bf, m0, n0, Kv, 64, tid);       \
        CP_COMMIT();                                                           \
        for (int i = 0; i < NK; i++) {                                         \
            int rem = NK - 1 - i;                                              \
            if (rem >= 2) { CP_WAIT2(); } else if (rem == 1) { CP_WAIT1(); }   \
            else { CP_WAIT0(); }                                               \
            __syncthreads();                                                   \
            if (i + 3 < NK) {                                                  \
                gemm_issue_stage(gsm + ((i + 3) & 3) * GSTAGE,                 \
                                 Af, Bf, m0, n0, Kv, (i + 3) * 32, tid);       \
                CP_COMMIT();                                                   \
            }                                                                  \
            uint32_t uS  = uG + (uint32_t)((i & 3) * GSTAGE);                  \
            uint32_t uAf = uS;                                                 \
            uint32_t uBf = uS + GT_BYTES;                                      \
            _Pragma("unroll")                                                  \
            for (int kk = 0; kk < 2; kk++) {                                   \
                uint32_t kb = kk * 32;                                         \
                uint32_t a4[2][4];                                             \
                _Pragma("unroll")                                              \
                for (int ii = 0; ii < 2; ii++)                                 \
                    ldsm_x4(a4[ii], uAf + SW64(baseA[ii] + kb));               \
                _Pragma("unroll")                                              \
                for (int jp = 0; jp < 4; jp++) {                               \
                    uint32_t b4[4];                                            \
                    ldsm_x4(b4, uBf + SW64(baseB[jp] + kb));                   \
                    _Pragma("unroll")                                          \
                    for (int jj = 0; jj < 2; jj++) {                           \
                        int j = jp * 2 + jj;                                   \
                        _Pragma("unroll")                                      \
                        for (int ii = 0; ii < 2; ii++)                         \
                            mma16816(acc[ii][j], a4[ii], b4 + 2 * jj);         \
                    }                                                          \
                }                                                              \
            }                                                                  \
        }                                                                      \
    } while (0)

#define GEMM_PROLOG()                                                          \
    extern __shared__ char gsm[];                                              \
    int tid = threadIdx.x, lane = tid & 31, w = tid >> 5;                      \
    int g = lane >> 2, qi = lane & 3;                                          \
    int wm = w >> 1, wn = w & 1;                                               \
    int m0 = blockIdx.y * 128, n0 = blockIdx.x * 128;                          \
    uint32_t uG = smem_to_u32(gsm);                                            \
    uint32_t baseA[2], baseB[4];                                               \
    _Pragma("unroll")                                                          \
    for (int i = 0; i < 2; i++)                                                \
        baseA[i] = (uint32_t)((wm * 32 + i * 16 + (lane & 15)) * 64            \
                              + (lane >> 4) * 16);                             \
    _Pragma("unroll")                                                          \
    for (int jp = 0; jp < 4; jp++)                                             \
        baseB[jp] = (uint32_t)((wn * 64 + jp * 16 + (lane >> 4) * 8            \
                                + (lane & 7)) * 64 + ((lane >> 3) & 1) * 16);  \
    float acc[2][8][4];                                                        \
    _Pragma("unroll")                                                          \
    for (int i = 0; i < 2; i++)                                                \
        _Pragma("unroll")                                                      \
        for (int j = 0; j < 8; j++)                                            \
            _Pragma("unroll")                                                  \
            for (int e = 0; e < 4; e++) acc[i][j][e] = 0.f;

// ---------------- generic GEMM (out-proj): fp32 C + bias ----------------
__global__ __launch_bounds__(256, 2) void gemm_mma(
    const __half* __restrict__ Af, const __half* __restrict__ Bf,
    const float* __restrict__ bias, float* __restrict__ C, int M, int N, int K)
{
    GEMM_PROLOG();
    GEMM_MAINLOOP(Af, Bf, m0, n0, K);

    #pragma unroll
    for (int i = 0; i < 2; i++) {
        int r0 = m0 + wm * 32 + i * 16 + g;
        #pragma unroll
        for (int j = 0; j < 8; j++) {
            int col = n0 + wn * 64 + j * 8 + 2 * qi;
            float b0 = __ldg(&bias[col]), b1 = __ldg(&bias[col + 1]);
            float2 v0 = make_float2(acc[i][j][0] + b0, acc[i][j][1] + b1);
            float2 v1 = make_float2(acc[i][j][2] + b0, acc[i][j][3] + b1);
            *(float2*)&C[(size_t)r0 * N + col]       = v0;
            *(float2*)&C[(size_t)(r0 + 8) * N + col] = v1;
        }
    }
}

// ---------------- fused QKV GEMM: bias + per-head LN + RoPE epilogue ----------------
__global__ __launch_bounds__(256, 2) void gemm_qkv(
    const __half* __restrict__ Af, const __half* __restrict__ Bf,
    const float* __restrict__ bias,
    const float* __restrict__ q_scale, const float* __restrict__ k_scale,
    __half* __restrict__ qf, __half* __restrict__ kf, __half* __restrict__ vf)
{
    GEMM_PROLOG();
    GEMM_MAINLOOP(Af, Bf, m0, n0, D_);

    int region = n0 >> 10;                  // 0=q, 1=k, 2=v
    int hh = ((n0 & 1023) >> 6) + wn;       // head
    #pragma unroll
    for (int i = 0; i < 2; i++) {
        #pragma unroll
        for (int half = 0; half < 2; half++) {
            int r = m0 + wm * 32 + i * 16 + g + half * 8;
            int s = r & (S_ - 1), bb = r >> 11;
            size_t obase = (((size_t)(bb * H_ + hh)) * S_ + s) * HD_;

            float x[16];
            #pragma unroll
            for (int j = 0; j < 8; j++) {
                int col = n0 + wn * 64 + j * 8 + 2 * qi;
                x[2 * j]     = acc[i][j][half * 2]     + __ldg(&bias[col]);
                x[2 * j + 1] = acc[i][j][half * 2 + 1] + __ldg(&bias[col + 1]);
            }

            if (region == 2) {
                #pragma unroll
                for (int j = 0; j < 8; j++) {
                    int d = j * 8 + 2 * qi;
                    *(__half2*)&vf[obase + d] = __floats2half2_rn(x[2*j], x[2*j+1]);
                }
            } else {
                float sum = 0.f, sq = 0.f;
                #pragma unroll
                for (int t = 0; t < 16; t++) { sum += x[t]; sq += x[t] * x[t]; }
                sum += __shfl_xor_sync(0xffffffffu, sum, 1);
                sum += __shfl_xor_sync(0xffffffffu, sum, 2);
                sq  += __shfl_xor_sync(0xffffffffu, sq, 1);
                sq  += __shfl_xor_sync(0xffffffffu, sq, 2);
                float mu = sum * (1.0f / HD_);
                float rstd = rsqrtf(sq * (1.0f / HD_) - mu * mu + EPS);
                const float* sc = (region == 0) ? q_scale : k_scale;
                #pragma unroll
                for (int j = 0; j < 8; j++) {
                    int d = j * 8 + 2 * qi;
                    x[2 * j]     = (x[2 * j]     - mu) * rstd * __ldg(&sc[d]);
                    x[2 * j + 1] = (x[2 * j + 1] - mu) * rstd * __ldg(&sc[d + 1]);
                }
                #pragma unroll
                for (int j = 0; j < 4; j++) {
                    int d = j * 8 + 2 * qi;      // < 32
                    #pragma unroll
                    for (int c = 0; c < 2; c++) {
                        float inv = expf(-(float)(2 * (d + c)) * (1.0f / 64.0f)
                                         * 9.210340371976184f);
                        float sn, cs;
                        sincosf((float)s * inv, &sn, &cs);
                        float lo = x[2 * j + c], hi = x[2 * (j + 4) + c];
                        x[2 * j + c]       = lo * cs - hi * sn;
                        x[2 * (j + 4) + c] = hi * cs + lo * sn;
                    }
                }
                if (region == 0) {
                    #pragma unroll
                    for (int j = 0; j < 8; j++) {
                        int d = j * 8 + 2 * qi;
                        *(__half2*)&qf[obase + d] =
                            __floats2half2_rn(x[2*j] * 0.125f, x[2*j+1] * 0.125f);
                    }
                } else {
                    #pragma unroll
                    for (int j = 0; j < 8; j++) {
                        int d = j * 8 + 2 * qi;
                        *(__half2*)&kf[obase + d] = __floats2half2_rn(x[2*j], x[2*j+1]);
                    }
                }
            }
        }
    }
}

// ---------------- flash attention: single-fp16 Q/K/V/P, 3-stage KV ring ----------------
#define LQ 72
#define KVT (64 * LQ)
#define KVSTG (2 * KVT)                    // K + V, one stage (elements)
#define FL_SMEM ((128 * LQ + 3 * KVSTG) * (int)sizeof(__half))

__device__ __forceinline__ void flash_issue_kv(
    __half* st,
    const __half* __restrict__ Kp, const __half* __restrict__ Vp,
    int j0, int tid)
{
    int r = tid >> 2, c = (tid & 3) * 16;
    size_t go = (size_t)(j0 + r) * HD_ + c;
    int so = r * LQ + c;
    cp16(st + so,           Kp + go);
    cp16(st + so + 8,       Kp + go + 8);
    cp16(st + KVT + so,     Vp + go);
    cp16(st + KVT + so + 8, Vp + go + 8);
}

__global__ __launch_bounds__(256, 2) void flash_mma(
    const __half* __restrict__ Qf_, const __half* __restrict__ Kf_,
    const __half* __restrict__ Vf_, __half* __restrict__ O_)
{
    extern __shared__ __half fsm[];
    __half* sQ  = fsm;                 // [128][LQ]
    __half* sKV = sQ + 128 * LQ;       // 3 stages x {K, V}

    int tid = threadIdx.x, lane = tid & 31, wid = tid >> 5;
    int g = lane >> 2, qi = lane & 3;
    int bh = blockIdx.y;
    int b = bh >> 4, h = bh & 15;
    int q0 = blockIdx.x * 128;
    size_t hbase = (size_t)bh * S_ * HD_;
    const __half* Qfp = Qf_ + hbase;
    const __half* Kfp = Kf_ + hbase;
    const __half* Vfp = Vf_ + hbase;

    int wr = wid * 16;
    uint32_t uQ  = smem_to_u32(sQ);
    uint32_t uKV = smem_to_u32(sKV);

    uint32_t offQ = ((wr + (lane & 15)) * LQ + (lane >> 4) * 8) * 2;
    uint32_t offK[4], offV[4];
    #pragma unroll
    for (int tp = 0; tp < 4; tp++)
        offK[tp] = ((tp * 16 + (lane >> 4) * 8 + (lane & 7)) * LQ
                    + ((lane >> 3) & 1) * 8) * 2;
    #pragma unroll
    for (int tdp = 0; tdp < 4; tdp++)
        offV[tdp] = ((((lane >> 3) & 1) * 8 + (lane & 7)) * LQ
                     + (2 * tdp + (lane >> 4)) * 8) * 2;

    #pragma unroll
    for (int i = 0; i < 4; i++) {
        int u = tid + i * 256;
        int r = u >> 3, c = (u & 7) * 8;
        *(uint4*)&sQ[r * LQ + c] = *(const uint4*)&Qfp[(size_t)(q0 + r) * HD_ + c];
    }
    flash_issue_kv(sKV,         Kfp, Vfp, 0,  tid);
    CP_COMMIT();
    flash_issue_kv(sKV + KVSTG, Kfp, Vfp, 64, tid);
    CP_COMMIT();

    float o[8][4];
    #pragma unroll
    for (int t = 0; t < 8; t++)
        #pragma unroll
        for (int e = 0; e < 4; e++) o[t][e] = 0.f;
    float m_g = -1e30f, m_g8 = -1e30f, l_g = 0.f, l_g8 = 0.f;

    const int NT = S_ / 64;
    int stg = 0;
    for (int kt = 0; kt < NT; kt++) {
        if (kt + 1 < NT) { CP_WAIT1(); } else { CP_WAIT0(); }
        __syncthreads();

        if (kt + 2 < NT) {
            int nst = stg + 2; if (nst >= 3) nst -= 3;
            flash_issue_kv(sKV + nst * KVSTG, Kfp, Vfp, (kt + 2) * 64, tid);
            CP_COMMIT();
        }

        uint32_t uS = uKV + (uint32_t)(stg * KVSTG) * 2;
        uint32_t uK = uS;
        uint32_t uV = uS + KVT * 2;

        float s[8][4];
        #pragma unroll
        for (int t = 0; t < 8; t++)
            #pragma unroll
            for (int e = 0; e < 4; e++) s[t][e] = 0.f;

        #pragma unroll
        for (int u = 0; u < 4; u++) {
            uint32_t a4[4];
            ldsm_x4(a4, uQ + offQ + u * 32);
            #pragma unroll
            for (int tp = 0; tp < 4; tp++) {
                uint32_t b4[4];
                ldsm_x4(b4, uK + offK[tp] + u * 32);
                mma16816(s[2 * tp],     a4, b4);
                mma16816(s[2 * tp + 1], a4, b4 + 2);
            }
        }

        float mt_g = -1e30f, mt_g8 = -1e30f;
        #pragma unroll
        for (int t = 0; t < 8; t++) {
            mt_g  = fmaxf(mt_g,  fmaxf(s[t][0], s[t][1]));
            mt_g8 = fmaxf(mt_g8, fmaxf(s[t][2], s[t][3]));
        }
        mt_g  = fmaxf(mt_g,  __shfl_xor_sync(0xffffffffu, mt_g, 1));
        mt_g  = fmaxf(mt_g,  __shfl_xor_sync(0xffffffffu, mt_g, 2));
        mt_g8 = fmaxf(mt_g8, __shfl_xor_sync(0xffffffffu, mt_g8, 1));
        mt_g8 = fmaxf(mt_g8, __shfl_xor_sync(0xffffffffu, mt_g8, 2));
        float mn_g = fmaxf(m_g, mt_g), mn_g8 = fmaxf(m_g8, mt_g8);
        float al_g = __expf(m_g - mn_g), al_g8 = __expf(m_g8 - mn_g8);
        m_g = mn_g; m_g8 = mn_g8;

        uint32_t ph01[8], ph23[8];
        float sum_g = 0.f, sum_g8 = 0.f;
        #pragma unroll
        for (int t = 0; t < 8; t++) {
            float p0 = __expf(s[t][0] - mn_g);
            float p1 = __expf(s[t][1] - mn_g);
            float p2 = __expf(s[t][2] - mn_g8);
            float p3 = __expf(s[t][3] - mn_g8);
            sum_g += p0 + p1; sum_g8 += p2 + p3;
            ph01[t] = h2u(__floats2half2_rn(p0, p1));
            ph23[t] = h2u(__floats2half2_rn(p2, p3));
        }
        sum_g  += __shfl_xor_sync(0xffffffffu, sum_g, 1);
        sum_g  += __shfl_xor_sync(0xffffffffu, sum_g, 2);
        sum_g8 += __shfl_xor_sync(0xffffffffu, sum_g8, 1);
        sum_g8 += __shfl_xor_sync(0xffffffffu, sum_g8, 2);
        l_g  = l_g  * al_g  + sum_g;
        l_g8 = l_g8 * al_g8 + sum_g8;

        #pragma unroll
        for (int t = 0; t < 8; t++) {
            o[t][0] *= al_g;  o[t][1] *= al_g;
            o[t][2] *= al_g8; o[t][3] *= al_g8;
        }

        #pragma unroll
        for (int u = 0; u < 4; u++) {
            uint32_t pah[4] = {ph01[2*u], ph23[2*u], ph01[2*u+1], ph23[2*u+1]};
            uint32_t ubase = u * 16 * LQ * 2;
            #pragma unroll
            for (int tdp = 0; tdp < 4; tdp++) {
                uint32_t bv4[4];
                ldsm_x4_t(bv4, uV + offV[tdp] + ubase);
                mma16816(o[2 * tdp],     pah, bv4);
                mma16816(o[2 * tdp + 1], pah, bv4 + 2);
            }
        }

        stg = stg + 1; if (stg >= 3) stg = 0;
    }

    float iv_g = 1.f / l_g, iv_g8 = 1.f / l_g8;
    size_t ob  = ((size_t)(b * S_ + q0 + wr + g)     * H_ + h) * HD_;
    size_t ob8 = ((size_t)(b * S_ + q0 + wr + g + 8) * H_ + h) * HD_;
    #pragma unroll
    for (int td = 0; td < 8; td++) {
        int d = 8 * td + 2 * qi;
        *(uint32_t*)&O_[ob + d]  = h2u(__floats2half2_rn(o[td][0] * iv_g,
                                                         o[td][1] * iv_g));
        *(uint32_t*)&O_[ob8 + d] = h2u(__floats2half2_rn(o[td][2] * iv_g8,
                                                         o[td][3] * iv_g8));
    }
}

// ---------------- launcher ----------------
extern "C" void kernel_launch(void* const* d_in, const int* in_sizes, int n_in,
                              void* d_out, int out_size)
{
    const float* x        = (const float*)d_in[0];
    const float* w_qkv    = (const float*)d_in[1];
    const float* b_qkv    = (const float*)d_in[2];
    const float* w_out    = (const float*)d_in[3];
    const float* b_out    = (const float*)d_in[4];
    const float* ln_scale = (const float*)d_in[5];
    const float* ln_bias  = (const float*)d_in[6];
    const float* q_scale  = (const float*)d_in[7];
    const float* k_scale  = (const float*)d_in[8];
    float* out = (float*)d_out;

    __half *xn, *wq, *wo, *attn, *qf, *kf, *vf;
    cudaGetSymbolAddress((void**)&xn,   g_xn);
    cudaGetSymbolAddress((void**)&wq,   g_wqT);
    cudaGetSymbolAddress((void**)&wo,   g_woT);
    cudaGetSymbolAddress((void**)&qf,   g_qf);
    cudaGetSymbolAddress((void**)&kf,   g_kf);
    cudaGetSymbolAddress((void**)&vf,   g_vf);
    cudaGetSymbolAddress((void**)&attn, g_attn);

    cudaFuncSetAttribute(gemm_mma,
        cudaFuncAttributeMaxDynamicSharedMemorySize, GEMM_SMEM);
    cudaFuncSetAttribute(gemm_qkv,
        cudaFuncAttributeMaxDynamicSharedMemorySize, GEMM_SMEM);
    cudaFuncSetAttribute(flash_mma,
        cudaFuncAttributeMaxDynamicSharedMemorySize, FL_SMEM);

    // 1. input layernorm -> fp16
    ln_kernel<<<ROWS, 256>>>(x, ln_scale, ln_bias, xn);

    // 2. weight transpose -> fp16
    convT_kernel<<<dim3((3 * D_) / 32, D_ / 32), dim3(32, 8)>>>(w_qkv, wq, D_, 3 * D_);
    convT_kernel<<<dim3(D_ / 32, D_ / 32), dim3(32, 8)>>>(w_out, wo, D_, D_);

    // 3. fused QKV GEMM + per-head LN + RoPE (single fp16)
    gemm_qkv<<<dim3((3 * D_) / 128, ROWS / 128), 256, GEMM_SMEM>>>(
        xn, wq, b_qkv, q_scale, k_scale, qf, kf, vf);

    // 4. flash attention (all single fp16)
    flash_mma<<<dim3(S_ / 128, B_ * H_), 256, FL_SMEM>>>(qf, kf, vf, attn);

    // 5. output GEMM
    gemm_mma<<<dim3(D_ / 128, ROWS / 128), 256, GEMM_SMEM>>>(
        attn, wo, b_out, out, ROWS, D_, D_);
}

// round 14
// speedup vs baseline: 12.8896x; 1.0419x over previous
#include <cuda_runtime.h>
#include <cuda_fp16.h>
#include <cstdint>
#include <math.h>

#define B_  2
#define S_  2048
#define D_  1024
#define H_  16
#define HD_ 64
#define EPS 1e-6f

#define ROWS (B_ * S_)          // 4096

// ---------------- scratch (device globals; no allocation) ----------------
__device__ __half g_xn  [ROWS * D_];
__device__ __half g_wqT [3 * D_ * D_];   // [3072][1024] K-major fp16
__device__ __half g_woT [D_ * D_];       // [1024][1024] K-major
__device__ __half g_qf[B_ * H_ * S_ * HD_];
__device__ __half g_kf[B_ * H_ * S_ * HD_];
__device__ __half g_vf[B_ * H_ * S_ * HD_];
__device__ __half g_attn[ROWS * D_];

// ================= helpers =================
__device__ __forceinline__ uint32_t smem_to_u32(const void* p) {
    uint32_t a;
    asm("{ .reg .u64 t; cvta.to.shared.u64 t, %1; cvt.u32.u64 %0, t; }"
        : "=r"(a) : "l"(p));
    return a;
}
__device__ __forceinline__ void cp16(void* sp, const void* gp) {
    uint32_t s = smem_to_u32(sp);
    asm volatile("cp.async.cg.shared.global [%0], [%1], 16;" :: "r"(s), "l"(gp));
}
#define CP_COMMIT() asm volatile("cp.async.commit_group;" ::: "memory")
#define CP_WAIT1()  asm volatile("cp.async.wait_group 1;"  ::: "memory")
#define CP_WAIT0()  asm volatile("cp.async.wait_group 0;"  ::: "memory")

__device__ __forceinline__ void mma16816(float* c, const uint32_t* a, const uint32_t* b) {
    asm volatile(
        "mma.sync.aligned.m16n8k16.row.col.f32.f16.f16.f32 "
        "{%0,%1,%2,%3}, {%4,%5,%6,%7}, {%8,%9}, {%0,%1,%2,%3};"
        : "+f"(c[0]), "+f"(c[1]), "+f"(c[2]), "+f"(c[3])
        : "r"(a[0]), "r"(a[1]), "r"(a[2]), "r"(a[3]),
          "r"(b[0]), "r"(b[1]));
}
__device__ __forceinline__ void ldsm_x4(uint32_t* r, uint32_t saddr) {
    asm volatile("ldmatrix.sync.aligned.m8n8.x4.shared.b16 {%0,%1,%2,%3}, [%4];"
        : "=r"(r[0]), "=r"(r[1]), "=r"(r[2]), "=r"(r[3]) : "r"(saddr));
}
__device__ __forceinline__ void ldsm_x4_t(uint32_t* r, uint32_t saddr) {
    asm volatile("ldmatrix.sync.aligned.m8n8.x4.trans.shared.b16 {%0,%1,%2,%3}, [%4];"
        : "=r"(r[0]), "=r"(r[1]), "=r"(r[2]), "=r"(r[3]) : "r"(saddr));
}
__device__ __forceinline__ uint32_t h2u(__half2 v) { return *(uint32_t*)&v; }

// swizzles
#define SW64(o)  ((o) ^ (((o) >> 3) & 0x30))
#define SW128(o) ((o) ^ (((o) >> 3) & 0x70))

// ---------------- block reduce (256 threads) ----------------
__device__ __forceinline__ float block_reduce_256(float v, float* sh) {
    #pragma unroll
    for (int o = 16; o; o >>= 1) v += __shfl_down_sync(0xffffffffu, v, o);
    if ((threadIdx.x & 31) == 0) sh[threadIdx.x >> 5] = v;
    __syncthreads();
    if (threadIdx.x == 0) {
        float t = 0.f;
        #pragma unroll
        for (int i = 0; i < 8; i++) t += sh[i];
        sh[0] = t;
    }
    __syncthreads();
    float r = sh[0];
    __syncthreads();
    return r;
}

// ---------------- fused prep: LN + weight transpose/cast ----------------
// blocks [0,4096): LN rows. [4096,7168): w_qkv tiles. [7168,8192): w_out tiles.
__global__ __launch_bounds__(256) void prep_kernel(
    const float* __restrict__ x, const float* __restrict__ scale,
    const float* __restrict__ bias, __half* __restrict__ xn,
    const float* __restrict__ Wq, __half* __restrict__ WqT,
    const float* __restrict__ Wo, __half* __restrict__ WoT)
{
    __shared__ float shred[8];
    __shared__ float t[32][33];
    int bid = blockIdx.x;
    int tid = threadIdx.x;

    if (bid < ROWS) {
        // ---- layernorm row ----
        int row = bid;
        const float4* xr = (const float4*)(x + (size_t)row * D_);
        float4 v = xr[tid];

        float s = v.x + v.y + v.z + v.w;
        float tot = block_reduce_256(s, shred);
        float mu = tot * (1.0f / D_);

        float dx = v.x - mu, dy = v.y - mu, dz = v.z - mu, dw = v.w - mu;
        float sq = dx*dx + dy*dy + dz*dz + dw*dw;
        float vtot = block_reduce_256(sq, shred);
        float rstd = rsqrtf(vtot * (1.0f / D_) + EPS);

        float4 sc = ((const float4*)scale)[tid];
        float4 bi = ((const float4*)bias)[tid];
        size_t base = (size_t)row * D_ + tid * 4;
        *(__half2*)&xn[base + 0] = __floats2half2_rn(dx * rstd * sc.x + bi.x,
                                                     dy * rstd * sc.y + bi.y);
        *(__half2*)&xn[base + 2] = __floats2half2_rn(dz * rstd * sc.z + bi.z,
                                                     dw * rstd * sc.w + bi.w);
    } else {
        // ---- weight transpose/cast 32x32 tile ----
        const float* W; __half* T; int K, N, tt;
        if (bid < ROWS + 3072) {
            tt = bid - ROWS; W = Wq; T = WqT; K = D_; N = 3 * D_;
        } else {
            tt = bid - ROWS - 3072; W = Wo; T = WoT; K = D_; N = D_;
        }
        int ntiles = N >> 5;
        int nb = (tt % ntiles) * 32, kb = (tt / ntiles) * 32;
        int tx = tid & 31, ty = tid >> 5;          // 32 x 8
        #pragma unroll
        for (int i = 0; i < 4; i++)
            t[ty + 8 * i][tx] = W[(size_t)(kb + ty + 8 * i) * N + nb + tx];
        __syncthreads();
        #pragma unroll
        for (int i = 0; i < 4; i++) {
            int n = nb + ty + 8 * i, k = kb + tx;
            T[(size_t)n * K + k] = __float2half(t[tx][ty + 8 * i]);
        }
    }
}

// ---------------- shared GEMM machinery (single fp16, K-slab 64) ----------------
#define GT_BYTES 16384                       // one 128x64 fp16 tile
#define GSTAGE   (2 * GT_BYTES)              // Af, Bf
#define GEMM_SMEM (3 * GSTAGE)               // 98304

__device__ __forceinline__ void gemm_issue_stage(
    char* st,
    const __half* __restrict__ Af, const __half* __restrict__ Bf,
    int m0, int n0, int K, int kc, int tid)
{
    const __half* srcs[2] = {Af, Bf};
    const int row0s[2] = {m0, n0};
    #pragma unroll
    for (int t = 0; t < 2; t++) {
        #pragma unroll
        for (int i = 0; i < 4; i++) {
            int u = tid + i * 256;
            int r = u >> 3, c = u & 7;
            uint32_t off = (uint32_t)(r * 128 + c * 16);
            cp16(st + t * GT_BYTES + SW128(off),
                 srcs[t] + (size_t)(row0s[t] + r) * K + kc + c * 8);
        }
    }
}

#define GEMM_MAINLOOP(Af, Bf, m0, n0, Kv)                                      \
    do {                                                                       \
        const int NK = (Kv) >> 6;                                              \
        gemm_issue_stage(gsm,          Af, Bf, m0, n0, Kv, 0,  tid);           \
        CP_COMMIT();                                                           \
        gemm_issue_stage(gsm + GSTAGE, Af, Bf, m0, n0, Kv, 64, tid);           \
        CP_COMMIT();                                                           \
        int stg_ = 0;                                                          \
        for (int i = 0; i < NK; i++) {                                         \
            if (i + 1 < NK) { CP_WAIT1(); } else { CP_WAIT0(); }               \
            __syncthreads();                                                   \
            if (i + 2 < NK) {                                                  \
                int nst_ = stg_ + 2; if (nst_ >= 3) nst_ -= 3;                 \
                gemm_issue_stage(gsm + nst_ * GSTAGE,                          \
                                 Af, Bf, m0, n0, Kv, (i + 2) * 64, tid);       \
                CP_COMMIT();                                                   \
            }                                                                  \
            uint32_t uS  = uG + (uint32_t)(stg_ * GSTAGE);                     \
            uint32_t uAf = uS;                                                 \
            uint32_t uBf = uS + GT_BYTES;                                      \
            _Pragma("unroll")                                                  \
            for (int kk = 0; kk < 4; kk++) {                                   \
                uint32_t kb = kk * 32;                                         \
                uint32_t a4[2][4];                                             \
                _Pragma("unroll")                                              \
                for (int ii = 0; ii < 2; ii++)                                 \
                    ldsm_x4(a4[ii], uAf + SW128(baseA[ii] + kb));              \
                _Pragma("unroll")                                              \
                for (int jp = 0; jp < 4; jp++) {                               \
                    uint32_t b4[4];                                            \
                    ldsm_x4(b4, uBf + SW128(baseB[jp] + kb));                  \
                    _Pragma("unroll")                                          \
                    for (int jj = 0; jj < 2; jj++) {                           \
                        int j = jp * 2 + jj;                                   \
                        _Pragma("unroll")                                      \
                        for (int ii = 0; ii < 2; ii++)                         \
                            mma16816(acc[ii][j], a4[ii], b4 + 2 * jj);         \
                    }                                                          \
                }                                                              \
            }                                                                  \
            stg_ = stg_ + 1; if (stg_ >= 3) stg_ = 0;                          \
        }                                                                      \
    } while (0)

#define GEMM_PROLOG()                                                          \
    extern __shared__ char gsm[];                                              \
    int tid = threadIdx.x, lane = tid & 31, w = tid >> 5;                      \
    int g = lane >> 2, qi = lane & 3;                                          \
    int wm = w >> 1, wn = w & 1;                                               \
    int m0 = blockIdx.y * 128, n0 = blockIdx.x * 128;                          \
    uint32_t uG = smem_to_u32(gsm);                                            \
    uint32_t baseA[2], baseB[4];                                               \
    _Pragma("unroll")                                                          \
    for (int i = 0; i < 2; i++)                                                \
        baseA[i] = (uint32_t)((wm * 32 + i * 16 + (lane & 15)) * 128           \
                              + (lane >> 4) * 16);                             \
    _Pragma("unroll")                                                          \
    for (int jp = 0; jp < 4; jp++)                                             \
        baseB[jp] = (uint32_t)((wn * 64 + jp * 16 + (lane >> 4) * 8            \
                                + (lane & 7)) * 128 + ((lane >> 3) & 1) * 16); \
    float acc[2][8][4];                                                        \
    _Pragma("unroll")                                                          \
    for (int i = 0; i < 2; i++)                                                \
        _Pragma("unroll")                                                      \
        for (int j = 0; j < 8; j++)                                            \
            _Pragma("unroll")                                                  \
            for (int e = 0; e < 4; e++) acc[i][j][e] = 0.f;

// ---------------- generic GEMM (out-proj): fp32 C + bias ----------------
__global__ __launch_bounds__(256, 2) void gemm_mma(
    const __half* __restrict__ Af, const __half* __restrict__ Bf,
    const float* __restrict__ bias, float* __restrict__ C, int M, int N, int K)
{
    GEMM_PROLOG();
    GEMM_MAINLOOP(Af, Bf, m0, n0, K);

    #pragma unroll
    for (int i = 0; i < 2; i++) {
        int r0 = m0 + wm * 32 + i * 16 + g;
        #pragma unroll
        for (int j = 0; j < 8; j++) {
            int col = n0 + wn * 64 + j * 8 + 2 * qi;
            float b0 = __ldg(&bias[col]), b1 = __ldg(&bias[col + 1]);
            float2 v0 = make_float2(acc[i][j][0] + b0, acc[i][j][1] + b1);
            float2 v1 = make_float2(acc[i][j][2] + b0, acc[i][j][3] + b1);
            *(float2*)&C[(size_t)r0 * N + col]       = v0;
            *(float2*)&C[(size_t)(r0 + 8) * N + col] = v1;
        }
    }
}

// ---------------- fused QKV GEMM: bias + per-head LN + RoPE epilogue ----------------
__global__ __launch_bounds__(256, 2) void gemm_qkv(
    const __half* __restrict__ Af, const __half* __restrict__ Bf,
    const float* __restrict__ bias,
    const float* __restrict__ q_scale, const float* __restrict__ k_scale,
    __half* __restrict__ qf, __half* __restrict__ kf, __half* __restrict__ vf)
{
    GEMM_PROLOG();
    GEMM_MAINLOOP(Af, Bf, m0, n0, D_);

    int region = n0 >> 10;                  // 0=q, 1=k, 2=v
    int hh = ((n0 & 1023) >> 6) + wn;       // head
    #pragma unroll
    for (int i = 0; i < 2; i++) {
        #pragma unroll
        for (int half = 0; half < 2; half++) {
            int r = m0 + wm * 32 + i * 16 + g + half * 8;
            int s = r & (S_ - 1), bb = r >> 11;
            size_t obase = (((size_t)(bb * H_ + hh)) * S_ + s) * HD_;

            float x[16];
            #pragma unroll
            for (int j = 0; j < 8; j++) {
                int col = n0 + wn * 64 + j * 8 + 2 * qi;
                x[2 * j]     = acc[i][j][half * 2]     + __ldg(&bias[col]);
                x[2 * j + 1] = acc[i][j][half * 2 + 1] + __ldg(&bias[col + 1]);
            }

            if (region == 2) {
                #pragma unroll
                for (int j = 0; j < 8; j++) {
                    int d = j * 8 + 2 * qi;
                    *(__half2*)&vf[obase + d] = __floats2half2_rn(x[2*j], x[2*j+1]);
                }
            } else {
                float sum = 0.f, sq = 0.f;
                #pragma unroll
                for (int t = 0; t < 16; t++) { sum += x[t]; sq += x[t] * x[t]; }
                sum += __shfl_xor_sync(0xffffffffu, sum, 1);
                sum += __shfl_xor_sync(0xffffffffu, sum, 2);
                sq  += __shfl_xor_sync(0xffffffffu, sq, 1);
                sq  += __shfl_xor_sync(0xffffffffu, sq, 2);
                float mu = sum * (1.0f / HD_);
                float rstd = rsqrtf(sq * (1.0f / HD_) - mu * mu + EPS);
                const float* sc = (region == 0) ? q_scale : k_scale;
                #pragma unroll
                for (int j = 0; j < 8; j++) {
                    int d = j * 8 + 2 * qi;
                    x[2 * j]     = (x[2 * j]     - mu) * rstd * __ldg(&sc[d]);
                    x[2 * j + 1] = (x[2 * j + 1] - mu) * rstd * __ldg(&sc[d + 1]);
                }
                #pragma unroll
                for (int j = 0; j < 4; j++) {
                    int d = j * 8 + 2 * qi;      // < 32
                    #pragma unroll
                    for (int c = 0; c < 2; c++) {
                        float inv = expf(-(float)(2 * (d + c)) * (1.0f / 64.0f)
                                         * 9.210340371976184f);
                        float sn, cs;
                        sincosf((float)s * inv, &sn, &cs);
                        float lo = x[2 * j + c], hi = x[2 * (j + 4) + c];
                        x[2 * j + c]       = lo * cs - hi * sn;
                        x[2 * (j + 4) + c] = hi * cs + lo * sn;
                    }
                }
                if (region == 0) {
                    #pragma unroll
                    for (int j = 0; j < 8; j++) {
                        int d = j * 8 + 2 * qi;
                        *(__half2*)&qf[obase + d] =
                            __floats2half2_rn(x[2*j] * 0.125f, x[2*j+1] * 0.125f);
                    }
                } else {
                    #pragma unroll
                    for (int j = 0; j < 8; j++) {
                        int d = j * 8 + 2 * qi;
                        *(__half2*)&kf[obase + d] = __floats2half2_rn(x[2*j], x[2*j+1]);
                    }
                }
            }
        }
    }
}

// ---------------- flash attention: single-fp16 Q/K/V/P, 3-stage KV ring ----------------
#define LQ 72
#define KVT (64 * LQ)
#define KVSTG (2 * KVT)                    // K + V, one stage (elements)
#define FL_SMEM ((128 * LQ + 3 * KVSTG) * (int)sizeof(__half))

__device__ __forceinline__ void flash_issue_kv(
    __half* st,
    const __half* __restrict__ Kp, const __half* __restrict__ Vp,
    int j0, int tid)
{
    int r = tid >> 2, c = (tid & 3) * 16;
    size_t go = (size_t)(j0 + r) * HD_ + c;
    int so = r * LQ + c;
    cp16(st + so,           Kp + go);
    cp16(st + so + 8,       Kp + go + 8);
    cp16(st + KVT + so,     Vp + go);
    cp16(st + KVT + so + 8, Vp + go + 8);
}

__global__ __launch_bounds__(256, 2) void flash_mma(
    const __half* __restrict__ Qf_, const __half* __restrict__ Kf_,
    const __half* __restrict__ Vf_, __half* __restrict__ O_)
{
    extern __shared__ __half fsm[];
    __half* sQ  = fsm;                 // [128][LQ]
    __half* sKV = sQ + 128 * LQ;       // 3 stages x {K, V}

    int tid = threadIdx.x, lane = tid & 31, wid = tid >> 5;
    int g = lane >> 2, qi = lane & 3;
    int bh = blockIdx.y;
    int b = bh >> 4, h = bh & 15;
    int q0 = blockIdx.x * 128;
    size_t hbase = (size_t)bh * S_ * HD_;
    const __half* Qfp = Qf_ + hbase;
    const __half* Kfp = Kf_ + hbase;
    const __half* Vfp = Vf_ + hbase;

    int wr = wid * 16;
    uint32_t uQ  = smem_to_u32(sQ);
    uint32_t uKV = smem_to_u32(sKV);

    uint32_t offQ = ((wr + (lane & 15)) * LQ + (lane >> 4) * 8) * 2;
    uint32_t offK[4], offV[4];
    #pragma unroll
    for (int tp = 0; tp < 4; tp++)
        offK[tp] = ((tp * 16 + (lane >> 4) * 8 + (lane & 7)) * LQ
                    + ((lane >> 3) & 1) * 8) * 2;
    #pragma unroll
    for (int tdp = 0; tdp < 4; tdp++)
        offV[tdp] = ((((lane >> 3) & 1) * 8 + (lane & 7)) * LQ
                     + (2 * tdp + (lane >> 4)) * 8) * 2;

    #pragma unroll
    for (int i = 0; i < 4; i++) {
        int u = tid + i * 256;
        int r = u >> 3, c = (u & 7) * 8;
        *(uint4*)&sQ[r * LQ + c] = *(const uint4*)&Qfp[(size_t)(q0 + r) * HD_ + c];
    }
    flash_issue_kv(sKV,         Kfp, Vfp, 0,  tid);
    CP_COMMIT();
    flash_issue_kv(sKV + KVSTG, Kfp, Vfp, 64, tid);
    CP_COMMIT();

    float o[8][4];
    #pragma unroll
    for (int t = 0; t < 8; t++)
        #pragma unroll
        for (int e = 0; e < 4; e++) o[t][e] = 0.f;
    float m_g = -1e30f, m_g8 = -1e30f, l_g = 0.f, l_g8 = 0.f;

    const int NT = S_ / 64;
    int stg = 0;
    for (int kt = 0; kt < NT; kt++) {
        if (kt + 1 < NT) { CP_WAIT1(); } else { CP_WAIT0(); }
        __syncthreads();

        if (kt + 2 < NT) {
            int nst = stg + 2; if (nst >= 3) nst -= 3;
            flash_issue_kv(sKV + nst * KVSTG, Kfp, Vfp, (kt + 2) * 64, tid);
            CP_COMMIT();
        }

        uint32_t uS = uKV + (uint32_t)(stg * KVSTG) * 2;
        uint32_t uK = uS;
        uint32_t uV = uS + KVT * 2;

        float s[8][4];
        #pragma unroll
        for (int t = 0; t < 8; t++)
            #pragma unroll
            for (int e = 0; e < 4; e++) s[t][e] = 0.f;

        #pragma unroll
        for (int u = 0; u < 4; u++) {
            uint32_t a4[4];
            ldsm_x4(a4, uQ + offQ + u * 32);
            #pragma unroll
            for (int tp = 0; tp < 4; tp++) {
                uint32_t b4[4];
                ldsm_x4(b4, uK + offK[tp] + u * 32);
                mma16816(s[2 * tp],     a4, b4);
                mma16816(s[2 * tp + 1], a4, b4 + 2);
            }
        }

        float mt_g = -1e30f, mt_g8 = -1e30f;
        #pragma unroll
        for (int t = 0; t < 8; t++) {
            mt_g  = fmaxf(mt_g,  fmaxf(s[t][0], s[t][1]));
            mt_g8 = fmaxf(mt_g8, fmaxf(s[t][2], s[t][3]));
        }
        mt_g  = fmaxf(mt_g,  __shfl_xor_sync(0xffffffffu, mt_g, 1));
        mt_g  = fmaxf(mt_g,  __shfl_xor_sync(0xffffffffu, mt_g, 2));
        mt_g8 = fmaxf(mt_g8, __shfl_xor_sync(0xffffffffu, mt_g8, 1));
        mt_g8 = fmaxf(mt_g8, __shfl_xor_sync(0xffffffffu, mt_g8, 2));
        float mn_g = fmaxf(m_g, mt_g), mn_g8 = fmaxf(m_g8, mt_g8);
        float al_g = __expf(m_g - mn_g), al_g8 = __expf(m_g8 - mn_g8);
        m_g = mn_g; m_g8 = mn_g8;

        uint32_t ph01[8], ph23[8];
        float sum_g = 0.f, sum_g8 = 0.f;
        #pragma unroll
        for (int t = 0; t < 8; t++) {
            float p0 = __expf(s[t][0] - mn_g);
            float p1 = __expf(s[t][1] - mn_g);
            float p2 = __expf(s[t][2] - mn_g8);
            float p3 = __expf(s[t][3] - mn_g8);
            sum_g += p0 + p1; sum_g8 += p2 + p3;
            ph01[t] = h2u(__floats2half2_rn(p0, p1));
            ph23[t] = h2u(__floats2half2_rn(p2, p3));
        }
        sum_g  += __shfl_xor_sync(0xffffffffu, sum_g, 1);
        sum_g  += __shfl_xor_sync(0xffffffffu, sum_g, 2);
        sum_g8 += __shfl_xor_sync(0xffffffffu, sum_g8, 1);
        sum_g8 += __shfl_xor_sync(0xffffffffu, sum_g8, 2);
        l_g  = l_g  * al_g  + sum_g;
        l_g8 = l_g8 * al_g8 + sum_g8;

        #pragma unroll
        for (int t = 0; t < 8; t++) {
            o[t][0] *= al_g;  o[t][1] *= al_g;
            o[t][2] *= al_g8; o[t][3] *= al_g8;
        }

        #pragma unroll
        for (int u = 0; u < 4; u++) {
            uint32_t pah[4] = {ph01[2*u], ph23[2*u], ph01[2*u+1], ph23[2*u+1]};
            uint32_t ubase = u * 16 * LQ * 2;
            #pragma unroll
            for (int tdp = 0; tdp < 4; tdp++) {
                uint32_t bv4[4];
                ldsm_x4_t(bv4, uV + offV[tdp] + ubase);
                mma16816(o[2 * tdp],     pah, bv4);
                mma16816(o[2 * tdp + 1], pah, bv4 + 2);
            }
        }

        stg = stg + 1; if (stg >= 3) stg = 0;
    }

    float iv_g = 1.f / l_g, iv_g8 = 1.f / l_g8;
    size_t ob  = ((size_t)(b * S_ + q0 + wr + g)     * H_ + h) * HD_;
    size_t ob8 = ((size_t)(b * S_ + q0 + wr + g + 8) * H_ + h) * HD_;
    #pragma unroll
    for (int td = 0; td < 8; td++) {
        int d = 8 * td + 2 * qi;
        *(uint32_t*)&O_[ob + d]  = h2u(__floats2half2_rn(o[td][0] * iv_g,
                                                         o[td][1] * iv_g));
        *(uint32_t*)&O_[ob8 + d] = h2u(__floats2half2_rn(o[td][2] * iv_g8,
                                                         o[td][3] * iv_g8));
    }
}

// ---------------- launcher ----------------
extern "C" void kernel_launch(void* const* d_in, const int* in_sizes, int n_in,
                              void* d_out, int out_size)
{
    const float* x        = (const float*)d_in[0];
    const float* w_qkv    = (const float*)d_in[1];
    const float* b_qkv    = (const float*)d_in[2];
    const float* w_out    = (const float*)d_in[3];
    const float* b_out    = (const float*)d_in[4];
    const float* ln_scale = (const float*)d_in[5];
    const float* ln_bias  = (const float*)d_in[6];
    const float* q_scale  = (const float*)d_in[7];
    const float* k_scale  = (const float*)d_in[8];
    float* out = (float*)d_out;

    __half *xn, *wq, *wo, *attn, *qf, *kf, *vf;
    cudaGetSymbolAddress((void**)&xn,   g_xn);
    cudaGetSymbolAddress((void**)&wq,   g_wqT);
    cudaGetSymbolAddress((void**)&wo,   g_woT);
    cudaGetSymbolAddress((void**)&qf,   g_qf);
    cudaGetSymbolAddress((void**)&kf,   g_kf);
    cudaGetSymbolAddress((void**)&vf,   g_vf);
    cudaGetSymbolAddress((void**)&attn, g_attn);

    cudaFuncSetAttribute(gemm_mma,
        cudaFuncAttributeMaxDynamicSharedMemorySize, GEMM_SMEM);
    cudaFuncSetAttribute(gemm_qkv,
        cudaFuncAttributeMaxDynamicSharedMemorySize, GEMM_SMEM);
    cudaFuncSetAttribute(flash_mma,
        cudaFuncAttributeMaxDynamicSharedMemorySize, FL_SMEM);

    // 1. fused prep: LN + both weight casts
    prep_kernel<<<ROWS + 3072 + 1024, 256>>>(x, ln_scale, ln_bias, xn,
                                             w_qkv, wq, w_out, wo);

    // 2. fused QKV GEMM + per-head LN + RoPE
    gemm_qkv<<<dim3((3 * D_) / 128, ROWS / 128), 256, GEMM_SMEM>>>(
        xn, wq, b_qkv, q_scale, k_scale, qf, kf, vf);

    // 3. flash attention
    flash_mma<<<dim3(S_ / 128, B_ * H_), 256, FL_SMEM>>>(qf, kf, vf, attn);

    // 4. output GEMM
    gemm_mma<<<dim3(D_ / 128, ROWS / 128), 256, GEMM_SMEM>>>(
        attn, wo, b_out, out, ROWS, D_, D_);
}

// round 15
// speedup vs baseline: 13.2182x; 1.0255x over previous
#include <cuda_runtime.h>
#include <cuda_fp16.h>
#include <cstdint>
#include <math.h>

#define B_  2
#define S_  2048
#define D_  1024
#define H_  16
#define HD_ 64
#define EPS 1e-6f

#define ROWS (B_ * S_)          // 4096

// ---------------- scratch (device globals; no allocation) ----------------
__device__ __half g_xn  [ROWS * D_];
__device__ __half g_wqT [3 * D_ * D_];   // [3072][1024] K-major fp16
__device__ __half g_woT [D_ * D_];       // [1024][1024] K-major
__device__ __half g_qf[B_ * H_ * S_ * HD_];
__device__ __half g_kf[B_ * H_ * S_ * HD_];
__device__ __half g_vf[B_ * H_ * S_ * HD_];
__device__ __half g_attn[ROWS * D_];
__device__ float  g_ropeC[S_ * 32];
__device__ float  g_ropeS[S_ * 32];

// ================= helpers =================
__device__ __forceinline__ uint32_t smem_to_u32(const void* p) {
    uint32_t a;
    asm("{ .reg .u64 t; cvta.to.shared.u64 t, %1; cvt.u32.u64 %0, t; }"
        : "=r"(a) : "l"(p));
    return a;
}
__device__ __forceinline__ void cp16(void* sp, const void* gp) {
    uint32_t s = smem_to_u32(sp);
    asm volatile("cp.async.cg.shared.global [%0], [%1], 16;" :: "r"(s), "l"(gp));
}
#define CP_COMMIT() asm volatile("cp.async.commit_group;" ::: "memory")
#define CP_WAIT1()  asm volatile("cp.async.wait_group 1;"  ::: "memory")
#define CP_WAIT0()  asm volatile("cp.async.wait_group 0;"  ::: "memory")

__device__ __forceinline__ void mma16816(float* c, const uint32_t* a, const uint32_t* b) {
    asm volatile(
        "mma.sync.aligned.m16n8k16.row.col.f32.f16.f16.f32 "
        "{%0,%1,%2,%3}, {%4,%5,%6,%7}, {%8,%9}, {%0,%1,%2,%3};"
        : "+f"(c[0]), "+f"(c[1]), "+f"(c[2]), "+f"(c[3])
        : "r"(a[0]), "r"(a[1]), "r"(a[2]), "r"(a[3]),
          "r"(b[0]), "r"(b[1]));
}
__device__ __forceinline__ void ldsm_x4(uint32_t* r, uint32_t saddr) {
    asm volatile("ldmatrix.sync.aligned.m8n8.x4.shared.b16 {%0,%1,%2,%3}, [%4];"
        : "=r"(r[0]), "=r"(r[1]), "=r"(r[2]), "=r"(r[3]) : "r"(saddr));
}
__device__ __forceinline__ void ldsm_x4_t(uint32_t* r, uint32_t saddr) {
    asm volatile("ldmatrix.sync.aligned.m8n8.x4.trans.shared.b16 {%0,%1,%2,%3}, [%4];"
        : "=r"(r[0]), "=r"(r[1]), "=r"(r[2]), "=r"(r[3]) : "r"(saddr));
}
__device__ __forceinline__ uint32_t h2u(__half2 v) { return *(uint32_t*)&v; }

#define SW128(o) ((o) ^ (((o) >> 3) & 0x70))

// ---------------- block reduce (256 threads) ----------------
__device__ __forceinline__ float block_reduce_256(float v, float* sh) {
    #pragma unroll
    for (int o = 16; o; o >>= 1) v += __shfl_down_sync(0xffffffffu, v, o);
    if ((threadIdx.x & 31) == 0) sh[threadIdx.x >> 5] = v;
    __syncthreads();
    if (threadIdx.x == 0) {
        float t = 0.f;
        #pragma unroll
        for (int i = 0; i < 8; i++) t += sh[i];
        sh[0] = t;
    }
    __syncthreads();
    float r = sh[0];
    __syncthreads();
    return r;
}

// ---------------- fused prep: LN + weight transpose/cast + rope tables ----------------
// blocks [0,4096): LN rows. [4096,7168): w_qkv. [7168,8192): w_out. [8192,8256): rope.
#define PREP_BLOCKS (ROWS + 3072 + 1024 + 64)
__global__ __launch_bounds__(256) void prep_kernel(
    const float* __restrict__ x, const float* __restrict__ scale,
    const float* __restrict__ bias, __half* __restrict__ xn,
    const float* __restrict__ Wq, __half* __restrict__ WqT,
    const float* __restrict__ Wo, __half* __restrict__ WoT,
    float* __restrict__ ropeC, float* __restrict__ ropeS)
{
    __shared__ float shred[8];
    __shared__ float t[32][33];
    int bid = blockIdx.x;
    int tid = threadIdx.x;

    if (bid < ROWS) {
        int row = bid;
        const float4* xr = (const float4*)(x + (size_t)row * D_);
        float4 v = xr[tid];

        float s = v.x + v.y + v.z + v.w;
        float tot = block_reduce_256(s, shred);
        float mu = tot * (1.0f / D_);

        float dx = v.x - mu, dy = v.y - mu, dz = v.z - mu, dw = v.w - mu;
        float sq = dx*dx + dy*dy + dz*dz + dw*dw;
        float vtot = block_reduce_256(sq, shred);
        float rstd = rsqrtf(vtot * (1.0f / D_) + EPS);

        float4 sc = ((const float4*)scale)[tid];
        float4 bi = ((const float4*)bias)[tid];
        size_t base = (size_t)row * D_ + tid * 4;
        *(__half2*)&xn[base + 0] = __floats2half2_rn(dx * rstd * sc.x + bi.x,
                                                     dy * rstd * sc.y + bi.y);
        *(__half2*)&xn[base + 2] = __floats2half2_rn(dz * rstd * sc.z + bi.z,
                                                     dw * rstd * sc.w + bi.w);
    } else if (bid < ROWS + 3072 + 1024) {
        const float* W; __half* T; int K, N, tt;
        if (bid < ROWS + 3072) {
            tt = bid - ROWS; W = Wq; T = WqT; K = D_; N = 3 * D_;
        } else {
            tt = bid - ROWS - 3072; W = Wo; T = WoT; K = D_; N = D_;
        }
        int ntiles = N >> 5;
        int nb = (tt % ntiles) * 32, kb = (tt / ntiles) * 32;
        int tx = tid & 31, ty = tid >> 5;
        #pragma unroll
        for (int i = 0; i < 4; i++)
            t[ty + 8 * i][tx] = W[(size_t)(kb + ty + 8 * i) * N + nb + tx];
        __syncthreads();
        #pragma unroll
        for (int i = 0; i < 4; i++) {
            int n = nb + ty + 8 * i, k = kb + tx;
            T[(size_t)n * K + k] = __float2half(t[tx][ty + 8 * i]);
        }
    } else {
        // rope tables: 65536 entries, 64 blocks x 256 threads x 4
        int base = (bid - (ROWS + 3072 + 1024)) * 1024 + tid * 4;
        #pragma unroll
        for (int e = 0; e < 4; e++) {
            int idx = base + e;
            int s = idx >> 5, d = idx & 31;
            float inv = expf(-(float)(2 * d) * (1.0f / 64.0f) * 9.210340371976184f);
            float sn, cs;
            sincosf((float)s * inv, &sn, &cs);
            ropeC[idx] = cs;
            ropeS[idx] = sn;
        }
    }
}

// ---------------- shared GEMM machinery (single fp16, K-slab 64) ----------------
#define GT_BYTES 16384                       // one 128x64 fp16 tile
#define GSTAGE   (2 * GT_BYTES)              // Af, Bf
#define GEMM_SMEM (3 * GSTAGE)               // 98304

__device__ __forceinline__ void gemm_issue_stage(
    char* st,
    const __half* __restrict__ Af, const __half* __restrict__ Bf,
    int m0, int n0, int K, int kc, int tid)
{
    const __half* srcs[2] = {Af, Bf};
    const int row0s[2] = {m0, n0};
    #pragma unroll
    for (int t = 0; t < 2; t++) {
        #pragma unroll
        for (int i = 0; i < 4; i++) {
            int u = tid + i * 256;
            int r = u >> 3, c = u & 7;
            uint32_t off = (uint32_t)(r * 128 + c * 16);
            cp16(st + t * GT_BYTES + SW128(off),
                 srcs[t] + (size_t)(row0s[t] + r) * K + kc + c * 8);
        }
    }
}

#define GEMM_MAINLOOP(Af, Bf, m0, n0, Kv)                                      \
    do {                                                                       \
        const int NK = (Kv) >> 6;                                              \
        gemm_issue_stage(gsm,          Af, Bf, m0, n0, Kv, 0,  tid);           \
        CP_COMMIT();                                                           \
        gemm_issue_stage(gsm + GSTAGE, Af, Bf, m0, n0, Kv, 64, tid);           \
        CP_COMMIT();                                                           \
        int stg_ = 0;                                                          \
        for (int i = 0; i < NK; i++) {                                         \
            if (i + 1 < NK) { CP_WAIT1(); } else { CP_WAIT0(); }               \
            __syncthreads();                                                   \
            if (i + 2 < NK) {                                                  \
                int nst_ = stg_ + 2; if (nst_ >= 3) nst_ -= 3;                 \
                gemm_issue_stage(gsm + nst_ * GSTAGE,                          \
                                 Af, Bf, m0, n0, Kv, (i + 2) * 64, tid);       \
                CP_COMMIT();                                                   \
            }                                                                  \
            uint32_t uS  = uG + (uint32_t)(stg_ * GSTAGE);                     \
            uint32_t uAf = uS;                                                 \
            uint32_t uBf = uS + GT_BYTES;                                      \
            _Pragma("unroll")                                                  \
            for (int kk = 0; kk < 4; kk++) {                                   \
                uint32_t kb = kk * 32;                                         \
                uint32_t a4[2][4];                                             \
                _Pragma("unroll")                                              \
                for (int ii = 0; ii < 2; ii++)                                 \
                    ldsm_x4(a4[ii], uAf + SW128(baseA[ii] + kb));              \
                _Pragma("unroll")                                              \
                for (int jp = 0; jp < 4; jp++) {                               \
                    uint32_t b4[4];                                            \
                    ldsm_x4(b4, uBf + SW128(baseB[jp] + kb));                  \
                    _Pragma("unroll")                                          \
                    for (int jj = 0; jj < 2; jj++) {                           \
                        int j = jp * 2 + jj;                                   \
                        _Pragma("unroll")                                      \
                        for (int ii = 0; ii < 2; ii++)                         \
                            mma16816(acc[ii][j], a4[ii], b4 + 2 * jj);         \
                    }                                                          \
                }                                                              \
            }                                                                  \
            stg_ = stg_ + 1; if (stg_ >= 3) stg_ = 0;                          \
        }                                                                      \
    } while (0)

#define GEMM_PROLOG()                                                          \
    extern __shared__ char gsm[];                                              \
    int tid = threadIdx.x, lane = tid & 31, w = tid >> 5;                      \
    int g = lane >> 2, qi = lane & 3;                                          \
    int wm = w >> 1, wn = w & 1;                                               \
    int m0 = blockIdx.y * 128, n0 = blockIdx.x * 128;                          \
    uint32_t uG = smem_to_u32(gsm);                                            \
    uint32_t baseA[2], baseB[4];                                               \
    _Pragma("unroll")                                                          \
    for (int i = 0; i < 2; i++)                                                \
        baseA[i] = (uint32_t)((wm * 32 + i * 16 + (lane & 15)) * 128           \
                              + (lane >> 4) * 16);                             \
    _Pragma("unroll")                                                          \
    for (int jp = 0; jp < 4; jp++)                                             \
        baseB[jp] = (uint32_t)((wn * 64 + jp * 16 + (lane >> 4) * 8            \
                                + (lane & 7)) * 128 + ((lane >> 3) & 1) * 16); \
    float acc[2][8][4];                                                        \
    _Pragma("unroll")                                                          \
    for (int i = 0; i < 2; i++)                                                \
        _Pragma("unroll")                                                      \
        for (int j = 0; j < 8; j++)                                            \
            _Pragma("unroll")                                                  \
            for (int e = 0; e < 4; e++) acc[i][j][e] = 0.f;

// ---------------- generic GEMM (out-proj): fp32 C + bias ----------------
__global__ __launch_bounds__(256, 2) void gemm_mma(
    const __half* __restrict__ Af, const __half* __restrict__ Bf,
    const float* __restrict__ bias, float* __restrict__ C, int M, int N, int K)
{
    GEMM_PROLOG();
    GEMM_MAINLOOP(Af, Bf, m0, n0, K);

    #pragma unroll
    for (int i = 0; i < 2; i++) {
        int r0 = m0 + wm * 32 + i * 16 + g;
        #pragma unroll
        for (int j = 0; j < 8; j++) {
            int col = n0 + wn * 64 + j * 8 + 2 * qi;
            float b0 = __ldg(&bias[col]), b1 = __ldg(&bias[col + 1]);
            float2 v0 = make_float2(acc[i][j][0] + b0, acc[i][j][1] + b1);
            float2 v1 = make_float2(acc[i][j][2] + b0, acc[i][j][3] + b1);
            *(float2*)&C[(size_t)r0 * N + col]       = v0;
            *(float2*)&C[(size_t)(r0 + 8) * N + col] = v1;
        }
    }
}

// ---------------- fused QKV GEMM: bias + per-head LN + RoPE (table) epilogue ----------------
__global__ __launch_bounds__(256, 2) void gemm_qkv(
    const __half* __restrict__ Af, const __half* __restrict__ Bf,
    const float* __restrict__ bias,
    const float* __restrict__ q_scale, const float* __restrict__ k_scale,
    const float* __restrict__ ropeC, const float* __restrict__ ropeS,
    __half* __restrict__ qf, __half* __restrict__ kf, __half* __restrict__ vf)
{
    GEMM_PROLOG();
    GEMM_MAINLOOP(Af, Bf, m0, n0, D_);

    int region = n0 >> 10;                  // 0=q, 1=k, 2=v
    int hh = ((n0 & 1023) >> 6) + wn;       // head
    #pragma unroll
    for (int i = 0; i < 2; i++) {
        #pragma unroll
        for (int half = 0; half < 2; half++) {
            int r = m0 + wm * 32 + i * 16 + g + half * 8;
            int s = r & (S_ - 1), bb = r >> 11;
            size_t obase = (((size_t)(bb * H_ + hh)) * S_ + s) * HD_;

            float x[16];
            #pragma unroll
            for (int j = 0; j < 8; j++) {
                int col = n0 + wn * 64 + j * 8 + 2 * qi;
                x[2 * j]     = acc[i][j][half * 2]     + __ldg(&bias[col]);
                x[2 * j + 1] = acc[i][j][half * 2 + 1] + __ldg(&bias[col + 1]);
            }

            if (region == 2) {
                #pragma unroll
                for (int j = 0; j < 8; j++) {
                    int d = j * 8 + 2 * qi;
                    *(__half2*)&vf[obase + d] = __floats2half2_rn(x[2*j], x[2*j+1]);
                }
            } else {
                float sum = 0.f, sq = 0.f;
                #pragma unroll
                for (int t = 0; t < 16; t++) { sum += x[t]; sq += x[t] * x[t]; }
                sum += __shfl_xor_sync(0xffffffffu, sum, 1);
                sum += __shfl_xor_sync(0xffffffffu, sum, 2);
                sq  += __shfl_xor_sync(0xffffffffu, sq, 1);
                sq  += __shfl_xor_sync(0xffffffffu, sq, 2);
                float mu = sum * (1.0f / HD_);
                float rstd = rsqrtf(sq * (1.0f / HD_) - mu * mu + EPS);
                const float* sc = (region == 0) ? q_scale : k_scale;
                #pragma unroll
                for (int j = 0; j < 8; j++) {
                    int d = j * 8 + 2 * qi;
                    x[2 * j]     = (x[2 * j]     - mu) * rstd * __ldg(&sc[d]);
                    x[2 * j + 1] = (x[2 * j + 1] - mu) * rstd * __ldg(&sc[d + 1]);
                }
                // RoPE via precomputed tables
                #pragma unroll
                for (int j = 0; j < 4; j++) {
                    int d = j * 8 + 2 * qi;      // < 32
                    float2 cs2 = *(const float2*)&ropeC[s * 32 + d];
                    float2 sn2 = *(const float2*)&ropeS[s * 32 + d];
                    float cs[2] = {cs2.x, cs2.y};
                    float sn[2] = {sn2.x, sn2.y};
                    #pragma unroll
                    for (int c = 0; c < 2; c++) {
                        float lo = x[2 * j + c], hi = x[2 * (j + 4) + c];
                        x[2 * j + c]       = lo * cs[c] - hi * sn[c];
                        x[2 * (j + 4) + c] = hi * cs[c] + lo * sn[c];
                    }
                }
                if (region == 0) {
                    #pragma unroll
                    for (int j = 0; j < 8; j++) {
                        int d = j * 8 + 2 * qi;
                        *(__half2*)&qf[obase + d] =
                            __floats2half2_rn(x[2*j] * 0.125f, x[2*j+1] * 0.125f);
                    }
                } else {
                    #pragma unroll
                    for (int j = 0; j < 8; j++) {
                        int d = j * 8 + 2 * qi;
                        *(__half2*)&kf[obase + d] = __floats2half2_rn(x[2*j], x[2*j+1]);
                    }
                }
            }
        }
    }
}

// ---------------- flash attention: Q fragments hoisted, 3-stage KV ring ----------------
#define LQ 72
#define KVT (64 * LQ)
#define KVSTG (2 * KVT)
#define FL_SMEM ((128 * LQ + 3 * KVSTG) * (int)sizeof(__half))

__device__ __forceinline__ void flash_issue_kv(
    __half* st,
    const __half* __restrict__ Kp, const __half* __restrict__ Vp,
    int j0, int tid)
{
    int r = tid >> 2, c = (tid & 3) * 16;
    size_t go = (size_t)(j0 + r) * HD_ + c;
    int so = r * LQ + c;
    cp16(st + so,           Kp + go);
    cp16(st + so + 8,       Kp + go + 8);
    cp16(st + KVT + so,     Vp + go);
    cp16(st + KVT + so + 8, Vp + go + 8);
}

__global__ __launch_bounds__(256, 2) void flash_mma(
    const __half* __restrict__ Qf_, const __half* __restrict__ Kf_,
    const __half* __restrict__ Vf_, __half* __restrict__ O_)
{
    extern __shared__ __half fsm[];
    __half* sQ  = fsm;                 // [128][LQ]
    __half* sKV = sQ + 128 * LQ;

    int tid = threadIdx.x, lane = tid & 31, wid = tid >> 5;
    int g = lane >> 2, qi = lane & 3;
    int bh = blockIdx.y;
    int b = bh >> 4, h = bh & 15;
    int q0 = blockIdx.x * 128;
    size_t hbase = (size_t)bh * S_ * HD_;
    const __half* Qfp = Qf_ + hbase;
    const __half* Kfp = Kf_ + hbase;
    const __half* Vfp = Vf_ + hbase;

    int wr = wid * 16;
    uint32_t uQ  = smem_to_u32(sQ);
    uint32_t uKV = smem_to_u32(sKV);

    uint32_t offQ = ((wr + (lane & 15)) * LQ + (lane >> 4) * 8) * 2;
    uint32_t offK[4], offV[4];
    #pragma unroll
    for (int tp = 0; tp < 4; tp++)
        offK[tp] = ((tp * 16 + (lane >> 4) * 8 + (lane & 7)) * LQ
                    + ((lane >> 3) & 1) * 8) * 2;
    #pragma unroll
    for (int tdp = 0; tdp < 4; tdp++)
        offV[tdp] = ((((lane >> 3) & 1) * 8 + (lane & 7)) * LQ
                     + (2 * tdp + (lane >> 4)) * 8) * 2;

    #pragma unroll
    for (int i = 0; i < 4; i++) {
        int u = tid + i * 256;
        int r = u >> 3, c = (u & 7) * 8;
        *(uint4*)&sQ[r * LQ + c] = *(const uint4*)&Qfp[(size_t)(q0 + r) * HD_ + c];
    }
    flash_issue_kv(sKV,         Kfp, Vfp, 0,  tid);
    CP_COMMIT();
    flash_issue_kv(sKV + KVSTG, Kfp, Vfp, 64, tid);
    CP_COMMIT();
    __syncthreads();

    // hoist Q fragments (loop-invariant)
    uint32_t qfrag[4][4];
    #pragma unroll
    for (int u = 0; u < 4; u++)
        ldsm_x4(qfrag[u], uQ + offQ + u * 32);

    float o[8][4];
    #pragma unroll
    for (int t = 0; t < 8; t++)
        #pragma unroll
        for (int e = 0; e < 4; e++) o[t][e] = 0.f;
    float m_g = -1e30f, m_g8 = -1e30f, l_g = 0.f, l_g8 = 0.f;

    const int NT = S_ / 64;
    int stg = 0;
    for (int kt = 0; kt < NT; kt++) {
        if (kt + 1 < NT) { CP_WAIT1(); } else { CP_WAIT0(); }
        __syncthreads();

        if (kt + 2 < NT) {
            int nst = stg + 2; if (nst >= 3) nst -= 3;
            flash_issue_kv(sKV + nst * KVSTG, Kfp, Vfp, (kt + 2) * 64, tid);
            CP_COMMIT();
        }

        uint32_t uS = uKV + (uint32_t)(stg * KVSTG) * 2;
        uint32_t uK = uS;
        uint32_t uV = uS + KVT * 2;

        float s[8][4];
        #pragma unroll
        for (int t = 0; t < 8; t++)
            #pragma unroll
            for (int e = 0; e < 4; e++) s[t][e] = 0.f;

        #pragma unroll
        for (int u = 0; u < 4; u++) {
            #pragma unroll
            for (int tp = 0; tp < 4; tp++) {
                uint32_t b4[4];
                ldsm_x4(b4, uK + offK[tp] + u * 32);
                mma16816(s[2 * tp],     qfrag[u], b4);
                mma16816(s[2 * tp + 1], qfrag[u], b4 + 2);
            }
        }

        float mt_g = -1e30f, mt_g8 = -1e30f;
        #pragma unroll
        for (int t = 0; t < 8; t++) {
            mt_g  = fmaxf(mt_g,  fmaxf(s[t][0], s[t][1]));
            mt_g8 = fmaxf(mt_g8, fmaxf(s[t][2], s[t][3]));
        }
        mt_g  = fmaxf(mt_g,  __shfl_xor_sync(0xffffffffu, mt_g, 1));
        mt_g  = fmaxf(mt_g,  __shfl_xor_sync(0xffffffffu, mt_g, 2));
        mt_g8 = fmaxf(mt_g8, __shfl_xor_sync(0xffffffffu, mt_g8, 1));
        mt_g8 = fmaxf(mt_g8, __shfl_xor_sync(0xffffffffu, mt_g8, 2));
        float mn_g = fmaxf(m_g, mt_g), mn_g8 = fmaxf(m_g8, mt_g8);
        float al_g = __expf(m_g - mn_g), al_g8 = __expf(m_g8 - mn_g8);
        m_g = mn_g; m_g8 = mn_g8;

        uint32_t ph01[8], ph23[8];
        float sum_g = 0.f, sum_g8 = 0.f;
        #pragma unroll
        for (int t = 0; t < 8; t++) {
            float p0 = __expf(s[t][0] - mn_g);
            float p1 = __expf(s[t][1] - mn_g);
            float p2 = __expf(s[t][2] - mn_g8);
            float p3 = __expf(s[t][3] - mn_g8);
            sum_g += p0 + p1; sum_g8 += p2 + p3;
            ph01[t] = h2u(__floats2half2_rn(p0, p1));
            ph23[t] = h2u(__floats2half2_rn(p2, p3));
        }
        sum_g  += __shfl_xor_sync(0xffffffffu, sum_g, 1);
        sum_g  += __shfl_xor_sync(0xffffffffu, sum_g, 2);
        sum_g8 += __shfl_xor_sync(0xffffffffu, sum_g8, 1);
        sum_g8 += __shfl_xor_sync(0xffffffffu, sum_g8, 2);
        l_g  = l_g  * al_g  + sum_g;
        l_g8 = l_g8 * al_g8 + sum_g8;

        #pragma unroll
        for (int t = 0; t < 8; t++) {
            o[t][0] *= al_g;  o[t][1] *= al_g;
            o[t][2] *= al_g8; o[t][3] *= al_g8;
        }

        #pragma unroll
        for (int u = 0; u < 4; u++) {
            uint32_t pah[4] = {ph01[2*u], ph23[2*u], ph01[2*u+1], ph23[2*u+1]};
            uint32_t ubase = u * 16 * LQ * 2;
            #pragma unroll
            for (int tdp = 0; tdp < 4; tdp++) {
                uint32_t bv4[4];
                ldsm_x4_t(bv4, uV + offV[tdp] + ubase);
                mma16816(o[2 * tdp],     pah, bv4);
                mma16816(o[2 * tdp + 1], pah, bv4 + 2);
            }
        }

        stg = stg + 1; if (stg >= 3) stg = 0;
    }

    float iv_g = 1.f / l_g, iv_g8 = 1.f / l_g8;
    size_t ob  = ((size_t)(b * S_ + q0 + wr + g)     * H_ + h) * HD_;
    size_t ob8 = ((size_t)(b * S_ + q0 + wr + g + 8) * H_ + h) * HD_;
    #pragma unroll
    for (int td = 0; td < 8; td++) {
        int d = 8 * td + 2 * qi;
        *(uint32_t*)&O_[ob + d]  = h2u(__floats2half2_rn(o[td][0] * iv_g,
                                                         o[td][1] * iv_g));
        *(uint32_t*)&O_[ob8 + d] = h2u(__floats2half2_rn(o[td][2] * iv_g8,
                                                         o[td][3] * iv_g8));
    }
}

// ---------------- launcher ----------------
extern "C" void kernel_launch(void* const* d_in, const int* in_sizes, int n_in,
                              void* d_out, int out_size)
{
    const float* x        = (const float*)d_in[0];
    const float* w_qkv    = (const float*)d_in[1];
    const float* b_qkv    = (const float*)d_in[2];
    const float* w_out    = (const float*)d_in[3];
    const float* b_out    = (const float*)d_in[4];
    const float* ln_scale = (const float*)d_in[5];
    const float* ln_bias  = (const float*)d_in[6];
    const float* q_scale  = (const float*)d_in[7];
    const float* k_scale  = (const float*)d_in[8];
    float* out = (float*)d_out;

    __half *xn, *wq, *wo, *attn, *qf, *kf, *vf;
    float *rC, *rS;
    cudaGetSymbolAddress((void**)&xn,   g_xn);
    cudaGetSymbolAddress((void**)&wq,   g_wqT);
    cudaGetSymbolAddress((void**)&wo,   g_woT);
    cudaGetSymbolAddress((void**)&qf,   g_qf);
    cudaGetSymbolAddress((void**)&kf,   g_kf);
    cudaGetSymbolAddress((void**)&vf,   g_vf);
    cudaGetSymbolAddress((void**)&attn, g_attn);
    cudaGetSymbolAddress((void**)&rC,   g_ropeC);
    cudaGetSymbolAddress((void**)&rS,   g_ropeS);

    cudaFuncSetAttribute(gemm_mma,
        cudaFuncAttributeMaxDynamicSharedMemorySize, GEMM_SMEM);
    cudaFuncSetAttribute(gemm_qkv,
        cudaFuncAttributeMaxDynamicSharedMemorySize, GEMM_SMEM);
    cudaFuncSetAttribute(flash_mma,
        cudaFuncAttributeMaxDynamicSharedMemorySize, FL_SMEM);

    // 1. fused prep: LN + weight casts + rope tables
    prep_kernel<<<PREP_BLOCKS, 256>>>(x, ln_scale, ln_bias, xn,
                                      w_qkv, wq, w_out, wo, rC, rS);

    // 2. fused QKV GEMM + per-head LN + RoPE
    gemm_qkv<<<dim3((3 * D_) / 128, ROWS / 128), 256, GEMM_SMEM>>>(
        xn, wq, b_qkv, q_scale, k_scale, rC, rS, qf, kf, vf);

    // 3. flash attention
    flash_mma<<<dim3(S_ / 128, B_ * H_), 256, FL_SMEM>>>(qf, kf, vf, attn);

    // 4. output GEMM
    gemm_mma<<<dim3(D_ / 128, ROWS / 128), 256, GEMM_SMEM>>>(
        attn, wo, b_out, out, ROWS, D_, D_);
}